// round 1
// baseline (speedup 1.0000x reference)
#include <cuda_runtime.h>
#include <math.h>

#define NG   2048
#define NP   128
#define NTOT (NG * NP)          // 262144 nodes
#define KNN  4

// ---------------- scratch (device globals; no allocs allowed) ----------------
__device__ float g_hagg[(size_t)NTOT * 384];   // EdgeConv agg output [N][384]
__device__ float g_hidden[(size_t)NTOT * 96];  // nn1 output (padded) [N][96]
__device__ float g_h2[(size_t)NTOT * 64];      // nn2 output [N][64]
__device__ float g_gfeat[NG * 256];            // per-graph features [2048][256]
__device__ float g_xin[2 * 1024 * 256];        // GRU layer-0 inputs [t][b][256]
__device__ float g_out0[2 * 1024 * 32];        // GRU layer-0 hidden seq
__device__ float g_out1[2 * 1024 * 32];        // GRU layer-1 hidden seq
__device__ float g_nn1p[384 * 96];             // nn1_W padded to 96 cols
__device__ float g_nn1bp[96];
__device__ float g_nn2p[96 * 64];              // nn2_W padded to 96 rows (zeros)
__device__ float g_wih0T[256 * 96];
__device__ float g_whh0T[32 * 96];
__device__ float g_wih1T[32 * 96];
__device__ float g_whh1T[32 * 96];

// ---------------- weight preprocessing: pad + transpose ----------------
__global__ void prep_kernel(const float* __restrict__ nn1W, const float* __restrict__ nn1b,
                            const float* __restrict__ nn2W,
                            const float* __restrict__ wih0, const float* __restrict__ whh0,
                            const float* __restrict__ wih1, const float* __restrict__ whh1)
{
    int idx = blockIdx.x * 256 + threadIdx.x;      // grid covers 384*96 = 36864
    if (idx < 384 * 96) {
        int r = idx / 96, c = idx % 96;
        g_nn1p[idx] = (c < 94) ? nn1W[r * 94 + c] : 0.f;
    }
    if (idx < 96) g_nn1bp[idx] = (idx < 94) ? nn1b[idx] : 0.f;
    if (idx < 96 * 64) g_nn2p[idx] = (idx < 94 * 64) ? nn2W[idx] : 0.f;
    if (idx < 96 * 256) { int gg = idx / 256, d = idx % 256; g_wih0T[d * 96 + gg] = wih0[idx]; }
    if (idx < 96 * 32) {
        int gg = idx / 32, d = idx % 32;
        g_whh0T[d * 96 + gg] = whh0[idx];
        g_wih1T[d * 96 + gg] = wih1[idx];
        g_whh1T[d * 96 + gg] = whh1[idx];
    }
}

// ---------------- fused KNN + EdgeConv MLP + K-aggregation ----------------
// one block per graph (128 nodes), 128 threads; thread = output channel c of W2.
__global__ void __launch_bounds__(128) knn_edgeconv_kernel(
    const float* __restrict__ x,    // [N,5]
    const float* __restrict__ W1,   // [10,64]
    const float* __restrict__ b1,   // [64]
    const float* __restrict__ W2,   // [64,128]
    const float* __restrict__ b2)   // [128]
{
    __shared__ float xs[NP][5];
    __shared__ int   nbr_s[NP][KNN];
    __shared__ float W1s[10][64];
    __shared__ float b1s[64];
    __shared__ float feats_all[NP][40];      // [node][k*10+d]
    __shared__ float4 hid4[2][64];           // double-buffered hidden [d] x (k0..k3)

    const int g   = blockIdx.x;
    const int tid = threadIdx.x;
    const int base = g * NP;

    for (int i = tid; i < NP * 5; i += 128) xs[i / 5][i % 5] = x[(size_t)base * 5 + i];
    for (int i = tid; i < 640; i += 128) W1s[i / 64][i % 64] = W1[i];
    if (tid < 64) b1s[tid] = b1[tid];

    // W2 column for this thread's channel, in registers
    float w2reg[64];
#pragma unroll
    for (int d = 0; d < 64; d++) w2reg[d] = W2[d * 128 + tid];
    const float b2c = b2[tid];
    __syncthreads();

    // ---- KNN: thread tid = node tid; 4 smallest d2, stable (earlier index wins ties)
    {
        const float px = xs[tid][0], py = xs[tid][1], pz = xs[tid][2];
        float d0 = 1e30f, d1 = 1e30f, d2b = 1e30f, d3 = 1e30f;
        int i0 = 0, i1 = 0, i2 = 0, i3 = 0;
        for (int j = 0; j < NP; j++) {
            if (j == tid) continue;
            float dx = xs[j][0] - px, dy = xs[j][1] - py, dz = xs[j][2] - pz;
            float dd = dx * dx + dy * dy + dz * dz;
            if (dd < d3) {
                if (dd < d0)      { d3=d2b; i3=i2; d2b=d1; i2=i1; d1=d0; i1=i0; d0=dd; i0=j; }
                else if (dd < d1) { d3=d2b; i3=i2; d2b=d1; i2=i1; d1=dd; i1=j; }
                else if (dd < d2b){ d3=d2b; i3=i2; d2b=dd; i2=j; }
                else              { d3=dd; i3=j; }
            }
        }
        nbr_s[tid][0] = i0; nbr_s[tid][1] = i1; nbr_s[tid][2] = i2; nbr_s[tid][3] = i3;
    }
    __syncthreads();

    // ---- edge features for all nodes: [x_i(5), x_j - x_i(5)]
    for (int idx = tid; idx < NP * 40; idx += 128) {
        int n = idx / 40, t = idx % 40, k = t / 10, d = t % 10;
        float v;
        if (d < 5) v = xs[n][d];
        else { int j = nbr_s[n][k]; v = xs[j][d - 5] - xs[n][d - 5]; }
        feats_all[n][t] = v;
    }
    __syncthreads();

    // ---- per-node: hidden1 (cooperative) then 128-ch message + agg (per thread)
    for (int n = 0; n < NP; n++) {
        const int buf = n & 1;
        {
            const int cc = tid & 63;
            const int khalf = tid >> 6;          // 0 or 1
#pragma unroll
            for (int kk = 0; kk < 2; kk++) {
                const int k = khalf + 2 * kk;
                float acc = b1s[cc];
#pragma unroll
                for (int d = 0; d < 10; d++)
                    acc = fmaf(feats_all[n][k * 10 + d], W1s[d][cc], acc);
                ((float*)&hid4[buf][cc])[k] = fmaxf(acc, 0.f);
            }
        }
        __syncthreads();

        float m0 = b2c, m1 = b2c, m2 = b2c, m3 = b2c;
#pragma unroll
        for (int d = 0; d < 64; d++) {
            const float4 h4 = hid4[buf][d];
            const float w = w2reg[d];
            m0 = fmaf(h4.x, w, m0);
            m1 = fmaf(h4.y, w, m1);
            m2 = fmaf(h4.z, w, m2);
            m3 = fmaf(h4.w, w, m3);
        }
        m0 = fmaxf(m0, 0.f); m1 = fmaxf(m1, 0.f);
        m2 = fmaxf(m2, 0.f); m3 = fmaxf(m3, 0.f);
        const float mx = fmaxf(fmaxf(m0, m1), fmaxf(m2, m3));
        const float sm = (m0 + m1) + (m2 + m3);
        const size_t nb = (size_t)(base + n) * 384;
        g_hagg[nb + tid]       = mx;          // max
        g_hagg[nb + 128 + tid] = sm * 0.25f;  // mean
        g_hagg[nb + 256 + tid] = sm;          // sum
        // single sync per node: separates this node's hid reads from writes 2 iters later
    }
}

// ---------------- tiled fp32 GEMM: C[N,NOUT] = act(A[N,KDIM] @ W + b) ----------------
template <int KDIM, int NOUT, int TN, bool RELU>
__global__ void __launch_bounds__(256) gemm_kernel(
    const float* __restrict__ A, const float* __restrict__ W,
    const float* __restrict__ bias, float* __restrict__ C)
{
    __shared__ __align__(16) float As[32][68];   // [k][node], padded
    __shared__ float Ws[32][NOUT];
    const int tid  = threadIdx.x;
    const int bm   = blockIdx.x * 64;
    const int trow = (tid & 15) * 4;
    const int tcol = (tid >> 4) * TN;

    float acc[4][TN];
#pragma unroll
    for (int i = 0; i < 4; i++)
#pragma unroll
        for (int j = 0; j < TN; j++) acc[i][j] = 0.f;

    const int lr = tid >> 3;          // 0..31
    const int lc = (tid & 7) * 4;     // 0..28

    for (int k0 = 0; k0 < KDIM; k0 += 32) {
        float4 v0 = *(const float4*)(A + (size_t)(bm + lr) * KDIM + k0 + lc);
        float4 v1 = *(const float4*)(A + (size_t)(bm + lr + 32) * KDIM + k0 + lc);
        As[lc + 0][lr] = v0.x; As[lc + 1][lr] = v0.y;
        As[lc + 2][lr] = v0.z; As[lc + 3][lr] = v0.w;
        As[lc + 0][lr + 32] = v1.x; As[lc + 1][lr + 32] = v1.y;
        As[lc + 2][lr + 32] = v1.z; As[lc + 3][lr + 32] = v1.w;
        for (int i = tid; i < 32 * NOUT; i += 256)
            (&Ws[0][0])[i] = W[k0 * NOUT + i];
        __syncthreads();

#pragma unroll
        for (int k = 0; k < 32; k++) {
            const float4 a4 = *(const float4*)&As[k][trow];
            const float av[4] = {a4.x, a4.y, a4.z, a4.w};
#pragma unroll
            for (int j = 0; j < TN; j++) {
                const float w = Ws[k][tcol + j];
#pragma unroll
                for (int i = 0; i < 4; i++) acc[i][j] = fmaf(av[i], w, acc[i][j]);
            }
        }
        __syncthreads();
    }

#pragma unroll
    for (int j = 0; j < TN; j++) {
        const float b = bias[tcol + j];
#pragma unroll
        for (int i = 0; i < 4; i++) {
            float v = acc[i][j] + b;
            if (RELU) v = fmaxf(v, 0.f);
            C[(size_t)(bm + trow + i) * NOUT + tcol + j] = v;
        }
    }
}

// ---------------- per-graph segment max/min/sum/mean + relu ----------------
__global__ void segreduce_kernel()
{
    const int g = blockIdx.x, c = threadIdx.x;   // 64 threads
    const float* p = g_h2 + (size_t)g * NP * 64 + c;
    float mx = -1e30f, mn = 1e30f, sm = 0.f;
    for (int n = 0; n < NP; n++) {
        const float v = p[(size_t)n * 64];
        mx = fmaxf(mx, v); mn = fminf(mn, v); sm += v;
    }
    float* o = g_gfeat + g * 256;
    o[c]        = fmaxf(mx, 0.f);
    o[64 + c]   = fmaxf(mn, 0.f);
    o[128 + c]  = fmaxf(sm, 0.f);
    o[192 + c]  = fmaxf(sm * (1.f / 128.f), 0.f);
}

// ---------------- g.reshape(2,256,1024).transpose(0,2,1) -> xin[t][b][i] ----------------
__global__ void permute_kernel()
{
    const int idx = blockIdx.x * 256 + threadIdx.x;   // 2*1024*256 = 524288
    const int i = idx & 255;
    const int b = (idx >> 8) & 1023;
    const int t = idx >> 18;
    g_xin[idx] = g_gfeat[(t * 1024 + i * 4 + (b >> 8)) * 256 + (b & 255)];
}

// ---------------- one GRU step (PyTorch gate order r,z,n) ----------------
__global__ void __launch_bounds__(96) gru_step_kernel(
    const float* __restrict__ x, int IN,
    const float* __restrict__ h_in,
    const float* __restrict__ wihT,   // [IN][96]
    const float* __restrict__ whhT,   // [32][96]
    const float* __restrict__ bih, const float* __restrict__ bhh,
    float* __restrict__ h_out)        // [1024][32]
{
    __shared__ float xs[16][256];
    __shared__ float hs[16][32];
    __shared__ float gi_s[16][96];
    __shared__ float gh_s[16][96];
    const int g  = threadIdx.x;       // gate index 0..95
    const int r0 = blockIdx.x * 16;

    for (int i = g; i < 16 * IN; i += 96) xs[i / IN][i % IN] = x[(size_t)r0 * IN + i];
    for (int i = g; i < 16 * 32; i += 96) hs[i / 32][i % 32] = h_in[r0 * 32 + i];
    __syncthreads();

    const float bi = bih[g], bh = bhh[g];
    for (int r = 0; r < 16; r++) {
        float ai = bi;
        for (int d = 0; d < IN; d++) ai = fmaf(xs[r][d], wihT[d * 96 + g], ai);
        float ah = bh;
#pragma unroll
        for (int d = 0; d < 32; d++) ah = fmaf(hs[r][d], whhT[d * 96 + g], ah);
        gi_s[r][g] = ai; gh_s[r][g] = ah;
    }
    __syncthreads();

    if (g < 32) {
        for (int r = 0; r < 16; r++) {
            const float ir = gi_s[r][g],      hr = gh_s[r][g];
            const float iz = gi_s[r][g + 32], hz = gh_s[r][g + 32];
            const float in_ = gi_s[r][g + 64], hn = gh_s[r][g + 64];
            const float rr = 1.f / (1.f + expf(-(ir + hr)));
            const float zz = 1.f / (1.f + expf(-(iz + hz)));
            const float nn = tanhf(in_ + rr * hn);
            const float hv = (1.f - zz) * nn + zz * hs[r][g];
            h_out[(r0 + r) * 32 + g] = hv;
        }
    }
}

// ---------------- final head + hT pack: out = [y(2048) | hT(2*1024*32)] ----------------
__global__ void final_kernel(const float* __restrict__ nn4W, const float* __restrict__ nn4b,
                             float* __restrict__ out, int out_size)
{
    const int idx = blockIdx.x * 256 + threadIdx.x;
    if (idx >= out_size) return;
    if (idx < 2048) {
        const int t  = idx >> 10;
        const int ch = (idx >> 5) & 31;
        const int b0 = (idx & 31) * 32;
        float acc = nn4b[0];
#pragma unroll
        for (int c = 0; c < 32; c++) {
            const float v = g_out1[t * 32768 + (b0 + c) * 32 + ch];
            acc = fmaf(fmaxf(v, 0.f), nn4W[c], acc);
        }
        out[idx] = fmaxf(acc, 0.f);
    } else if (idx < 2048 + 65536) {
        const int j = idx - 2048;
        out[idx] = (j < 32768) ? g_out0[32768 + j] : g_out1[32768 + (j - 32768)];
    }
}

// ---------------- launch ----------------
extern "C" void kernel_launch(void* const* d_in, const int* in_sizes, int n_in,
                              void* d_out, int out_size)
{
    const float* x    = (const float*)d_in[0];
    const float* h1   = (const float*)d_in[2];
    const float* W1   = (const float*)d_in[3];
    const float* b1   = (const float*)d_in[4];
    const float* W2   = (const float*)d_in[5];
    const float* b2   = (const float*)d_in[6];
    const float* nn1W = (const float*)d_in[7];
    const float* nn1b = (const float*)d_in[8];
    const float* nn2W = (const float*)d_in[9];
    const float* nn2b = (const float*)d_in[10];
    const float* nn4W = (const float*)d_in[11];
    const float* nn4b = (const float*)d_in[12];
    const float* wih0 = (const float*)d_in[13];
    const float* whh0 = (const float*)d_in[14];
    const float* bih0 = (const float*)d_in[15];
    const float* bhh0 = (const float*)d_in[16];
    const float* wih1 = (const float*)d_in[17];
    const float* whh1 = (const float*)d_in[18];
    const float* bih1 = (const float*)d_in[19];
    const float* bhh1 = (const float*)d_in[20];
    float* out = (float*)d_out;

    float *hagg, *hidden, *h2, *xin, *out0, *out1;
    float *nn1p, *nn1bp, *nn2p, *wih0T, *whh0T, *wih1T, *whh1T;
    cudaGetSymbolAddress((void**)&hagg,  g_hagg);
    cudaGetSymbolAddress((void**)&hidden, g_hidden);
    cudaGetSymbolAddress((void**)&h2,    g_h2);
    cudaGetSymbolAddress((void**)&xin,   g_xin);
    cudaGetSymbolAddress((void**)&out0,  g_out0);
    cudaGetSymbolAddress((void**)&out1,  g_out1);
    cudaGetSymbolAddress((void**)&nn1p,  g_nn1p);
    cudaGetSymbolAddress((void**)&nn1bp, g_nn1bp);
    cudaGetSymbolAddress((void**)&nn2p,  g_nn2p);
    cudaGetSymbolAddress((void**)&wih0T, g_wih0T);
    cudaGetSymbolAddress((void**)&whh0T, g_whh0T);
    cudaGetSymbolAddress((void**)&wih1T, g_wih1T);
    cudaGetSymbolAddress((void**)&whh1T, g_whh1T);

    prep_kernel<<<144, 256>>>(nn1W, nn1b, nn2W, wih0, whh0, wih1, whh1);
    knn_edgeconv_kernel<<<NG, 128>>>(x, W1, b1, W2, b2);
    gemm_kernel<384, 96, 6, true><<<NTOT / 64, 256>>>(hagg, nn1p, nn1bp, hidden);
    gemm_kernel<96, 64, 4, false><<<NTOT / 64, 256>>>(hidden, nn2p, nn2b, h2);
    segreduce_kernel<<<NG, 64>>>();
    permute_kernel<<<2048, 256>>>();
    // GRU: layer0 (IN=256) over 2 steps, then layer1 (IN=32)
    gru_step_kernel<<<64, 96>>>(xin,          256, h1,          wih0T, whh0T, bih0, bhh0, out0);
    gru_step_kernel<<<64, 96>>>(xin + 262144, 256, out0,        wih0T, whh0T, bih0, bhh0, out0 + 32768);
    gru_step_kernel<<<64, 96>>>(out0,          32, h1 + 32768,  wih1T, whh1T, bih1, bhh1, out1);
    gru_step_kernel<<<64, 96>>>(out0 + 32768,  32, out1,        wih1T, whh1T, bih1, bhh1, out1 + 32768);
    final_kernel<<<(out_size + 255) / 256, 256>>>(nn4W, nn4b, out, out_size);
}

// round 4
// speedup vs baseline: 1.2289x; 1.2289x over previous
#include <cuda_runtime.h>
#include <math.h>
#include <stdint.h>

#define NG 2048
#define NP 128

// ---------------- scratch (device globals) ----------------
__device__ float g_gfeat[NG * 256];
__device__ float g_xin[2 * 1024 * 256];
__device__ float g_out0[2 * 1024 * 32];
__device__ float g_out1[2 * 1024 * 32];
__device__ float g_w2T[128 * 64];      // edge W2^T  [n][k] fp32
__device__ float g_nn1T2[96 * 256];    // folded nn1^T [n][k=256] fp32
__device__ float g_nn2T[64 * 96];      // nn2^T [n][k] fp32 (padded k)
__device__ float g_nn1bp[96];
__device__ float g_wih0T[256 * 96];
__device__ float g_whh0T[32 * 96];
__device__ float g_wih1T[32 * 96];
__device__ float g_whh1T[32 * 96];

// ---------------- helpers ----------------
__device__ __forceinline__ float cvt_tf32(float x) {
    float r; asm("cvt.rna.tf32.f32 %0, %1;" : "=f"(r) : "f"(x)); return r;
}
__device__ __forceinline__ void splitf(float x, uint32_t& h, uint32_t& l) {
    float hh = cvt_tf32(x);
    h = __float_as_uint(hh);
    l = __float_as_uint(cvt_tf32(x - hh));
}
__device__ __forceinline__ void mma8(float d[4], const uint32_t a[4], const uint32_t b[2]) {
    asm volatile(
        "mma.sync.aligned.m16n8k8.row.col.f32.tf32.tf32.f32 "
        "{%0,%1,%2,%3},{%4,%5,%6,%7},{%8,%9},{%0,%1,%2,%3};"
        : "+f"(d[0]), "+f"(d[1]), "+f"(d[2]), "+f"(d[3])
        : "r"(a[0]), "r"(a[1]), "r"(a[2]), "r"(a[3]), "r"(b[0]), "r"(b[1]));
}
__device__ __forceinline__ void mma3(float d[4], const uint32_t ah[4], const uint32_t al[4],
                                     const uint32_t bh[2], const uint32_t bl[2]) {
    mma8(d, ah, bh); mma8(d, ah, bl); mma8(d, al, bh);
}
// A frag from fp32 smem, split in regs. [m][k] row-major, stride floats.
__device__ __forceinline__ void ldA2(const float* S, int stride, int m0, int k0, int lid,
                                     uint32_t ah[4], uint32_t al[4]) {
    const float* p = S + (m0 + (lid >> 2)) * stride + k0 + (lid & 3);
    splitf(p[0], ah[0], al[0]);
    splitf(p[8 * stride], ah[1], al[1]);
    splitf(p[4], ah[2], al[2]);
    splitf(p[8 * stride + 4], ah[3], al[3]);
}
// B frag from fp32 smem, split in regs. [n][k] rows, stride floats.
__device__ __forceinline__ void ldB2(const float* S, int stride, int n0, int k0, int lid,
                                     uint32_t bh[2], uint32_t bl[2]) {
    const float* p = S + (n0 + (lid >> 2)) * stride + k0 + (lid & 3);
    splitf(p[0], bh[0], bl[0]);
    splitf(p[4], bh[1], bl[1]);
}
// B frag from pre-split hi/lo planes.
__device__ __forceinline__ void ldBp(const float* Bh, const float* Bl, int stride, int n0, int k0,
                                     int lid, uint32_t bh[2], uint32_t bl[2]) {
    int off = (n0 + (lid >> 2)) * stride + k0 + (lid & 3);
    bh[0] = __float_as_uint(Bh[off]); bh[1] = __float_as_uint(Bh[off + 4]);
    bl[0] = __float_as_uint(Bl[off]); bl[1] = __float_as_uint(Bl[off + 4]);
}

// ---------------- weight prep ----------------
__global__ void prep_kernel(const float* __restrict__ nn1W, const float* __restrict__ nn1b,
                            const float* __restrict__ nn2W, const float* __restrict__ W2,
                            const float* __restrict__ wih0, const float* __restrict__ whh0,
                            const float* __restrict__ wih1, const float* __restrict__ whh1)
{
    int idx = blockIdx.x * 256 + threadIdx.x;   // 96 blocks -> 24576
    if (idx < 128 * 64) { int n = idx >> 6, k = idx & 63; g_w2T[idx] = W2[k * 128 + n]; }
    if (idx < 96 * 256) {
        int n = idx >> 8, k = idx & 255;
        float v = 0.f;
        if (n < 94) {
            if (k < 128) v = nn1W[k * 94 + n];
            else { int kk = k - 128; v = 0.25f * nn1W[(128 + kk) * 94 + n] + nn1W[(256 + kk) * 94 + n]; }
        }
        g_nn1T2[idx] = v;
    }
    if (idx < 64 * 96) { int n = idx / 96, k = idx % 96; g_nn2T[idx] = (k < 94) ? nn2W[k * 64 + n] : 0.f; }
    if (idx < 96) g_nn1bp[idx] = (idx < 94) ? nn1b[idx] : 0.f;
    if (idx < 96 * 256) { int gg = idx >> 8, d = idx & 255; g_wih0T[d * 96 + gg] = wih0[idx]; }
    if (idx < 96 * 32) {
        int gg = idx / 32, d = idx % 32;
        g_whh0T[d * 96 + gg] = whh0[idx];
        g_wih1T[d * 96 + gg] = wih1[idx];
        g_whh1T[d * 96 + gg] = whh1[idx];
    }
}

// ---------------- smem layout (bytes) ----------------
#define SM_XS    0        // 128*5*4    = 2560
#define SM_NBR   2560     // 128*4*4    = 2048
#define SM_W1BH  4608     // [64][20]   = 5120
#define SM_W1BL  9728     // 5120
#define SM_B1    14848    // 64*4
#define SM_B2    15104    // 128*4
#define SM_B1V   15616    // 96*4
#define SM_B2V   16000    // 64*4
#define SM_FEATS 16256    // [128][20]  = 10240
#define SM_W2T   26496    // [128][68]  = 34816 (fp32, B split in regs)
#define SM_STG   61312    // 34816: H [128][68] / B1 planes 2x[96][36]=27648
#define SM_HAGG  96128    // 133120: hagg [128][260] / later H2 [128][100] + B2 planes 2x[64][100]
#define SMEM_TOT 229248

// ---------------- mega kernel ----------------
__global__ void __launch_bounds__(256) mega_kernel(
    const float* __restrict__ x, const float* __restrict__ W1,
    const float* __restrict__ b1, const float* __restrict__ b2,
    const float* __restrict__ nn2b)
{
    extern __shared__ __align__(16) char smem[];
    float* xs    = (float*)(smem + SM_XS);
    int*   nbr   = (int*)(smem + SM_NBR);
    float* W1Bh  = (float*)(smem + SM_W1BH);
    float* W1Bl  = (float*)(smem + SM_W1BL);
    float* b1s   = (float*)(smem + SM_B1);
    float* b2s   = (float*)(smem + SM_B2);
    float* b1v   = (float*)(smem + SM_B1V);
    float* b2v   = (float*)(smem + SM_B2V);
    float* feats = (float*)(smem + SM_FEATS);
    float* W2T   = (float*)(smem + SM_W2T);
    float* stg   = (float*)(smem + SM_STG);     // H / B1 planes
    float* hagg  = (float*)(smem + SM_HAGG);    // [128][260]
    float* H2    = (float*)(smem + SM_HAGG);    // later [128][100]
    float* B2h   = (float*)(smem + SM_HAGG + 51200);
    float* B2l   = (float*)(smem + SM_HAGG + 76800);

    const int tid = threadIdx.x, wid = tid >> 5, lid = tid & 31;
    const int qr = lid >> 2, qc = lid & 3;
    const int g = blockIdx.x;
    const size_t base = (size_t)g * NP;

    for (int i = tid; i < NP * 5; i += 256) xs[i] = x[base * 5 + i];
    // W1 B-planes [64 n][20 k], k<10 real, rest 0
    for (int i = tid; i < 64 * 20; i += 256) {
        int n = i / 20, k = i % 20;
        float v = (k < 10) ? W1[k * 64 + n] : 0.f;
        uint32_t h, l; splitf(v, h, l);
        W1Bh[i] = __uint_as_float(h); W1Bl[i] = __uint_as_float(l);
    }
    if (tid < 64) b1s[tid] = b1[tid];
    if (tid >= 64 && tid < 192) b2s[tid - 64] = b2[tid - 64];
    if (tid >= 192 && tid < 256) b2v[tid - 192] = nn2b[tid - 192];
    for (int i = tid; i < 96; i += 256) b1v[i] = g_nn1bp[i];
    for (int i = tid; i < 2048; i += 256) {      // W2T -> [128][68] fp32
        int n = i >> 4, q = i & 15;
        *(float4*)&W2T[n * 68 + q * 4] = *(const float4*)&g_w2T[n * 64 + q * 4];
    }
    for (int i = tid; i < 128 * 20; i += 256) feats[i] = 0.f;   // zero k-padding
    __syncthreads();

    // ---- KNN (thread = node), stable ties
    if (tid < NP) {
        const float px = xs[tid * 5 + 0], py = xs[tid * 5 + 1], pz = xs[tid * 5 + 2];
        float d0 = 1e30f, d1 = 1e30f, d2v = 1e30f, d3 = 1e30f;
        int i0 = 0, i1 = 0, i2 = 0, i3 = 0;
        for (int j = 0; j < NP; j++) {
            if (j == tid) continue;
            float dx = xs[j * 5 + 0] - px, dy = xs[j * 5 + 1] - py, dz = xs[j * 5 + 2] - pz;
            float dd = dx * dx + dy * dy + dz * dz;
            if (dd < d3) {
                if (dd < d0)      { d3=d2v; i3=i2; d2v=d1; i2=i1; d1=d0; i1=i0; d0=dd; i0=j; }
                else if (dd < d1) { d3=d2v; i3=i2; d2v=d1; i2=i1; d1=dd; i1=j; }
                else if (dd < d2v){ d3=d2v; i3=i2; d2v=dd; i2=j; }
                else              { d3=dd; i3=j; }
            }
        }
        nbr[tid * 4 + 0] = i0; nbr[tid * 4 + 1] = i1; nbr[tid * 4 + 2] = i2; nbr[tid * 4 + 3] = i3;
    }
    __syncthreads();

    // ================= EdgeConv in 4 passes of 128 edges =================
    for (int p = 0; p < 4; p++) {
        // edge features [128][20] (cols 0-9) for edges p*128..p*128+127
        for (int i = tid; i < 128 * 10; i += 256) {
            int le = i / 10, d = i % 10;
            int node = p * 32 + (le >> 2), k = le & 3;
            float v;
            if (d < 5) v = xs[node * 5 + d];
            else { int j = nbr[node * 4 + k]; v = xs[j * 5 + (d - 5)] - xs[node * 5 + (d - 5)]; }
            feats[le * 20 + d] = v;
        }
        __syncthreads();

        // layer-1 mma: warp w -> rows 16w..16w+15, 8 nt (64 ch), K=16
        {
            float la[8][4];
#pragma unroll
            for (int nt = 0; nt < 8; nt++) { la[nt][0]=0.f; la[nt][1]=0.f; la[nt][2]=0.f; la[nt][3]=0.f; }
#pragma unroll
            for (int ks = 0; ks < 2; ks++) {
                uint32_t ah[4], al[4]; ldA2(feats, 20, wid * 16, ks * 8, lid, ah, al);
#pragma unroll
                for (int nt = 0; nt < 8; nt++) {
                    uint32_t bh[2], bl[2]; ldBp(W1Bh, W1Bl, 20, nt * 8, ks * 8, lid, bh, bl);
                    mma3(la[nt], ah, al, bh, bl);
                }
            }
            // epilogue: +b1, relu -> H [128][68] fp32 (warp-private rows)
            int r0 = wid * 16 + qr, r1 = r0 + 8;
#pragma unroll
            for (int nt = 0; nt < 8; nt++) {
                int col = nt * 8 + 2 * qc;
                stg[r0 * 68 + col]     = fmaxf(la[nt][0] + b1s[col], 0.f);
                stg[r0 * 68 + col + 1] = fmaxf(la[nt][1] + b1s[col + 1], 0.f);
                stg[r1 * 68 + col]     = fmaxf(la[nt][2] + b1s[col], 0.f);
                stg[r1 * 68 + col + 1] = fmaxf(la[nt][3] + b1s[col + 1], 0.f);
            }
        }
        __syncthreads();

        // layer-2 mma: warp w -> rows 16w..16w+15, 16 nt (128 cols), K=64
        float acc[16][4];
#pragma unroll
        for (int nt = 0; nt < 16; nt++) { acc[nt][0]=0.f; acc[nt][1]=0.f; acc[nt][2]=0.f; acc[nt][3]=0.f; }
#pragma unroll
        for (int ks = 0; ks < 8; ks++) {
            uint32_t ah[4], al[4]; ldA2(stg, 68, wid * 16, ks * 8, lid, ah, al);
#pragma unroll
            for (int nt = 0; nt < 16; nt++) {
                uint32_t bh[2], bl[2]; ldB2(W2T, 68, nt * 8, ks * 8, lid, bh, bl);
                mma3(acc[nt], ah, al, bh, bl);
            }
        }

        // epilogue: +b2, relu, reduce 4 edges -> node (shfl xor 4,8), write hagg fp32
        const int nodeBase = p * 32 + wid * 4;
#pragma unroll
        for (int nt = 0; nt < 16; nt++) {
            int col = nt * 8 + 2 * qc;
            float v0 = fmaxf(acc[nt][0] + b2s[col], 0.f);
            float v1 = fmaxf(acc[nt][1] + b2s[col + 1], 0.f);
            float v2 = fmaxf(acc[nt][2] + b2s[col], 0.f);
            float v3 = fmaxf(acc[nt][3] + b2s[col + 1], 0.f);
            float m0 = v0, m1 = v1, m2 = v2, m3 = v3;
            float s0 = v0, s1 = v1, s2 = v2, s3 = v3;
            m0 = fmaxf(m0, __shfl_xor_sync(0xffffffffu, m0, 4)); s0 += __shfl_xor_sync(0xffffffffu, s0, 4);
            m1 = fmaxf(m1, __shfl_xor_sync(0xffffffffu, m1, 4)); s1 += __shfl_xor_sync(0xffffffffu, s1, 4);
            m2 = fmaxf(m2, __shfl_xor_sync(0xffffffffu, m2, 4)); s2 += __shfl_xor_sync(0xffffffffu, s2, 4);
            m3 = fmaxf(m3, __shfl_xor_sync(0xffffffffu, m3, 4)); s3 += __shfl_xor_sync(0xffffffffu, s3, 4);
            m0 = fmaxf(m0, __shfl_xor_sync(0xffffffffu, m0, 8)); s0 += __shfl_xor_sync(0xffffffffu, s0, 8);
            m1 = fmaxf(m1, __shfl_xor_sync(0xffffffffu, m1, 8)); s1 += __shfl_xor_sync(0xffffffffu, s1, 8);
            m2 = fmaxf(m2, __shfl_xor_sync(0xffffffffu, m2, 8)); s2 += __shfl_xor_sync(0xffffffffu, s2, 8);
            m3 = fmaxf(m3, __shfl_xor_sync(0xffffffffu, m3, 8)); s3 += __shfl_xor_sync(0xffffffffu, s3, 8);
            if (qr == 0 || qr == 4) {
                int nA = nodeBase + (qr >> 2);
                int nB = nodeBase + 2 + (qr >> 2);
                float* hA = hagg + (size_t)nA * 260;
                float* hB = hagg + (size_t)nB * 260;
                hA[col] = m0; hA[col + 1] = m1;
                hA[128 + col] = s0; hA[128 + col + 1] = s1;
                hB[col] = m2; hB[col + 1] = m3;
                hB[128 + col] = s2; hB[128 + col + 1] = s3;
            }
        }
        __syncthreads();
    }

    // ================= nn1: [128][256] @ [256][96], B pre-split per chunk =================
    float acc1[12][4];
#pragma unroll
    for (int nt = 0; nt < 12; nt++) { acc1[nt][0]=0.f; acc1[nt][1]=0.f; acc1[nt][2]=0.f; acc1[nt][3]=0.f; }
    float* B1h = stg;                 // [96][36]
    float* B1l = stg + 96 * 36;       // [96][36]
    for (int kc = 0; kc < 8; kc++) {
        for (int i = tid; i < 768; i += 256) {    // split-load B1 chunk
            int n = i >> 3, q = i & 7;
            float4 v = *(const float4*)&g_nn1T2[n * 256 + kc * 32 + q * 4];
            float4 vh, vl; uint32_t h, l;
            splitf(v.x, h, l); vh.x = __uint_as_float(h); vl.x = __uint_as_float(l);
            splitf(v.y, h, l); vh.y = __uint_as_float(h); vl.y = __uint_as_float(l);
            splitf(v.z, h, l); vh.z = __uint_as_float(h); vl.z = __uint_as_float(l);
            splitf(v.w, h, l); vh.w = __uint_as_float(h); vl.w = __uint_as_float(l);
            *(float4*)&B1h[n * 36 + q * 4] = vh;
            *(float4*)&B1l[n * 36 + q * 4] = vl;
        }
        __syncthreads();
#pragma unroll
        for (int ks = 0; ks < 4; ks++) {
            uint32_t ah[4], al[4]; ldA2(hagg, 260, wid * 16, kc * 32 + ks * 8, lid, ah, al);
#pragma unroll
            for (int nt = 0; nt < 12; nt++) {
                uint32_t bh[2], bl[2]; ldBp(B1h, B1l, 36, nt * 8, ks * 8, lid, bh, bl);
                mma3(acc1[nt], ah, al, bh, bl);
            }
        }
        __syncthreads();
    }
    // epilogue1: H2 [128][100] = relu(acc1 + b1v), plus split-load B2 into hagg tail
    {
        int r0 = wid * 16 + qr, r1 = r0 + 8;
#pragma unroll
        for (int nt = 0; nt < 12; nt++) {
            int col = nt * 8 + 2 * qc;
            H2[r0 * 100 + col]     = fmaxf(acc1[nt][0] + b1v[col], 0.f);
            H2[r0 * 100 + col + 1] = fmaxf(acc1[nt][1] + b1v[col + 1], 0.f);
            H2[r1 * 100 + col]     = fmaxf(acc1[nt][2] + b1v[col], 0.f);
            H2[r1 * 100 + col + 1] = fmaxf(acc1[nt][3] + b1v[col + 1], 0.f);
        }
        for (int i = tid; i < 1536; i += 256) {   // B2 [64][100] hi/lo
            int n = i / 24, q = i % 24;
            float4 v = *(const float4*)&g_nn2T[n * 96 + q * 4];
            float4 vh, vl; uint32_t h, l;
            splitf(v.x, h, l); vh.x = __uint_as_float(h); vl.x = __uint_as_float(l);
            splitf(v.y, h, l); vh.y = __uint_as_float(h); vl.y = __uint_as_float(l);
            splitf(v.z, h, l); vh.z = __uint_as_float(h); vl.z = __uint_as_float(l);
            splitf(v.w, h, l); vh.w = __uint_as_float(h); vl.w = __uint_as_float(l);
            *(float4*)&B2h[n * 100 + q * 4] = vh;
            *(float4*)&B2l[n * 100 + q * 4] = vl;
        }
    }
    __syncthreads();

    // ================= nn2: [128][96] @ [96][64] =================
    float acc2[8][4];
#pragma unroll
    for (int nt = 0; nt < 8; nt++) { acc2[nt][0]=0.f; acc2[nt][1]=0.f; acc2[nt][2]=0.f; acc2[nt][3]=0.f; }
#pragma unroll
    for (int ks = 0; ks < 12; ks++) {
        uint32_t ah[4], al[4]; ldA2(H2, 100, wid * 16, ks * 8, lid, ah, al);
#pragma unroll
        for (int nt = 0; nt < 8; nt++) {
            uint32_t bh[2], bl[2]; ldBp(B2h, B2l, 100, nt * 8, ks * 8, lid, bh, bl);
            mma3(acc2[nt], ah, al, bh, bl);
        }
    }
    __syncthreads();
    // h2 [128][68] fp32 (+bias, no relu) into stg
    {
        int r0 = wid * 16 + qr, r1 = r0 + 8;
#pragma unroll
        for (int nt = 0; nt < 8; nt++) {
            int col = nt * 8 + 2 * qc;
            stg[r0 * 68 + col]     = acc2[nt][0] + b2v[col];
            stg[r0 * 68 + col + 1] = acc2[nt][1] + b2v[col + 1];
            stg[r1 * 68 + col]     = acc2[nt][2] + b2v[col];
            stg[r1 * 68 + col + 1] = acc2[nt][3] + b2v[col + 1];
        }
    }
    __syncthreads();

    // ================= segment max/min/sum/mean + relu -> g_gfeat =================
    {
        int c = tid & 63, q = tid >> 6;
        float mx = -1e30f, mn = 1e30f, sm = 0.f;
        for (int r = q * 32; r < q * 32 + 32; r++) {
            float v = stg[r * 68 + c];
            mx = fmaxf(mx, v); mn = fminf(mn, v); sm += v;
        }
        feats[q * 192 + c] = mx; feats[q * 192 + 64 + c] = mn; feats[q * 192 + 128 + c] = sm;
        __syncthreads();
        if (tid < 64) {
            float MX = feats[c], MN = feats[64 + c], SM = feats[128 + c];
            for (int qq = 1; qq < 4; qq++) {
                MX = fmaxf(MX, feats[qq * 192 + c]);
                MN = fminf(MN, feats[qq * 192 + 64 + c]);
                SM += feats[qq * 192 + 128 + c];
            }
            float* o = g_gfeat + (size_t)g * 256;
            o[c]        = fmaxf(MX, 0.f);
            o[64 + c]   = fmaxf(MN, 0.f);
            o[128 + c]  = fmaxf(SM, 0.f);
            o[192 + c]  = fmaxf(SM * (1.f / 128.f), 0.f);
        }
    }
}

// ---------------- g.reshape(2,256,1024).transpose(0,2,1) ----------------
__global__ void permute_kernel()
{
    const int idx = blockIdx.x * 256 + threadIdx.x;
    const int i = idx & 255;
    const int b = (idx >> 8) & 1023;
    const int t = idx >> 18;
    g_xin[idx] = g_gfeat[(t * 1024 + i * 4 + (b >> 8)) * 256 + (b & 255)];
}

// ---------------- one GRU step (PyTorch gate order r,z,n) ----------------
__global__ void __launch_bounds__(96) gru_step_kernel(
    const float* __restrict__ x, int IN,
    const float* __restrict__ h_in,
    const float* __restrict__ wihT, const float* __restrict__ whhT,
    const float* __restrict__ bih, const float* __restrict__ bhh,
    float* __restrict__ h_out)
{
    __shared__ float xs[16][256];
    __shared__ float hs[16][32];
    __shared__ float gi_s[16][96];
    __shared__ float gh_s[16][96];
    const int g = threadIdx.x;
    const int r0 = blockIdx.x * 16;

    for (int i = g; i < 16 * IN; i += 96) xs[i / IN][i % IN] = x[(size_t)r0 * IN + i];
    for (int i = g; i < 16 * 32; i += 96) hs[i / 32][i % 32] = h_in[r0 * 32 + i];
    __syncthreads();

    const float bi = bih[g], bh = bhh[g];
    for (int r = 0; r < 16; r++) {
        float ai = bi;
        for (int d = 0; d < IN; d++) ai = fmaf(xs[r][d], wihT[d * 96 + g], ai);
        float ah = bh;
#pragma unroll
        for (int d = 0; d < 32; d++) ah = fmaf(hs[r][d], whhT[d * 96 + g], ah);
        gi_s[r][g] = ai; gh_s[r][g] = ah;
    }
    __syncthreads();

    if (g < 32) {
        for (int r = 0; r < 16; r++) {
            const float ir = gi_s[r][g],       hr = gh_s[r][g];
            const float iz = gi_s[r][g + 32],  hz = gh_s[r][g + 32];
            const float in_ = gi_s[r][g + 64], hn = gh_s[r][g + 64];
            const float rr = 1.f / (1.f + expf(-(ir + hr)));
            const float zz = 1.f / (1.f + expf(-(iz + hz)));
            const float nn = tanhf(in_ + rr * hn);
            h_out[(r0 + r) * 32 + g] = (1.f - zz) * nn + zz * hs[r][g];
        }
    }
}

// ---------------- final head + hT pack ----------------
__global__ void final_kernel(const float* __restrict__ nn4W, const float* __restrict__ nn4b,
                             float* __restrict__ out, int out_size)
{
    const int idx = blockIdx.x * 256 + threadIdx.x;
    if (idx >= out_size) return;
    if (idx < 2048) {
        const int t  = idx >> 10;
        const int ch = (idx >> 5) & 31;
        const int b0 = (idx & 31) * 32;
        float acc = nn4b[0];
#pragma unroll
        for (int c = 0; c < 32; c++) {
            const float v = g_out1[t * 32768 + (b0 + c) * 32 + ch];
            acc = fmaf(fmaxf(v, 0.f), nn4W[c], acc);
        }
        out[idx] = fmaxf(acc, 0.f);
    } else if (idx < 2048 + 65536) {
        const int j = idx - 2048;
        out[idx] = (j < 32768) ? g_out0[32768 + j] : g_out1[32768 + (j - 32768)];
    }
}

// ---------------- launch ----------------
extern "C" void kernel_launch(void* const* d_in, const int* in_sizes, int n_in,
                              void* d_out, int out_size)
{
    const float* x    = (const float*)d_in[0];
    const float* h1   = (const float*)d_in[2];
    const float* W1   = (const float*)d_in[3];
    const float* b1   = (const float*)d_in[4];
    const float* W2   = (const float*)d_in[5];
    const float* b2   = (const float*)d_in[6];
    const float* nn1W = (const float*)d_in[7];
    const float* nn1b = (const float*)d_in[8];
    const float* nn2W = (const float*)d_in[9];
    const float* nn2b = (const float*)d_in[10];
    const float* nn4W = (const float*)d_in[11];
    const float* nn4b = (const float*)d_in[12];
    const float* wih0 = (const float*)d_in[13];
    const float* whh0 = (const float*)d_in[14];
    const float* bih0 = (const float*)d_in[15];
    const float* bhh0 = (const float*)d_in[16];
    const float* wih1 = (const float*)d_in[17];
    const float* whh1 = (const float*)d_in[18];
    const float* bih1 = (const float*)d_in[19];
    const float* bhh1 = (const float*)d_in[20];
    float* out = (float*)d_out;

    float *xin, *out0, *out1, *wih0T, *whh0T, *wih1T, *whh1T;
    cudaGetSymbolAddress((void**)&xin,   g_xin);
    cudaGetSymbolAddress((void**)&out0,  g_out0);
    cudaGetSymbolAddress((void**)&out1,  g_out1);
    cudaGetSymbolAddress((void**)&wih0T, g_wih0T);
    cudaGetSymbolAddress((void**)&whh0T, g_whh0T);
    cudaGetSymbolAddress((void**)&wih1T, g_wih1T);
    cudaGetSymbolAddress((void**)&whh1T, g_whh1T);

    cudaFuncSetAttribute(mega_kernel, cudaFuncAttributeMaxDynamicSharedMemorySize, SMEM_TOT);

    prep_kernel<<<96, 256>>>(nn1W, nn1b, nn2W, W2, wih0, whh0, wih1, whh1);
    mega_kernel<<<NG, 256, SMEM_TOT>>>(x, W1, b1, b2, nn2b);
    permute_kernel<<<2048, 256>>>();
    gru_step_kernel<<<64, 96>>>(xin,          256, h1,         wih0T, whh0T, bih0, bhh0, out0);
    gru_step_kernel<<<64, 96>>>(xin + 262144, 256, out0,       wih0T, whh0T, bih0, bhh0, out0 + 32768);
    gru_step_kernel<<<64, 96>>>(out0,          32, h1 + 32768, wih1T, whh1T, bih1, bhh1, out1);
    gru_step_kernel<<<64, 96>>>(out0 + 32768,  32, out1,       wih1T, whh1T, bih1, bhh1, out1 + 32768);
    final_kernel<<<(out_size + 255) / 256, 256>>>(nn4W, nn4b, out, out_size);
}

// round 5
// speedup vs baseline: 1.4180x; 1.1539x over previous
#include <cuda_runtime.h>
#include <math.h>
#include <stdint.h>

#define NG 2048
#define NP 128

// ---------------- scratch (device globals) ----------------
__device__ float g_gfeat[NG * 256];
__device__ float g_xin[2 * 1024 * 256];
__device__ float g_gi[2 * 1024 * 96];
__device__ float g_out0[2 * 1024 * 32];
__device__ float g_out1[2 * 1024 * 32];
__device__ float g_w2T[128 * 64];      // edge W2^T  [n][k] fp32
__device__ float g_nn1T2[96 * 256];    // folded nn1^T [n][k=256] fp32
__device__ float g_nn2T[64 * 96];      // nn2^T [n][k] fp32 (padded k)
__device__ float g_nn1bp[96];
__device__ float g_wih0T[256 * 96];    // [k][n] for GI gemm

// ---------------- helpers ----------------
__device__ __forceinline__ float cvt_tf32(float x) {
    float r; asm("cvt.rna.tf32.f32 %0, %1;" : "=f"(r) : "f"(x)); return r;
}
__device__ __forceinline__ void splitf(float x, uint32_t& h, uint32_t& l) {
    float hh = cvt_tf32(x);
    h = __float_as_uint(hh);
    l = __float_as_uint(cvt_tf32(x - hh));
}
__device__ __forceinline__ void mma8(float d[4], const uint32_t a[4], const uint32_t b[2]) {
    asm volatile(
        "mma.sync.aligned.m16n8k8.row.col.f32.tf32.tf32.f32 "
        "{%0,%1,%2,%3},{%4,%5,%6,%7},{%8,%9},{%0,%1,%2,%3};"
        : "+f"(d[0]), "+f"(d[1]), "+f"(d[2]), "+f"(d[3])
        : "r"(a[0]), "r"(a[1]), "r"(a[2]), "r"(a[3]), "r"(b[0]), "r"(b[1]));
}
__device__ __forceinline__ void mma3(float d[4], const uint32_t ah[4], const uint32_t al[4],
                                     const uint32_t bh[2], const uint32_t bl[2]) {
    mma8(d, ah, bh); mma8(d, ah, bl); mma8(d, al, bh);
}
__device__ __forceinline__ void ldA2(const float* S, int stride, int m0, int k0, int lid,
                                     uint32_t ah[4], uint32_t al[4]) {
    const float* p = S + (m0 + (lid >> 2)) * stride + k0 + (lid & 3);
    splitf(p[0], ah[0], al[0]);
    splitf(p[8 * stride], ah[1], al[1]);
    splitf(p[4], ah[2], al[2]);
    splitf(p[8 * stride + 4], ah[3], al[3]);
}
__device__ __forceinline__ void ldB2(const float* S, int stride, int n0, int k0, int lid,
                                     uint32_t bh[2], uint32_t bl[2]) {
    const float* p = S + (n0 + (lid >> 2)) * stride + k0 + (lid & 3);
    splitf(p[0], bh[0], bl[0]);
    splitf(p[4], bh[1], bl[1]);
}
__device__ __forceinline__ void ldBp(const float* Bh, const float* Bl, int stride, int n0, int k0,
                                     int lid, uint32_t bh[2], uint32_t bl[2]) {
    int off = (n0 + (lid >> 2)) * stride + k0 + (lid & 3);
    bh[0] = __float_as_uint(Bh[off]); bh[1] = __float_as_uint(Bh[off + 4]);
    bl[0] = __float_as_uint(Bl[off]); bl[1] = __float_as_uint(Bl[off + 4]);
}

// ---------------- weight prep ----------------
__global__ void prep_kernel(const float* __restrict__ nn1W, const float* __restrict__ nn1b,
                            const float* __restrict__ nn2W, const float* __restrict__ W2,
                            const float* __restrict__ wih0)
{
    int idx = blockIdx.x * 256 + threadIdx.x;   // 96 blocks -> 24576
    if (idx < 128 * 64) { int n = idx >> 6, k = idx & 63; g_w2T[idx] = W2[k * 128 + n]; }
    if (idx < 96 * 256) {
        int n = idx >> 8, k = idx & 255;
        float v = 0.f;
        if (n < 94) {
            if (k < 128) v = nn1W[k * 94 + n];
            else { int kk = k - 128; v = 0.25f * nn1W[(128 + kk) * 94 + n] + nn1W[(256 + kk) * 94 + n]; }
        }
        g_nn1T2[idx] = v;
    }
    if (idx < 64 * 96) { int n = idx / 96, k = idx % 96; g_nn2T[idx] = (k < 94) ? nn2W[k * 64 + n] : 0.f; }
    if (idx < 96) g_nn1bp[idx] = (idx < 94) ? nn1b[idx] : 0.f;
    if (idx < 96 * 256) { int gg = idx >> 8, d = idx & 255; g_wih0T[d * 96 + gg] = wih0[idx]; }
}

// ---------------- smem layout (bytes) ----------------
#define SM_XS    0        // 128*5*4    = 2560
#define SM_NBR   2560     // 128*4*4    = 2048
#define SM_W1BH  4608     // [64][20]   = 5120
#define SM_W1BL  9728     // 5120
#define SM_B1    14848    // 64*4
#define SM_B2    15104    // 128*4
#define SM_B1V   15616    // 96*4
#define SM_B2V   16000    // 64*4
#define SM_FEATS 16256    // [128][20]  = 10240
#define SM_W2T   26496    // [128][68]  = 34816 (fp32, B split in regs)
#define SM_STG   61312    // 34816: H [128][68] / B1 planes 2x[96][36]
#define SM_HAGG  96128    // 133120: hagg [128][260] / later H2 [128][100] + B2 planes
#define SMEM_TOT 229248

// ---------------- mega kernel (512 threads: warp-pairs split nt) ----------------
__global__ void __launch_bounds__(512) mega_kernel(
    const float* __restrict__ x, const float* __restrict__ W1,
    const float* __restrict__ b1, const float* __restrict__ b2,
    const float* __restrict__ nn2b)
{
    extern __shared__ __align__(16) char smem[];
    float* xs    = (float*)(smem + SM_XS);
    int*   nbr   = (int*)(smem + SM_NBR);
    float* W1Bh  = (float*)(smem + SM_W1BH);
    float* W1Bl  = (float*)(smem + SM_W1BL);
    float* b1s   = (float*)(smem + SM_B1);
    float* b2s   = (float*)(smem + SM_B2);
    float* b1v   = (float*)(smem + SM_B1V);
    float* b2v   = (float*)(smem + SM_B2V);
    float* feats = (float*)(smem + SM_FEATS);
    float* W2T   = (float*)(smem + SM_W2T);
    float* stg   = (float*)(smem + SM_STG);
    float* hagg  = (float*)(smem + SM_HAGG);    // [128][260]
    float* H2    = (float*)(smem + SM_HAGG);    // later [128][100]
    float* B2h   = (float*)(smem + SM_HAGG + 51200);
    float* B2l   = (float*)(smem + SM_HAGG + 76800);

    const int tid = threadIdx.x, wid = tid >> 5, lid = tid & 31;
    const int rw = wid >> 1;          // row-group 0..7 (16 rows each)
    const int nh = wid & 1;           // nt half
    const int qr = lid >> 2, qc = lid & 3;
    const int g = blockIdx.x;
    const size_t base = (size_t)g * NP;

    for (int i = tid; i < NP * 5; i += 512) xs[i] = x[base * 5 + i];
    for (int i = tid; i < 64 * 20; i += 512) {
        int n = i / 20, k = i % 20;
        float v = (k < 10) ? W1[k * 64 + n] : 0.f;
        uint32_t h, l; splitf(v, h, l);
        W1Bh[i] = __uint_as_float(h); W1Bl[i] = __uint_as_float(l);
    }
    if (tid < 64) b1s[tid] = b1[tid];
    if (tid >= 64 && tid < 192) b2s[tid - 64] = b2[tid - 64];
    if (tid >= 192 && tid < 256) b2v[tid - 192] = nn2b[tid - 192];
    if (tid >= 256 && tid < 352) b1v[tid - 256] = g_nn1bp[tid - 256];
    for (int i = tid; i < 2048; i += 512) {      // W2T -> [128][68] fp32
        int n = i >> 4, q = i & 15;
        *(float4*)&W2T[n * 68 + q * 4] = *(const float4*)&g_w2T[n * 64 + q * 4];
    }
    for (int i = tid; i < 128 * 20; i += 512) feats[i] = 0.f;
    __syncthreads();

    // ---- KNN (thread = node), stable ties
    if (tid < NP) {
        const float px = xs[tid * 5 + 0], py = xs[tid * 5 + 1], pz = xs[tid * 5 + 2];
        float d0 = 1e30f, d1 = 1e30f, d2v = 1e30f, d3 = 1e30f;
        int i0 = 0, i1 = 0, i2 = 0, i3 = 0;
        for (int j = 0; j < NP; j++) {
            if (j == tid) continue;
            float dx = xs[j * 5 + 0] - px, dy = xs[j * 5 + 1] - py, dz = xs[j * 5 + 2] - pz;
            float dd = dx * dx + dy * dy + dz * dz;
            if (dd < d3) {
                if (dd < d0)      { d3=d2v; i3=i2; d2v=d1; i2=i1; d1=d0; i1=i0; d0=dd; i0=j; }
                else if (dd < d1) { d3=d2v; i3=i2; d2v=d1; i2=i1; d1=dd; i1=j; }
                else if (dd < d2v){ d3=d2v; i3=i2; d2v=dd; i2=j; }
                else              { d3=dd; i3=j; }
            }
        }
        nbr[tid * 4 + 0] = i0; nbr[tid * 4 + 1] = i1; nbr[tid * 4 + 2] = i2; nbr[tid * 4 + 3] = i3;
    }
    __syncthreads();

    // ================= EdgeConv in 4 passes of 128 edges =================
    for (int p = 0; p < 4; p++) {
        for (int i = tid; i < 128 * 10; i += 512) {
            int le = i / 10, d = i % 10;
            int node = p * 32 + (le >> 2), k = le & 3;
            float v;
            if (d < 5) v = xs[node * 5 + d];
            else { int j = nbr[node * 4 + k]; v = xs[j * 5 + (d - 5)] - xs[node * 5 + (d - 5)]; }
            feats[le * 20 + d] = v;
        }
        __syncthreads();

        // layer-1 mma: row-group rw, warp handles 4 of 8 nt
        {
            float la[4][4];
#pragma unroll
            for (int j = 0; j < 4; j++) { la[j][0]=0.f; la[j][1]=0.f; la[j][2]=0.f; la[j][3]=0.f; }
#pragma unroll
            for (int ks = 0; ks < 2; ks++) {
                uint32_t ah[4], al[4]; ldA2(feats, 20, rw * 16, ks * 8, lid, ah, al);
#pragma unroll
                for (int j = 0; j < 4; j++) {
                    int nt = nh * 4 + j;
                    uint32_t bh[2], bl[2]; ldBp(W1Bh, W1Bl, 20, nt * 8, ks * 8, lid, bh, bl);
                    mma3(la[j], ah, al, bh, bl);
                }
            }
            int r0 = rw * 16 + qr, r1 = r0 + 8;
#pragma unroll
            for (int j = 0; j < 4; j++) {
                int col = (nh * 4 + j) * 8 + 2 * qc;
                stg[r0 * 68 + col]     = fmaxf(la[j][0] + b1s[col], 0.f);
                stg[r0 * 68 + col + 1] = fmaxf(la[j][1] + b1s[col + 1], 0.f);
                stg[r1 * 68 + col]     = fmaxf(la[j][2] + b1s[col], 0.f);
                stg[r1 * 68 + col + 1] = fmaxf(la[j][3] + b1s[col + 1], 0.f);
            }
        }
        __syncthreads();

        // layer-2 mma: warp handles 8 of 16 nt, K=64
        float acc[8][4];
#pragma unroll
        for (int j = 0; j < 8; j++) { acc[j][0]=0.f; acc[j][1]=0.f; acc[j][2]=0.f; acc[j][3]=0.f; }
#pragma unroll
        for (int ks = 0; ks < 8; ks++) {
            uint32_t ah[4], al[4]; ldA2(stg, 68, rw * 16, ks * 8, lid, ah, al);
#pragma unroll
            for (int j = 0; j < 8; j++) {
                int nt = nh * 8 + j;
                uint32_t bh[2], bl[2]; ldB2(W2T, 68, nt * 8, ks * 8, lid, bh, bl);
                mma3(acc[j], ah, al, bh, bl);
            }
        }

        // epilogue: +b2, relu, reduce 4 edges -> node (shfl xor 4,8), write hagg
        const int nodeBase = p * 32 + rw * 4;
#pragma unroll
        for (int j = 0; j < 8; j++) {
            int col = (nh * 8 + j) * 8 + 2 * qc;
            float v0 = fmaxf(acc[j][0] + b2s[col], 0.f);
            float v1 = fmaxf(acc[j][1] + b2s[col + 1], 0.f);
            float v2 = fmaxf(acc[j][2] + b2s[col], 0.f);
            float v3 = fmaxf(acc[j][3] + b2s[col + 1], 0.f);
            float m0 = v0, m1 = v1, m2 = v2, m3 = v3;
            float s0 = v0, s1 = v1, s2 = v2, s3 = v3;
            m0 = fmaxf(m0, __shfl_xor_sync(0xffffffffu, m0, 4)); s0 += __shfl_xor_sync(0xffffffffu, s0, 4);
            m1 = fmaxf(m1, __shfl_xor_sync(0xffffffffu, m1, 4)); s1 += __shfl_xor_sync(0xffffffffu, s1, 4);
            m2 = fmaxf(m2, __shfl_xor_sync(0xffffffffu, m2, 4)); s2 += __shfl_xor_sync(0xffffffffu, s2, 4);
            m3 = fmaxf(m3, __shfl_xor_sync(0xffffffffu, m3, 4)); s3 += __shfl_xor_sync(0xffffffffu, s3, 4);
            m0 = fmaxf(m0, __shfl_xor_sync(0xffffffffu, m0, 8)); s0 += __shfl_xor_sync(0xffffffffu, s0, 8);
            m1 = fmaxf(m1, __shfl_xor_sync(0xffffffffu, m1, 8)); s1 += __shfl_xor_sync(0xffffffffu, s1, 8);
            m2 = fmaxf(m2, __shfl_xor_sync(0xffffffffu, m2, 8)); s2 += __shfl_xor_sync(0xffffffffu, s2, 8);
            m3 = fmaxf(m3, __shfl_xor_sync(0xffffffffu, m3, 8)); s3 += __shfl_xor_sync(0xffffffffu, s3, 8);
            if (qr == 0 || qr == 4) {
                int nA = nodeBase + (qr >> 2);
                int nB = nodeBase + 2 + (qr >> 2);
                float* hA = hagg + (size_t)nA * 260;
                float* hB = hagg + (size_t)nB * 260;
                hA[col] = m0; hA[col + 1] = m1;
                hA[128 + col] = s0; hA[128 + col + 1] = s1;
                hB[col] = m2; hB[col + 1] = m3;
                hB[128 + col] = s2; hB[128 + col + 1] = s3;
            }
        }
        __syncthreads();
    }

    // ================= nn1: [128][256] @ [256][96], warp does 6 of 12 nt =================
    float acc1[6][4];
#pragma unroll
    for (int j = 0; j < 6; j++) { acc1[j][0]=0.f; acc1[j][1]=0.f; acc1[j][2]=0.f; acc1[j][3]=0.f; }
    float* B1h = stg;
    float* B1l = stg + 96 * 36;
    for (int kc = 0; kc < 8; kc++) {
        for (int i = tid; i < 768; i += 512) {
            int n = i >> 3, q = i & 7;
            float4 v = *(const float4*)&g_nn1T2[n * 256 + kc * 32 + q * 4];
            float4 vh, vl; uint32_t h, l;
            splitf(v.x, h, l); vh.x = __uint_as_float(h); vl.x = __uint_as_float(l);
            splitf(v.y, h, l); vh.y = __uint_as_float(h); vl.y = __uint_as_float(l);
            splitf(v.z, h, l); vh.z = __uint_as_float(h); vl.z = __uint_as_float(l);
            splitf(v.w, h, l); vh.w = __uint_as_float(h); vl.w = __uint_as_float(l);
            *(float4*)&B1h[n * 36 + q * 4] = vh;
            *(float4*)&B1l[n * 36 + q * 4] = vl;
        }
        __syncthreads();
#pragma unroll
        for (int ks = 0; ks < 4; ks++) {
            uint32_t ah[4], al[4]; ldA2(hagg, 260, rw * 16, kc * 32 + ks * 8, lid, ah, al);
#pragma unroll
            for (int j = 0; j < 6; j++) {
                int nt = nh * 6 + j;
                uint32_t bh[2], bl[2]; ldBp(B1h, B1l, 36, nt * 8, ks * 8, lid, bh, bl);
                mma3(acc1[j], ah, al, bh, bl);
            }
        }
        __syncthreads();
    }
    // epilogue1: H2 [128][100] = relu(acc1 + b1v); split-load B2 planes
    {
        int r0 = rw * 16 + qr, r1 = r0 + 8;
#pragma unroll
        for (int j = 0; j < 6; j++) {
            int col = (nh * 6 + j) * 8 + 2 * qc;
            H2[r0 * 100 + col]     = fmaxf(acc1[j][0] + b1v[col], 0.f);
            H2[r0 * 100 + col + 1] = fmaxf(acc1[j][1] + b1v[col + 1], 0.f);
            H2[r1 * 100 + col]     = fmaxf(acc1[j][2] + b1v[col], 0.f);
            H2[r1 * 100 + col + 1] = fmaxf(acc1[j][3] + b1v[col + 1], 0.f);
        }
        for (int i = tid; i < 1536; i += 512) {
            int n = i / 24, q = i % 24;
            float4 v = *(const float4*)&g_nn2T[n * 96 + q * 4];
            float4 vh, vl; uint32_t h, l;
            splitf(v.x, h, l); vh.x = __uint_as_float(h); vl.x = __uint_as_float(l);
            splitf(v.y, h, l); vh.y = __uint_as_float(h); vl.y = __uint_as_float(l);
            splitf(v.z, h, l); vh.z = __uint_as_float(h); vl.z = __uint_as_float(l);
            splitf(v.w, h, l); vh.w = __uint_as_float(h); vl.w = __uint_as_float(l);
            *(float4*)&B2h[n * 100 + q * 4] = vh;
            *(float4*)&B2l[n * 100 + q * 4] = vl;
        }
    }
    __syncthreads();

    // ================= nn2: [128][96] @ [96][64], warp does 4 of 8 nt =================
    float acc2[4][4];
#pragma unroll
    for (int j = 0; j < 4; j++) { acc2[j][0]=0.f; acc2[j][1]=0.f; acc2[j][2]=0.f; acc2[j][3]=0.f; }
#pragma unroll
    for (int ks = 0; ks < 12; ks++) {
        uint32_t ah[4], al[4]; ldA2(H2, 100, rw * 16, ks * 8, lid, ah, al);
#pragma unroll
        for (int j = 0; j < 4; j++) {
            int nt = nh * 4 + j;
            uint32_t bh[2], bl[2]; ldBp(B2h, B2l, 100, nt * 8, ks * 8, lid, bh, bl);
            mma3(acc2[j], ah, al, bh, bl);
        }
    }
    __syncthreads();
    // h2 [128][68] fp32 into stg
    {
        int r0 = rw * 16 + qr, r1 = r0 + 8;
#pragma unroll
        for (int j = 0; j < 4; j++) {
            int col = (nh * 4 + j) * 8 + 2 * qc;
            stg[r0 * 68 + col]     = acc2[j][0] + b2v[col];
            stg[r0 * 68 + col + 1] = acc2[j][1] + b2v[col + 1];
            stg[r1 * 68 + col]     = acc2[j][2] + b2v[col];
            stg[r1 * 68 + col + 1] = acc2[j][3] + b2v[col + 1];
        }
    }
    __syncthreads();

    // ================= segment max/min/sum/mean + relu -> g_gfeat =================
    {
        int c = tid & 63, q = tid >> 6;     // q 0..7, 16 rows each
        float mx = -1e30f, mn = 1e30f, sm = 0.f;
        for (int r = q * 16; r < q * 16 + 16; r++) {
            float v = stg[r * 68 + c];
            mx = fmaxf(mx, v); mn = fminf(mn, v); sm += v;
        }
        feats[q * 192 + c] = mx; feats[q * 192 + 64 + c] = mn; feats[q * 192 + 128 + c] = sm;
        __syncthreads();
        if (tid < 64) {
            float MX = feats[c], MN = feats[64 + c], SM = feats[128 + c];
            for (int qq = 1; qq < 8; qq++) {
                MX = fmaxf(MX, feats[qq * 192 + c]);
                MN = fminf(MN, feats[qq * 192 + 64 + c]);
                SM += feats[qq * 192 + 128 + c];
            }
            float* o = g_gfeat + (size_t)g * 256;
            o[c]        = fmaxf(MX, 0.f);
            o[64 + c]   = fmaxf(MN, 0.f);
            o[128 + c]  = fmaxf(SM, 0.f);
            o[192 + c]  = fmaxf(SM * (1.f / 128.f), 0.f);
        }
    }
}

// ---------------- g.reshape(2,256,1024).transpose(0,2,1) ----------------
__global__ void permute_kernel()
{
    const int idx = blockIdx.x * 256 + threadIdx.x;
    const int i = idx & 255;
    const int b = (idx >> 8) & 1023;
    const int t = idx >> 18;
    g_xin[idx] = g_gfeat[(t * 1024 + i * 4 + (b >> 8)) * 256 + (b & 255)];
}

// ---------------- tiled GEMM for GI = xin @ wih0T + bih0 ----------------
template <int KDIM, int NOUT, int TN>
__global__ void __launch_bounds__(256) gi_gemm_kernel(
    const float* __restrict__ A, const float* __restrict__ W,
    const float* __restrict__ bias, float* __restrict__ C)
{
    __shared__ __align__(16) float As[32][68];
    __shared__ float Ws[32][NOUT];
    const int tid  = threadIdx.x;
    const int bm   = blockIdx.x * 64;
    const int trow = (tid & 15) * 4;
    const int tcol = (tid >> 4) * TN;

    float acc[4][TN];
#pragma unroll
    for (int i = 0; i < 4; i++)
#pragma unroll
        for (int j = 0; j < TN; j++) acc[i][j] = 0.f;

    const int lr = tid >> 3;
    const int lc = (tid & 7) * 4;

    for (int k0 = 0; k0 < KDIM; k0 += 32) {
        float4 v0 = *(const float4*)(A + (size_t)(bm + lr) * KDIM + k0 + lc);
        float4 v1 = *(const float4*)(A + (size_t)(bm + lr + 32) * KDIM + k0 + lc);
        As[lc + 0][lr] = v0.x; As[lc + 1][lr] = v0.y;
        As[lc + 2][lr] = v0.z; As[lc + 3][lr] = v0.w;
        As[lc + 0][lr + 32] = v1.x; As[lc + 1][lr + 32] = v1.y;
        As[lc + 2][lr + 32] = v1.z; As[lc + 3][lr + 32] = v1.w;
        for (int i = tid; i < 32 * NOUT; i += 256)
            (&Ws[0][0])[i] = W[k0 * NOUT + i];
        __syncthreads();
#pragma unroll
        for (int k = 0; k < 32; k++) {
            const float4 a4 = *(const float4*)&As[k][trow];
            const float av[4] = {a4.x, a4.y, a4.z, a4.w};
#pragma unroll
            for (int j = 0; j < TN; j++) {
                const float w = Ws[k][tcol + j];
#pragma unroll
                for (int i = 0; i < 4; i++) acc[i][j] = fmaf(av[i], w, acc[i][j]);
            }
        }
        __syncthreads();
    }
#pragma unroll
    for (int j = 0; j < TN; j++) {
        const float b = bias[tcol + j];
#pragma unroll
        for (int i = 0; i < 4; i++)
            C[(size_t)(bm + trow + i) * NOUT + tcol + j] = acc[i][j] + b;
    }
}

// ---------------- fast GRU step: thread = (row, hidden unit) ----------------
__global__ void __launch_bounds__(512) gru_fast_kernel(
    const float* __restrict__ gi,     // [1024][96] or null
    const float* __restrict__ xprev,  // [1024][32] used when gi==null
    const float* __restrict__ wih,    // [96][32] raw, used when gi==null
    const float* __restrict__ bih,    // used when gi==null
    const float* __restrict__ whh,    // [96][32] raw
    const float* __restrict__ bhh,
    const float* __restrict__ h_in,   // [1024][32]
    float* __restrict__ h_out)        // [1024][32]
{
    __shared__ float whh_s[96][33];
    __shared__ float wih_s[96][33];
    __shared__ float hs[16][33];
    __shared__ float xsv[16][33];
    const int tid = threadIdx.x;
    const int r = tid >> 5, u = tid & 31;
    const int row = blockIdx.x * 16 + r;

    for (int i = tid; i < 96 * 32; i += 512) whh_s[i >> 5][i & 31] = whh[i];
    if (gi == nullptr)
        for (int i = tid; i < 96 * 32; i += 512) wih_s[i >> 5][i & 31] = wih[i];
    hs[r][u] = h_in[row * 32 + u];
    if (gi == nullptr) xsv[r][u] = xprev[row * 32 + u];
    __syncthreads();

    float gir, giz, gin;
    if (gi != nullptr) {
        gir = gi[row * 96 + u];
        giz = gi[row * 96 + 32 + u];
        gin = gi[row * 96 + 64 + u];
    } else {
        gir = bih[u]; giz = bih[32 + u]; gin = bih[64 + u];
#pragma unroll
        for (int d = 0; d < 32; d++) {
            float xv = xsv[r][d];
            gir = fmaf(xv, wih_s[u][d], gir);
            giz = fmaf(xv, wih_s[32 + u][d], giz);
            gin = fmaf(xv, wih_s[64 + u][d], gin);
        }
    }
    float ghr = bhh[u], ghz = bhh[32 + u], ghn = bhh[64 + u];
#pragma unroll
    for (int d = 0; d < 32; d++) {
        float hv = hs[r][d];
        ghr = fmaf(hv, whh_s[u][d], ghr);
        ghz = fmaf(hv, whh_s[32 + u][d], ghz);
        ghn = fmaf(hv, whh_s[64 + u][d], ghn);
    }
    float rr = 1.f / (1.f + expf(-(gir + ghr)));
    float zz = 1.f / (1.f + expf(-(giz + ghz)));
    float nn = tanhf(gin + rr * ghn);
    h_out[row * 32 + u] = (1.f - zz) * nn + zz * hs[r][u];
}

// ---------------- final head + hT pack ----------------
__global__ void final_kernel(const float* __restrict__ nn4W, const float* __restrict__ nn4b,
                             float* __restrict__ out, int out_size)
{
    const int idx = blockIdx.x * 256 + threadIdx.x;
    if (idx >= out_size) return;
    if (idx < 2048) {
        const int t  = idx >> 10;
        const int ch = (idx >> 5) & 31;
        const int b0 = (idx & 31) * 32;
        float acc = nn4b[0];
#pragma unroll
        for (int c = 0; c < 32; c++) {
            const float v = g_out1[t * 32768 + (b0 + c) * 32 + ch];
            acc = fmaf(fmaxf(v, 0.f), nn4W[c], acc);
        }
        out[idx] = fmaxf(acc, 0.f);
    } else if (idx < 2048 + 65536) {
        const int j = idx - 2048;
        out[idx] = (j < 32768) ? g_out0[32768 + j] : g_out1[32768 + (j - 32768)];
    }
}

// ---------------- launch ----------------
extern "C" void kernel_launch(void* const* d_in, const int* in_sizes, int n_in,
                              void* d_out, int out_size)
{
    const float* x    = (const float*)d_in[0];
    const float* h1   = (const float*)d_in[2];
    const float* W1   = (const float*)d_in[3];
    const float* b1   = (const float*)d_in[4];
    const float* W2   = (const float*)d_in[5];
    const float* b2   = (const float*)d_in[6];
    const float* nn1W = (const float*)d_in[7];
    const float* nn1b = (const float*)d_in[8];
    const float* nn2W = (const float*)d_in[9];
    const float* nn2b = (const float*)d_in[10];
    const float* nn4W = (const float*)d_in[11];
    const float* nn4b = (const float*)d_in[12];
    const float* wih0 = (const float*)d_in[13];
    const float* whh0 = (const float*)d_in[14];
    const float* bih0 = (const float*)d_in[15];
    const float* bhh0 = (const float*)d_in[16];
    const float* wih1 = (const float*)d_in[17];
    const float* whh1 = (const float*)d_in[18];
    const float* bih1 = (const float*)d_in[19];
    const float* bhh1 = (const float*)d_in[20];
    float* out = (float*)d_out;

    float *xin, *gi, *out0, *out1, *wih0T;
    cudaGetSymbolAddress((void**)&xin,   g_xin);
    cudaGetSymbolAddress((void**)&gi,    g_gi);
    cudaGetSymbolAddress((void**)&out0,  g_out0);
    cudaGetSymbolAddress((void**)&out1,  g_out1);
    cudaGetSymbolAddress((void**)&wih0T, g_wih0T);

    cudaFuncSetAttribute(mega_kernel, cudaFuncAttributeMaxDynamicSharedMemorySize, SMEM_TOT);

    prep_kernel<<<96, 256>>>(nn1W, nn1b, nn2W, W2, wih0);
    mega_kernel<<<NG, 512, SMEM_TOT>>>(x, W1, b1, b2, nn2b);
    permute_kernel<<<2048, 256>>>();
    // GI for both timesteps of GRU layer 0: [2048,256] @ [256,96] + bih0
    gi_gemm_kernel<256, 96, 6><<<32, 256>>>(xin, wih0T, bih0, gi);
    // GRU layer 0 (gi precomputed), then layer 1 (gi computed in-kernel, IN=32)
    gru_fast_kernel<<<64, 512>>>(gi,         nullptr,       nullptr, nullptr, whh0, bhh0, h1,         out0);
    gru_fast_kernel<<<64, 512>>>(gi + 98304, nullptr,       nullptr, nullptr, whh0, bhh0, out0,       out0 + 32768);
    gru_fast_kernel<<<64, 512>>>(nullptr,    out0,          wih1,    bih1,    whh1, bhh1, h1 + 32768, out1);
    gru_fast_kernel<<<64, 512>>>(nullptr,    out0 + 32768,  wih1,    bih1,    whh1, bhh1, out1,       out1 + 32768);
    final_kernel<<<(out_size + 255) / 256, 256>>>(nn4W, nn4b, out, out_size);
}

// round 6
// speedup vs baseline: 1.7751x; 1.2518x over previous
#include <cuda_runtime.h>
#include <math.h>
#include <stdint.h>

#define NG 2048
#define NP 128

// ---------------- scratch (device globals) ----------------
__device__ float g_gfeat[NG * 256];
__device__ float g_xin[2 * 1024 * 256];
__device__ float g_gi[2 * 1024 * 96];
__device__ float g_out0[2 * 1024 * 32];
__device__ float g_out1[2 * 1024 * 32];
__device__ float g_w2T[128 * 64];      // edge W2^T  [n][k] fp32
__device__ float g_nn1T2[96 * 256];    // folded nn1^T [n][k=256] fp32
__device__ float g_nn2T[64 * 96];      // nn2^T [n][k] fp32 (padded k)
__device__ float g_nn1bp[96];
__device__ float g_wih0T[256 * 96];    // [k][n] for GI gemm

// ---------------- helpers ----------------
__device__ __forceinline__ float cvt_tf32(float x) {
    float r; asm("cvt.rna.tf32.f32 %0, %1;" : "=f"(r) : "f"(x)); return r;
}
__device__ __forceinline__ void splitf(float x, uint32_t& h, uint32_t& l) {
    float hh = cvt_tf32(x);
    h = __float_as_uint(hh);
    l = __float_as_uint(cvt_tf32(x - hh));
}
__device__ __forceinline__ void mma8(float d[4], const uint32_t a[4], const uint32_t b[2]) {
    asm volatile(
        "mma.sync.aligned.m16n8k8.row.col.f32.tf32.tf32.f32 "
        "{%0,%1,%2,%3},{%4,%5,%6,%7},{%8,%9},{%0,%1,%2,%3};"
        : "+f"(d[0]), "+f"(d[1]), "+f"(d[2]), "+f"(d[3])
        : "r"(a[0]), "r"(a[1]), "r"(a[2]), "r"(a[3]), "r"(b[0]), "r"(b[1]));
}
__device__ __forceinline__ void mma3(float d[4], const uint32_t ah[4], const uint32_t al[4],
                                     const uint32_t bh[2], const uint32_t bl[2]) {
    mma8(d, ah, bh); mma8(d, ah, bl); mma8(d, al, bh);
}
__device__ __forceinline__ void ldA2(const float* S, int stride, int m0, int k0, int lid,
                                     uint32_t ah[4], uint32_t al[4]) {
    const float* p = S + (m0 + (lid >> 2)) * stride + k0 + (lid & 3);
    splitf(p[0], ah[0], al[0]);
    splitf(p[8 * stride], ah[1], al[1]);
    splitf(p[4], ah[2], al[2]);
    splitf(p[8 * stride + 4], ah[3], al[3]);
}
__device__ __forceinline__ void ldB2(const float* S, int stride, int n0, int k0, int lid,
                                     uint32_t bh[2], uint32_t bl[2]) {
    const float* p = S + (n0 + (lid >> 2)) * stride + k0 + (lid & 3);
    splitf(p[0], bh[0], bl[0]);
    splitf(p[4], bh[1], bl[1]);
}
__device__ __forceinline__ void ldBp(const float* Bh, const float* Bl, int stride, int n0, int k0,
                                     int lid, uint32_t bh[2], uint32_t bl[2]) {
    int off = (n0 + (lid >> 2)) * stride + k0 + (lid & 3);
    bh[0] = __float_as_uint(Bh[off]); bh[1] = __float_as_uint(Bh[off + 4]);
    bl[0] = __float_as_uint(Bl[off]); bl[1] = __float_as_uint(Bl[off + 4]);
}

// ---------------- weight prep ----------------
__global__ void prep_kernel(const float* __restrict__ nn1W, const float* __restrict__ nn1b,
                            const float* __restrict__ nn2W, const float* __restrict__ W2,
                            const float* __restrict__ wih0)
{
    int idx = blockIdx.x * 256 + threadIdx.x;   // 96 blocks -> 24576
    if (idx < 128 * 64) { int n = idx >> 6, k = idx & 63; g_w2T[idx] = W2[k * 128 + n]; }
    if (idx < 96 * 256) {
        int n = idx >> 8, k = idx & 255;
        float v = 0.f;
        if (n < 94) {
            if (k < 128) v = nn1W[k * 94 + n];
            else { int kk = k - 128; v = 0.25f * nn1W[(128 + kk) * 94 + n] + nn1W[(256 + kk) * 94 + n]; }
        }
        g_nn1T2[idx] = v;
    }
    if (idx < 64 * 96) { int n = idx / 96, k = idx % 96; g_nn2T[idx] = (k < 94) ? nn2W[k * 64 + n] : 0.f; }
    if (idx < 96) g_nn1bp[idx] = (idx < 94) ? nn1b[idx] : 0.f;
    if (idx < 96 * 256) { int gg = idx >> 8, d = idx & 255; g_wih0T[d * 96 + gg] = wih0[idx]; }
}

// ---------------- smem layout (bytes) ----------------
#define SM_XS    0        // 128*5*4
#define SM_NBR   2560     // 128*4*4
#define SM_W1BH  4608     // [64][20]
#define SM_W1BL  9728
#define SM_B1    14848
#define SM_B2    15104
#define SM_B1V   15616
#define SM_B2V   16000
#define SM_FEATS 16256    // [128][20]
#define SM_W2T   26496    // [128][68]
#define SM_STG   61312    // H [128][68] / B1 planes 2x[96][36] / h2 [128][68]
#define SM_HAGG  96128    // hagg [128][260] / later H2 [128][100] + B2 planes
#define SMEM_TOT 229248

// ---------------- mega kernel (256 threads; 4 rw x 2 nh warps, 2 M-tiles/warp) ----------------
__global__ void __launch_bounds__(256) mega_kernel(
    const float* __restrict__ x, const float* __restrict__ W1,
    const float* __restrict__ b1, const float* __restrict__ b2,
    const float* __restrict__ nn2b)
{
    extern __shared__ __align__(16) char smem[];
    float* xs    = (float*)(smem + SM_XS);
    int*   nbr   = (int*)(smem + SM_NBR);
    float* W1Bh  = (float*)(smem + SM_W1BH);
    float* W1Bl  = (float*)(smem + SM_W1BL);
    float* b1s   = (float*)(smem + SM_B1);
    float* b2s   = (float*)(smem + SM_B2);
    float* b1v   = (float*)(smem + SM_B1V);
    float* b2v   = (float*)(smem + SM_B2V);
    float* feats = (float*)(smem + SM_FEATS);
    float* W2T   = (float*)(smem + SM_W2T);
    float* stg   = (float*)(smem + SM_STG);
    float* hagg  = (float*)(smem + SM_HAGG);    // [128][260]
    float* H2    = (float*)(smem + SM_HAGG);    // later [128][100]
    float* B2h   = (float*)(smem + SM_HAGG + 51200);
    float* B2l   = (float*)(smem + SM_HAGG + 76800);

    const int tid = threadIdx.x, wid = tid >> 5, lid = tid & 31;
    const int rw = wid >> 1;          // 0..3, 32 rows each
    const int nh = wid & 1;           // col half
    const int qr = lid >> 2, qc = lid & 3;
    const int g = blockIdx.x;
    const size_t base = (size_t)g * NP;

    for (int i = tid; i < NP * 5; i += 256) xs[i] = x[base * 5 + i];
    for (int i = tid; i < 64 * 20; i += 256) {
        int n = i / 20, k = i % 20;
        float v = (k < 10) ? W1[k * 64 + n] : 0.f;
        uint32_t h, l; splitf(v, h, l);
        W1Bh[i] = __uint_as_float(h); W1Bl[i] = __uint_as_float(l);
    }
    if (tid < 64) b1s[tid] = b1[tid];
    if (tid >= 64 && tid < 192) b2s[tid - 64] = b2[tid - 64];
    if (tid >= 192 && tid < 256) b2v[tid - 192] = nn2b[tid - 192];
    for (int i = tid; i < 96; i += 256) b1v[i] = g_nn1bp[i];
    for (int i = tid; i < 2048; i += 256) {      // W2T -> [128][68] fp32
        int n = i >> 4, q = i & 15;
        *(float4*)&W2T[n * 68 + q * 4] = *(const float4*)&g_w2T[n * 64 + q * 4];
    }
    for (int i = tid; i < 128 * 20; i += 256) feats[i] = 0.f;
    __syncthreads();

    // ---- KNN (thread = node), branchless predicated insertion, stable ties
    if (tid < NP) {
        const float px = xs[tid * 5 + 0], py = xs[tid * 5 + 1], pz = xs[tid * 5 + 2];
        float d0 = 1e30f, d1 = 1e30f, d2v = 1e30f, d3 = 1e30f;
        int i0 = 0, i1 = 0, i2 = 0, i3 = 0;
#pragma unroll 4
        for (int j = 0; j < NP; j++) {
            float dx = xs[j * 5 + 0] - px, dy = xs[j * 5 + 1] - py, dz = xs[j * 5 + 2] - pz;
            float dd = dx * dx + dy * dy + dz * dz;
            dd = (j == tid) ? 1e30f : dd;
            bool c0 = dd < d0, c1 = dd < d1, c2 = dd < d2v, c3 = dd < d3;
            i3 = c2 ? i2 : (c3 ? j : i3);  d3  = c2 ? d2v : (c3 ? dd : d3);
            i2 = c1 ? i1 : (c2 ? j : i2);  d2v = c1 ? d1  : (c2 ? dd : d2v);
            i1 = c0 ? i0 : (c1 ? j : i1);  d1  = c0 ? d0  : (c1 ? dd : d1);
            i0 = c0 ? j : i0;              d0  = c0 ? dd  : d0;
        }
        nbr[tid * 4 + 0] = i0; nbr[tid * 4 + 1] = i1; nbr[tid * 4 + 2] = i2; nbr[tid * 4 + 3] = i3;
    }
    __syncthreads();

    // ================= EdgeConv in 4 passes of 128 edges =================
    // row permutation: fr in [0,128): rw'=fr>>5, r=fr&31 ->
    //   node = p*32 + rw'*8 + (r&7), k = ((r>>4)<<1) | ((r>>3)&1)
    for (int p = 0; p < 4; p++) {
        for (int i = tid; i < 128 * 10; i += 256) {
            int fr = i / 10, d = i % 10;
            int r = fr & 31;
            int node = p * 32 + (fr >> 5) * 8 + (r & 7);
            int k = ((r >> 4) << 1) | ((r >> 3) & 1);
            float v;
            if (d < 5) v = xs[node * 5 + d];
            else { int j = nbr[node * 4 + k]; v = xs[j * 5 + (d - 5)] - xs[node * 5 + (d - 5)]; }
            feats[fr * 20 + d] = v;
        }
        __syncthreads();

        // layer-1: warp (rw, nh): 2 M-tiles x 4 nt, K=16
        {
            float la[2][4][4];
#pragma unroll
            for (int rt = 0; rt < 2; rt++)
#pragma unroll
                for (int j = 0; j < 4; j++) { la[rt][j][0]=0.f; la[rt][j][1]=0.f; la[rt][j][2]=0.f; la[rt][j][3]=0.f; }
#pragma unroll
            for (int ks = 0; ks < 2; ks++) {
                uint32_t ah[2][4], al[2][4];
                ldA2(feats, 20, rw * 32,      ks * 8, lid, ah[0], al[0]);
                ldA2(feats, 20, rw * 32 + 16, ks * 8, lid, ah[1], al[1]);
#pragma unroll
                for (int j = 0; j < 4; j++) {
                    uint32_t bh[2], bl[2]; ldBp(W1Bh, W1Bl, 20, (nh * 4 + j) * 8, ks * 8, lid, bh, bl);
                    mma3(la[0][j], ah[0], al[0], bh, bl);
                    mma3(la[1][j], ah[1], al[1], bh, bl);
                }
            }
#pragma unroll
            for (int rt = 0; rt < 2; rt++) {
                int r0 = rw * 32 + rt * 16 + qr, r1 = r0 + 8;
#pragma unroll
                for (int j = 0; j < 4; j++) {
                    int col = (nh * 4 + j) * 8 + 2 * qc;
                    float2 u0 = { fmaxf(la[rt][j][0] + b1s[col], 0.f), fmaxf(la[rt][j][1] + b1s[col + 1], 0.f) };
                    float2 u1 = { fmaxf(la[rt][j][2] + b1s[col], 0.f), fmaxf(la[rt][j][3] + b1s[col + 1], 0.f) };
                    *(float2*)&stg[r0 * 68 + col] = u0;
                    *(float2*)&stg[r1 * 68 + col] = u1;
                }
            }
        }
        __syncthreads();

        // layer-2: warp (rw, nh): 2 M-tiles x 8 nt, K=64
        float acc[2][8][4];
#pragma unroll
        for (int rt = 0; rt < 2; rt++)
#pragma unroll
            for (int j = 0; j < 8; j++) { acc[rt][j][0]=0.f; acc[rt][j][1]=0.f; acc[rt][j][2]=0.f; acc[rt][j][3]=0.f; }
#pragma unroll
        for (int ks = 0; ks < 8; ks++) {
            uint32_t ah[2][4], al[2][4];
            ldA2(stg, 68, rw * 32,      ks * 8, lid, ah[0], al[0]);
            ldA2(stg, 68, rw * 32 + 16, ks * 8, lid, ah[1], al[1]);
#pragma unroll
            for (int j = 0; j < 8; j++) {
                uint32_t bh[2], bl[2]; ldB2(W2T, 68, (nh * 8 + j) * 8, ks * 8, lid, bh, bl);
                mma3(acc[0][j], ah[0], al[0], bh, bl);
                mma3(acc[1][j], ah[1], al[1], bh, bl);
            }
        }

        // epilogue: all 4 edges of node (p*32+rw*8+qr) live in this thread
        {
            const int node = p * 32 + rw * 8 + qr;
            float* hrow = hagg + (size_t)node * 260;
#pragma unroll
            for (int j = 0; j < 8; j++) {
                int col = (nh * 8 + j) * 8 + 2 * qc;
                float bcol = b2s[col], bcol1 = b2s[col + 1];
                float v00 = fmaxf(acc[0][j][0] + bcol, 0.f),  v01 = fmaxf(acc[0][j][1] + bcol1, 0.f);
                float v10 = fmaxf(acc[0][j][2] + bcol, 0.f),  v11 = fmaxf(acc[0][j][3] + bcol1, 0.f);
                float v20 = fmaxf(acc[1][j][0] + bcol, 0.f),  v21 = fmaxf(acc[1][j][1] + bcol1, 0.f);
                float v30 = fmaxf(acc[1][j][2] + bcol, 0.f),  v31 = fmaxf(acc[1][j][3] + bcol1, 0.f);
                float2 mx = { fmaxf(fmaxf(v00, v10), fmaxf(v20, v30)),
                              fmaxf(fmaxf(v01, v11), fmaxf(v21, v31)) };
                float2 sm = { (v00 + v10) + (v20 + v30), (v01 + v11) + (v21 + v31) };
                *(float2*)&hrow[col] = mx;
                *(float2*)&hrow[128 + col] = sm;
            }
        }
        __syncthreads();
    }

    // ================= nn1: [128][256] @ [256][96] =================
    float acc1[2][6][4];
#pragma unroll
    for (int rt = 0; rt < 2; rt++)
#pragma unroll
        for (int j = 0; j < 6; j++) { acc1[rt][j][0]=0.f; acc1[rt][j][1]=0.f; acc1[rt][j][2]=0.f; acc1[rt][j][3]=0.f; }
    float* B1h = stg;
    float* B1l = stg + 96 * 36;
    for (int kc = 0; kc < 8; kc++) {
        for (int i = tid; i < 768; i += 256) {
            int n = i >> 3, q = i & 7;
            float4 v = *(const float4*)&g_nn1T2[n * 256 + kc * 32 + q * 4];
            float4 vh, vl; uint32_t h, l;
            splitf(v.x, h, l); vh.x = __uint_as_float(h); vl.x = __uint_as_float(l);
            splitf(v.y, h, l); vh.y = __uint_as_float(h); vl.y = __uint_as_float(l);
            splitf(v.z, h, l); vh.z = __uint_as_float(h); vl.z = __uint_as_float(l);
            splitf(v.w, h, l); vh.w = __uint_as_float(h); vl.w = __uint_as_float(l);
            *(float4*)&B1h[n * 36 + q * 4] = vh;
            *(float4*)&B1l[n * 36 + q * 4] = vl;
        }
        __syncthreads();
#pragma unroll
        for (int ks = 0; ks < 4; ks++) {
            uint32_t ah[2][4], al[2][4];
            ldA2(hagg, 260, rw * 32,      kc * 32 + ks * 8, lid, ah[0], al[0]);
            ldA2(hagg, 260, rw * 32 + 16, kc * 32 + ks * 8, lid, ah[1], al[1]);
#pragma unroll
            for (int j = 0; j < 6; j++) {
                uint32_t bh[2], bl[2]; ldBp(B1h, B1l, 36, (nh * 6 + j) * 8, ks * 8, lid, bh, bl);
                mma3(acc1[0][j], ah[0], al[0], bh, bl);
                mma3(acc1[1][j], ah[1], al[1], bh, bl);
            }
        }
        __syncthreads();
    }
    // epilogue1: H2 [128][100] = relu(acc1 + b1v); stage B2 hi/lo planes
    {
#pragma unroll
        for (int rt = 0; rt < 2; rt++) {
            int r0 = rw * 32 + rt * 16 + qr, r1 = r0 + 8;
#pragma unroll
            for (int j = 0; j < 6; j++) {
                int col = (nh * 6 + j) * 8 + 2 * qc;
                float2 u0 = { fmaxf(acc1[rt][j][0] + b1v[col], 0.f), fmaxf(acc1[rt][j][1] + b1v[col + 1], 0.f) };
                float2 u1 = { fmaxf(acc1[rt][j][2] + b1v[col], 0.f), fmaxf(acc1[rt][j][3] + b1v[col + 1], 0.f) };
                *(float2*)&H2[r0 * 100 + col] = u0;
                *(float2*)&H2[r1 * 100 + col] = u1;
            }
        }
        for (int i = tid; i < 1536; i += 256) {
            int n = i / 24, q = i % 24;
            float4 v = *(const float4*)&g_nn2T[n * 96 + q * 4];
            float4 vh, vl; uint32_t h, l;
            splitf(v.x, h, l); vh.x = __uint_as_float(h); vl.x = __uint_as_float(l);
            splitf(v.y, h, l); vh.y = __uint_as_float(h); vl.y = __uint_as_float(l);
            splitf(v.z, h, l); vh.z = __uint_as_float(h); vl.z = __uint_as_float(l);
            splitf(v.w, h, l); vh.w = __uint_as_float(h); vl.w = __uint_as_float(l);
            *(float4*)&B2h[n * 100 + q * 4] = vh;
            *(float4*)&B2l[n * 100 + q * 4] = vl;
        }
    }
    __syncthreads();

    // ================= nn2: [128][96] @ [96][64] =================
    float acc2[2][4][4];
#pragma unroll
    for (int rt = 0; rt < 2; rt++)
#pragma unroll
        for (int j = 0; j < 4; j++) { acc2[rt][j][0]=0.f; acc2[rt][j][1]=0.f; acc2[rt][j][2]=0.f; acc2[rt][j][3]=0.f; }
#pragma unroll
    for (int ks = 0; ks < 12; ks++) {
        uint32_t ah[2][4], al[2][4];
        ldA2(H2, 100, rw * 32,      ks * 8, lid, ah[0], al[0]);
        ldA2(H2, 100, rw * 32 + 16, ks * 8, lid, ah[1], al[1]);
#pragma unroll
        for (int j = 0; j < 4; j++) {
            uint32_t bh[2], bl[2]; ldBp(B2h, B2l, 100, (nh * 4 + j) * 8, ks * 8, lid, bh, bl);
            mma3(acc2[0][j], ah[0], al[0], bh, bl);
            mma3(acc2[1][j], ah[1], al[1], bh, bl);
        }
    }
    __syncthreads();
    // h2 [128][68] fp32 into stg
    {
#pragma unroll
        for (int rt = 0; rt < 2; rt++) {
            int r0 = rw * 32 + rt * 16 + qr, r1 = r0 + 8;
#pragma unroll
            for (int j = 0; j < 4; j++) {
                int col = (nh * 4 + j) * 8 + 2 * qc;
                float2 u0 = { acc2[rt][j][0] + b2v[col], acc2[rt][j][1] + b2v[col + 1] };
                float2 u1 = { acc2[rt][j][2] + b2v[col], acc2[rt][j][3] + b2v[col + 1] };
                *(float2*)&stg[r0 * 68 + col] = u0;
                *(float2*)&stg[r1 * 68 + col] = u1;
            }
        }
    }
    __syncthreads();

    // ================= segment max/min/sum/mean + relu -> g_gfeat =================
    {
        int c = tid & 63, q = tid >> 6;     // q 0..3, 32 rows each
        float mx = -1e30f, mn = 1e30f, sm = 0.f;
        for (int r = q * 32; r < q * 32 + 32; r++) {
            float v = stg[r * 68 + c];
            mx = fmaxf(mx, v); mn = fminf(mn, v); sm += v;
        }
        feats[q * 192 + c] = mx; feats[q * 192 + 64 + c] = mn; feats[q * 192 + 128 + c] = sm;
        __syncthreads();
        if (tid < 64) {
            float MX = feats[c], MN = feats[64 + c], SM = feats[128 + c];
            for (int qq = 1; qq < 4; qq++) {
                MX = fmaxf(MX, feats[qq * 192 + c]);
                MN = fminf(MN, feats[qq * 192 + 64 + c]);
                SM += feats[qq * 192 + 128 + c];
            }
            float* o = g_gfeat + (size_t)g * 256;
            o[c]        = fmaxf(MX, 0.f);
            o[64 + c]   = fmaxf(MN, 0.f);
            o[128 + c]  = fmaxf(SM, 0.f);
            o[192 + c]  = fmaxf(SM * (1.f / 128.f), 0.f);
        }
    }
}

// ---------------- g.reshape(2,256,1024).transpose(0,2,1) ----------------
__global__ void permute_kernel()
{
    const int idx = blockIdx.x * 256 + threadIdx.x;
    const int i = idx & 255;
    const int b = (idx >> 8) & 1023;
    const int t = idx >> 18;
    g_xin[idx] = g_gfeat[(t * 1024 + i * 4 + (b >> 8)) * 256 + (b & 255)];
}

// ---------------- tiled GEMM: GI = xin @ wih0T + bih0, 32-row tiles ----------------
template <int KDIM, int NOUT, int TN>
__global__ void __launch_bounds__(256) gi_gemm_kernel(
    const float* __restrict__ A, const float* __restrict__ W,
    const float* __restrict__ bias, float* __restrict__ C)
{
    __shared__ __align__(16) float As[32][36];
    __shared__ float Ws[32][NOUT];
    const int tid  = threadIdx.x;
    const int bm   = blockIdx.x * 32;
    const int trow = (tid & 7) * 4;
    const int tcol = (tid >> 3) * TN;

    float acc[4][TN];
#pragma unroll
    for (int i = 0; i < 4; i++)
#pragma unroll
        for (int j = 0; j < TN; j++) acc[i][j] = 0.f;

    const int lr = tid >> 3;          // 0..31
    const int lc = (tid & 7) * 4;     // 0..28

    for (int k0 = 0; k0 < KDIM; k0 += 32) {
        float4 v0 = *(const float4*)(A + (size_t)(bm + lr) * KDIM + k0 + lc);
        As[lc + 0][lr] = v0.x; As[lc + 1][lr] = v0.y;
        As[lc + 2][lr] = v0.z; As[lc + 3][lr] = v0.w;
        for (int i = tid; i < 32 * NOUT; i += 256)
            (&Ws[0][0])[i] = W[k0 * NOUT + i];
        __syncthreads();
#pragma unroll
        for (int k = 0; k < 32; k++) {
            const float4 a4 = *(const float4*)&As[k][trow];
            const float av[4] = {a4.x, a4.y, a4.z, a4.w};
#pragma unroll
            for (int j = 0; j < TN; j++) {
                const float w = Ws[k][tcol + j];
#pragma unroll
                for (int i = 0; i < 4; i++) acc[i][j] = fmaf(av[i], w, acc[i][j]);
            }
        }
        __syncthreads();
    }
#pragma unroll
    for (int j = 0; j < TN; j++) {
        const float b = bias[tcol + j];
#pragma unroll
        for (int i = 0; i < 4; i++)
            C[(size_t)(bm + trow + i) * NOUT + tcol + j] = acc[i][j] + b;
    }
}

// ---------------- fast GRU step: thread = (row, hidden unit) ----------------
__global__ void __launch_bounds__(512) gru_fast_kernel(
    const float* __restrict__ gi,
    const float* __restrict__ xprev,
    const float* __restrict__ wih,
    const float* __restrict__ bih,
    const float* __restrict__ whh,
    const float* __restrict__ bhh,
    const float* __restrict__ h_in,
    float* __restrict__ h_out)
{
    __shared__ float whh_s[96][33];
    __shared__ float wih_s[96][33];
    __shared__ float hs[16][33];
    __shared__ float xsv[16][33];
    const int tid = threadIdx.x;
    const int r = tid >> 5, u = tid & 31;
    const int row = blockIdx.x * 16 + r;

    for (int i = tid; i < 96 * 32; i += 512) whh_s[i >> 5][i & 31] = whh[i];
    if (gi == nullptr)
        for (int i = tid; i < 96 * 32; i += 512) wih_s[i >> 5][i & 31] = wih[i];
    hs[r][u] = h_in[row * 32 + u];
    if (gi == nullptr) xsv[r][u] = xprev[row * 32 + u];
    __syncthreads();

    float gir, giz, gin;
    if (gi != nullptr) {
        gir = gi[row * 96 + u];
        giz = gi[row * 96 + 32 + u];
        gin = gi[row * 96 + 64 + u];
    } else {
        gir = bih[u]; giz = bih[32 + u]; gin = bih[64 + u];
#pragma unroll
        for (int d = 0; d < 32; d++) {
            float xv = xsv[r][d];
            gir = fmaf(xv, wih_s[u][d], gir);
            giz = fmaf(xv, wih_s[32 + u][d], giz);
            gin = fmaf(xv, wih_s[64 + u][d], gin);
        }
    }
    float ghr = bhh[u], ghz = bhh[32 + u], ghn = bhh[64 + u];
#pragma unroll
    for (int d = 0; d < 32; d++) {
        float hv = hs[r][d];
        ghr = fmaf(hv, whh_s[u][d], ghr);
        ghz = fmaf(hv, whh_s[32 + u][d], ghz);
        ghn = fmaf(hv, whh_s[64 + u][d], ghn);
    }
    float rr = 1.f / (1.f + expf(-(gir + ghr)));
    float zz = 1.f / (1.f + expf(-(giz + ghz)));
    float nn = tanhf(gin + rr * ghn);
    h_out[row * 32 + u] = (1.f - zz) * nn + zz * hs[r][u];
}

// ---------------- final head + hT pack ----------------
__global__ void final_kernel(const float* __restrict__ nn4W, const float* __restrict__ nn4b,
                             float* __restrict__ out, int out_size)
{
    const int idx = blockIdx.x * 256 + threadIdx.x;
    if (idx >= out_size) return;
    if (idx < 2048) {
        const int t  = idx >> 10;
        const int ch = (idx >> 5) & 31;
        const int b0 = (idx & 31) * 32;
        float acc = nn4b[0];
#pragma unroll
        for (int c = 0; c < 32; c++) {
            const float v = g_out1[t * 32768 + (b0 + c) * 32 + ch];
            acc = fmaf(fmaxf(v, 0.f), nn4W[c], acc);
        }
        out[idx] = fmaxf(acc, 0.f);
    } else if (idx < 2048 + 65536) {
        const int j = idx - 2048;
        out[idx] = (j < 32768) ? g_out0[32768 + j] : g_out1[32768 + (j - 32768)];
    }
}

// ---------------- launch ----------------
extern "C" void kernel_launch(void* const* d_in, const int* in_sizes, int n_in,
                              void* d_out, int out_size)
{
    const float* x    = (const float*)d_in[0];
    const float* h1   = (const float*)d_in[2];
    const float* W1   = (const float*)d_in[3];
    const float* b1   = (const float*)d_in[4];
    const float* W2   = (const float*)d_in[5];
    const float* b2   = (const float*)d_in[6];
    const float* nn1W = (const float*)d_in[7];
    const float* nn1b = (const float*)d_in[8];
    const float* nn2W = (const float*)d_in[9];
    const float* nn2b = (const float*)d_in[10];
    const float* nn4W = (const float*)d_in[11];
    const float* nn4b = (const float*)d_in[12];
    const float* wih0 = (const float*)d_in[13];
    const float* whh0 = (const float*)d_in[14];
    const float* bih0 = (const float*)d_in[15];
    const float* bhh0 = (const float*)d_in[16];
    const float* wih1 = (const float*)d_in[17];
    const float* whh1 = (const float*)d_in[18];
    const float* bih1 = (const float*)d_in[19];
    const float* bhh1 = (const float*)d_in[20];
    float* out = (float*)d_out;

    float *xin, *gi, *out0, *out1, *wih0T;
    cudaGetSymbolAddress((void**)&xin,   g_xin);
    cudaGetSymbolAddress((void**)&gi,    g_gi);
    cudaGetSymbolAddress((void**)&out0,  g_out0);
    cudaGetSymbolAddress((void**)&out1,  g_out1);
    cudaGetSymbolAddress((void**)&wih0T, g_wih0T);

    cudaFuncSetAttribute(mega_kernel, cudaFuncAttributeMaxDynamicSharedMemorySize, SMEM_TOT);

    prep_kernel<<<96, 256>>>(nn1W, nn1b, nn2W, W2, wih0);
    mega_kernel<<<NG, 256, SMEM_TOT>>>(x, W1, b1, b2, nn2b);
    permute_kernel<<<2048, 256>>>();
    gi_gemm_kernel<256, 96, 3><<<64, 256>>>(xin, wih0T, bih0, gi);
    gru_fast_kernel<<<64, 512>>>(gi,         nullptr,       nullptr, nullptr, whh0, bhh0, h1,         out0);
    gru_fast_kernel<<<64, 512>>>(gi + 98304, nullptr,       nullptr, nullptr, whh0, bhh0, out0,       out0 + 32768);
    gru_fast_kernel<<<64, 512>>>(nullptr,    out0,          wih1,    bih1,    whh1, bhh1, h1 + 32768, out1);
    gru_fast_kernel<<<64, 512>>>(nullptr,    out0 + 32768,  wih1,    bih1,    whh1, bhh1, out1,       out1 + 32768);
    final_kernel<<<(out_size + 255) / 256, 256>>>(nn4W, nn4b, out, out_size);
}

// round 8
// speedup vs baseline: 1.9125x; 1.0774x over previous
#include <cuda_runtime.h>
#include <math.h>
#include <stdint.h>

#define NG 2048
#define NP 128

// ---------------- scratch (device globals) ----------------
__device__ float g_hagg[(size_t)NG * NP * 256];   // [N][256]: max | sum(folded mean)
__device__ float g_gfeat[NG * 256];
__device__ float g_gi[2 * 1024 * 96];
__device__ float g_out0[2 * 1024 * 32];
__device__ float g_out1[2 * 1024 * 32];
__device__ float g_w2T[128 * 64];      // edge W2^T  [n][k] fp32
__device__ float g_nn1T2[96 * 256];    // folded nn1^T [n][k=256] fp32
__device__ float g_nn2T[64 * 96];      // nn2^T [n][k] fp32 (padded k)
__device__ float g_nn1bp[96];
__device__ float g_wih0T[256 * 96];    // [k][n] for GI gemm

// ---------------- helpers ----------------
__device__ __forceinline__ float cvt_tf32(float x) {
    float r; asm("cvt.rna.tf32.f32 %0, %1;" : "=f"(r) : "f"(x)); return r;
}
__device__ __forceinline__ void splitf(float x, uint32_t& h, uint32_t& l) {
    float hh = cvt_tf32(x);
    h = __float_as_uint(hh);
    l = __float_as_uint(cvt_tf32(x - hh));
}
__device__ __forceinline__ void mma8(float d[4], const uint32_t a[4], const uint32_t b[2]) {
    asm volatile(
        "mma.sync.aligned.m16n8k8.row.col.f32.tf32.tf32.f32 "
        "{%0,%1,%2,%3},{%4,%5,%6,%7},{%8,%9},{%0,%1,%2,%3};"
        : "+f"(d[0]), "+f"(d[1]), "+f"(d[2]), "+f"(d[3])
        : "r"(a[0]), "r"(a[1]), "r"(a[2]), "r"(a[3]), "r"(b[0]), "r"(b[1]));
}
__device__ __forceinline__ void mma3(float d[4], const uint32_t ah[4], const uint32_t al[4],
                                     const uint32_t bh[2], const uint32_t bl[2]) {
    mma8(d, ah, bh); mma8(d, ah, bl); mma8(d, al, bh);
}
// A frag (smem or gmem), split in regs. [m][k] row-major, stride floats.
__device__ __forceinline__ void ldA2(const float* S, int stride, int m0, int k0, int lid,
                                     uint32_t ah[4], uint32_t al[4]) {
    const float* p = S + (m0 + (lid >> 2)) * stride + k0 + (lid & 3);
    splitf(p[0], ah[0], al[0]);
    splitf(p[8 * stride], ah[1], al[1]);
    splitf(p[4], ah[2], al[2]);
    splitf(p[8 * stride + 4], ah[3], al[3]);
}
__device__ __forceinline__ void ldB2(const float* S, int stride, int n0, int k0, int lid,
                                     uint32_t bh[2], uint32_t bl[2]) {
    const float* p = S + (n0 + (lid >> 2)) * stride + k0 + (lid & 3);
    splitf(p[0], bh[0], bl[0]);
    splitf(p[4], bh[1], bl[1]);
}
__device__ __forceinline__ void ldBp(const float* Bh, const float* Bl, int stride, int n0, int k0,
                                     int lid, uint32_t bh[2], uint32_t bl[2]) {
    int off = (n0 + (lid >> 2)) * stride + k0 + (lid & 3);
    bh[0] = __float_as_uint(Bh[off]); bh[1] = __float_as_uint(Bh[off + 4]);
    bl[0] = __float_as_uint(Bl[off]); bl[1] = __float_as_uint(Bl[off + 4]);
}

// ---------------- weight prep ----------------
__global__ void prep_kernel(const float* __restrict__ nn1W, const float* __restrict__ nn1b,
                            const float* __restrict__ nn2W, const float* __restrict__ W2,
                            const float* __restrict__ wih0)
{
    int idx = blockIdx.x * 256 + threadIdx.x;
    if (idx < 128 * 64) { int n = idx >> 6, k = idx & 63; g_w2T[idx] = W2[k * 128 + n]; }
    if (idx < 96 * 256) {
        int n = idx >> 8, k = idx & 255;
        float v = 0.f;
        if (n < 94) {
            if (k < 128) v = nn1W[k * 94 + n];
            else { int kk = k - 128; v = 0.25f * nn1W[(128 + kk) * 94 + n] + nn1W[(256 + kk) * 94 + n]; }
        }
        g_nn1T2[idx] = v;
    }
    if (idx < 64 * 96) { int n = idx / 96, k = idx % 96; g_nn2T[idx] = (k < 94) ? nn2W[k * 64 + n] : 0.f; }
    if (idx < 96) g_nn1bp[idx] = (idx < 94) ? nn1b[idx] : 0.f;
    if (idx < 96 * 256) { int gg = idx >> 8, d = idx & 255; g_wih0T[d * 96 + gg] = wih0[idx]; }
}

// ================= EC kernel: KNN + EdgeConv + edge agg -> g_hagg =================
#define EC_XS    0        // 128*5*4  = 2560
#define EC_NBR   2560     // 2048
#define EC_W1BH  4608     // [64][20] = 5120
#define EC_W1BL  9728     // 5120
#define EC_B1    14848    // 256
#define EC_B2    15104    // 512
#define EC_FEATS 15616    // [128][20] = 10240
#define EC_W2T   25856    // [128][68] = 34816
#define EC_STG   60672    // H [128][68] = 34816
#define EC_SMEM  95488

__global__ void __launch_bounds__(256, 2) ec_kernel(
    const float* __restrict__ x, const float* __restrict__ W1,
    const float* __restrict__ b1, const float* __restrict__ b2)
{
    extern __shared__ __align__(16) char smem[];
    float* xs    = (float*)(smem + EC_XS);
    int*   nbr   = (int*)(smem + EC_NBR);
    float* W1Bh  = (float*)(smem + EC_W1BH);
    float* W1Bl  = (float*)(smem + EC_W1BL);
    float* b1s   = (float*)(smem + EC_B1);
    float* b2s   = (float*)(smem + EC_B2);
    float* feats = (float*)(smem + EC_FEATS);
    float* W2T   = (float*)(smem + EC_W2T);
    float* stg   = (float*)(smem + EC_STG);

    const int tid = threadIdx.x, wid = tid >> 5, lid = tid & 31;
    const int rw = wid >> 1, nh = wid & 1;
    const int qr = lid >> 2, qc = lid & 3;
    const int g = blockIdx.x;
    const size_t base = (size_t)g * NP;

    for (int i = tid; i < NP * 5; i += 256) xs[i] = x[base * 5 + i];
    for (int i = tid; i < 64 * 20; i += 256) {
        int n = i / 20, k = i % 20;
        float v = (k < 10) ? W1[k * 64 + n] : 0.f;
        uint32_t h, l; splitf(v, h, l);
        W1Bh[i] = __uint_as_float(h); W1Bl[i] = __uint_as_float(l);
    }
    if (tid < 64) b1s[tid] = b1[tid];
    if (tid >= 64 && tid < 192) b2s[tid - 64] = b2[tid - 64];
    for (int i = tid; i < 2048; i += 256) {
        int n = i >> 4, q = i & 15;
        *(float4*)&W2T[n * 68 + q * 4] = *(const float4*)&g_w2T[n * 64 + q * 4];
    }
    for (int i = tid; i < 128 * 20; i += 256) feats[i] = 0.f;
    __syncthreads();

    // ---- KNN (thread = node), branchless predicated insertion, stable ties
    if (tid < NP) {
        const float px = xs[tid * 5 + 0], py = xs[tid * 5 + 1], pz = xs[tid * 5 + 2];
        float d0 = 1e30f, d1 = 1e30f, d2v = 1e30f, d3 = 1e30f;
        int i0 = 0, i1 = 0, i2 = 0, i3 = 0;
#pragma unroll 4
        for (int j = 0; j < NP; j++) {
            float dx = xs[j * 5 + 0] - px, dy = xs[j * 5 + 1] - py, dz = xs[j * 5 + 2] - pz;
            float dd = dx * dx + dy * dy + dz * dz;
            dd = (j == tid) ? 1e30f : dd;
            bool c0 = dd < d0, c1 = dd < d1, c2 = dd < d2v, c3 = dd < d3;
            i3 = c2 ? i2 : (c3 ? j : i3);  d3  = c2 ? d2v : (c3 ? dd : d3);
            i2 = c1 ? i1 : (c2 ? j : i2);  d2v = c1 ? d1  : (c2 ? dd : d2v);
            i1 = c0 ? i0 : (c1 ? j : i1);  d1  = c0 ? d0  : (c1 ? dd : d1);
            i0 = c0 ? j : i0;              d0  = c0 ? dd  : d0;
        }
        nbr[tid * 4 + 0] = i0; nbr[tid * 4 + 1] = i1; nbr[tid * 4 + 2] = i2; nbr[tid * 4 + 3] = i3;
    }
    __syncthreads();

    // 4 passes of 128 edges; row perm: node = p*32 + (fr>>5)*8 + (r&7), k = ((r>>4)<<1)|((r>>3)&1)
    for (int p = 0; p < 4; p++) {
        for (int i = tid; i < 128 * 10; i += 256) {
            int fr = i / 10, d = i % 10;
            int r = fr & 31;
            int node = p * 32 + (fr >> 5) * 8 + (r & 7);
            int k = ((r >> 4) << 1) | ((r >> 3) & 1);
            float v;
            if (d < 5) v = xs[node * 5 + d];
            else { int j = nbr[node * 4 + k]; v = xs[j * 5 + (d - 5)] - xs[node * 5 + (d - 5)]; }
            feats[fr * 20 + d] = v;
        }
        __syncthreads();

        // layer-1: 2 M-tiles x 4 nt, K=16
        {
            float la[2][4][4];
#pragma unroll
            for (int rt = 0; rt < 2; rt++)
#pragma unroll
                for (int j = 0; j < 4; j++) { la[rt][j][0]=0.f; la[rt][j][1]=0.f; la[rt][j][2]=0.f; la[rt][j][3]=0.f; }
#pragma unroll
            for (int ks = 0; ks < 2; ks++) {
                uint32_t ah[2][4], al[2][4];
                ldA2(feats, 20, rw * 32,      ks * 8, lid, ah[0], al[0]);
                ldA2(feats, 20, rw * 32 + 16, ks * 8, lid, ah[1], al[1]);
#pragma unroll
                for (int j = 0; j < 4; j++) {
                    uint32_t bh[2], bl[2]; ldBp(W1Bh, W1Bl, 20, (nh * 4 + j) * 8, ks * 8, lid, bh, bl);
                    mma3(la[0][j], ah[0], al[0], bh, bl);
                    mma3(la[1][j], ah[1], al[1], bh, bl);
                }
            }
#pragma unroll
            for (int rt = 0; rt < 2; rt++) {
                int r0 = rw * 32 + rt * 16 + qr, r1 = r0 + 8;
#pragma unroll
                for (int j = 0; j < 4; j++) {
                    int col = (nh * 4 + j) * 8 + 2 * qc;
                    float2 u0 = { fmaxf(la[rt][j][0] + b1s[col], 0.f), fmaxf(la[rt][j][1] + b1s[col + 1], 0.f) };
                    float2 u1 = { fmaxf(la[rt][j][2] + b1s[col], 0.f), fmaxf(la[rt][j][3] + b1s[col + 1], 0.f) };
                    *(float2*)&stg[r0 * 68 + col] = u0;
                    *(float2*)&stg[r1 * 68 + col] = u1;
                }
            }
        }
        __syncthreads();

        // layer-2: 2 M-tiles x 8 nt, K=64
        float acc[2][8][4];
#pragma unroll
        for (int rt = 0; rt < 2; rt++)
#pragma unroll
            for (int j = 0; j < 8; j++) { acc[rt][j][0]=0.f; acc[rt][j][1]=0.f; acc[rt][j][2]=0.f; acc[rt][j][3]=0.f; }
#pragma unroll
        for (int ks = 0; ks < 8; ks++) {
            uint32_t ah[2][4], al[2][4];
            ldA2(stg, 68, rw * 32,      ks * 8, lid, ah[0], al[0]);
            ldA2(stg, 68, rw * 32 + 16, ks * 8, lid, ah[1], al[1]);
#pragma unroll
            for (int j = 0; j < 8; j++) {
                uint32_t bh[2], bl[2]; ldB2(W2T, 68, (nh * 8 + j) * 8, ks * 8, lid, bh, bl);
                mma3(acc[0][j], ah[0], al[0], bh, bl);
                mma3(acc[1][j], ah[1], al[1], bh, bl);
            }
        }

        // epilogue: all 4 edges of node (p*32+rw*8+qr) in this thread -> gmem hagg
        {
            const int node = p * 32 + rw * 8 + qr;
            float* hrow = g_hagg + (base + node) * 256;
#pragma unroll
            for (int j = 0; j < 8; j++) {
                int col = (nh * 8 + j) * 8 + 2 * qc;
                float bcol = b2s[col], bcol1 = b2s[col + 1];
                float v00 = fmaxf(acc[0][j][0] + bcol, 0.f),  v01 = fmaxf(acc[0][j][1] + bcol1, 0.f);
                float v10 = fmaxf(acc[0][j][2] + bcol, 0.f),  v11 = fmaxf(acc[0][j][3] + bcol1, 0.f);
                float v20 = fmaxf(acc[1][j][0] + bcol, 0.f),  v21 = fmaxf(acc[1][j][1] + bcol1, 0.f);
                float v30 = fmaxf(acc[1][j][2] + bcol, 0.f),  v31 = fmaxf(acc[1][j][3] + bcol1, 0.f);
                float2 mx = { fmaxf(fmaxf(v00, v10), fmaxf(v20, v30)),
                              fmaxf(fmaxf(v01, v11), fmaxf(v21, v31)) };
                float2 sm = { (v00 + v10) + (v20 + v30), (v01 + v11) + (v21 + v31) };
                *(float2*)&hrow[col] = mx;
                *(float2*)&hrow[128 + col] = sm;
            }
        }
        __syncthreads();
    }
}

// ================= NN kernel: nn1 + nn2 + segreduce (block = graph) =================
#define NN_B1H  0         // [96][36] = 13824
#define NN_B1L  13824     // 13824  (B2 fp32 [64][100]=25600 overlays B1H..)
#define NN_H2   27648     // [128][100] = 51200
#define NN_RED  78848     // 4*192*4 = 3072
#define NN_B1V  81920     // 384
#define NN_B2V  82304     // 256
#define NN_SMEM 82560

__global__ void __launch_bounds__(256, 2) nn_kernel(const float* __restrict__ nn2b)
{
    extern __shared__ __align__(16) char smem[];
    float* B1h = (float*)(smem + NN_B1H);
    float* B1l = (float*)(smem + NN_B1L);
    float* B2  = (float*)(smem + NN_B1H);     // overlay after nn1
    float* H2  = (float*)(smem + NN_H2);
    float* red = (float*)(smem + NN_RED);
    float* b1v = (float*)(smem + NN_B1V);
    float* b2v = (float*)(smem + NN_B2V);

    const int tid = threadIdx.x, wid = tid >> 5, lid = tid & 31;
    const int rw = wid >> 1, nh = wid & 1;
    const int qr = lid >> 2, qc = lid & 3;
    const int g = blockIdx.x;
    const float* A = g_hagg + (size_t)g * NP * 256;

    if (tid < 96) b1v[tid] = g_nn1bp[tid];
    if (tid >= 96 && tid < 160) b2v[tid - 96] = nn2b[tid - 96];

    // ---- nn1: [128][256] @ [256][96], A direct from gmem
    float acc1[2][6][4];
#pragma unroll
    for (int rt = 0; rt < 2; rt++)
#pragma unroll
        for (int j = 0; j < 6; j++) { acc1[rt][j][0]=0.f; acc1[rt][j][1]=0.f; acc1[rt][j][2]=0.f; acc1[rt][j][3]=0.f; }
    for (int kc = 0; kc < 8; kc++) {
        for (int i = tid; i < 768; i += 256) {
            int n = i >> 3, q = i & 7;
            float4 v = *(const float4*)&g_nn1T2[n * 256 + kc * 32 + q * 4];
            float4 vh, vl; uint32_t h, l;
            splitf(v.x, h, l); vh.x = __uint_as_float(h); vl.x = __uint_as_float(l);
            splitf(v.y, h, l); vh.y = __uint_as_float(h); vl.y = __uint_as_float(l);
            splitf(v.z, h, l); vh.z = __uint_as_float(h); vl.z = __uint_as_float(l);
            splitf(v.w, h, l); vh.w = __uint_as_float(h); vl.w = __uint_as_float(l);
            *(float4*)&B1h[n * 36 + q * 4] = vh;
            *(float4*)&B1l[n * 36 + q * 4] = vl;
        }
        __syncthreads();
#pragma unroll
        for (int ks = 0; ks < 4; ks++) {
            uint32_t ah[2][4], al[2][4];
            ldA2(A, 256, rw * 32,      kc * 32 + ks * 8, lid, ah[0], al[0]);
            ldA2(A, 256, rw * 32 + 16, kc * 32 + ks * 8, lid, ah[1], al[1]);
#pragma unroll
            for (int j = 0; j < 6; j++) {
                uint32_t bh[2], bl[2]; ldBp(B1h, B1l, 36, (nh * 6 + j) * 8, ks * 8, lid, bh, bl);
                mma3(acc1[0][j], ah[0], al[0], bh, bl);
                mma3(acc1[1][j], ah[1], al[1], bh, bl);
            }
        }
        __syncthreads();
    }
    // epilogue1: H2 = relu(acc1 + b1v); stage B2 fp32 (overlay)
    {
#pragma unroll
        for (int rt = 0; rt < 2; rt++) {
            int r0 = rw * 32 + rt * 16 + qr, r1 = r0 + 8;
#pragma unroll
            for (int j = 0; j < 6; j++) {
                int col = (nh * 6 + j) * 8 + 2 * qc;
                float2 u0 = { fmaxf(acc1[rt][j][0] + b1v[col], 0.f), fmaxf(acc1[rt][j][1] + b1v[col + 1], 0.f) };
                float2 u1 = { fmaxf(acc1[rt][j][2] + b1v[col], 0.f), fmaxf(acc1[rt][j][3] + b1v[col + 1], 0.f) };
                *(float2*)&H2[r0 * 100 + col] = u0;
                *(float2*)&H2[r1 * 100 + col] = u1;
            }
        }
        for (int i = tid; i < 1536; i += 256) {
            int n = i / 24, q = i % 24;
            *(float4*)&B2[n * 100 + q * 4] = *(const float4*)&g_nn2T[n * 96 + q * 4];
        }
    }
    __syncthreads();

    // ---- nn2: [128][96] @ [96][64]
    float acc2[2][4][4];
#pragma unroll
    for (int rt = 0; rt < 2; rt++)
#pragma unroll
        for (int j = 0; j < 4; j++) { acc2[rt][j][0]=0.f; acc2[rt][j][1]=0.f; acc2[rt][j][2]=0.f; acc2[rt][j][3]=0.f; }
#pragma unroll
    for (int ks = 0; ks < 12; ks++) {
        uint32_t ah[2][4], al[2][4];
        ldA2(H2, 100, rw * 32,      ks * 8, lid, ah[0], al[0]);
        ldA2(H2, 100, rw * 32 + 16, ks * 8, lid, ah[1], al[1]);
#pragma unroll
        for (int j = 0; j < 4; j++) {
            uint32_t bh[2], bl[2]; ldB2(B2, 100, (nh * 4 + j) * 8, ks * 8, lid, bh, bl);
            mma3(acc2[0][j], ah[0], al[0], bh, bl);
            mma3(acc2[1][j], ah[1], al[1], bh, bl);
        }
    }
    __syncthreads();    // all warps done reading H2 before overwrite
    // h2 (+bias, no relu) into H2 region, cols 0..63
    {
#pragma unroll
        for (int rt = 0; rt < 2; rt++) {
            int r0 = rw * 32 + rt * 16 + qr, r1 = r0 + 8;
#pragma unroll
            for (int j = 0; j < 4; j++) {
                int col = (nh * 4 + j) * 8 + 2 * qc;
                float2 u0 = { acc2[rt][j][0] + b2v[col], acc2[rt][j][1] + b2v[col + 1] };
                float2 u1 = { acc2[rt][j][2] + b2v[col], acc2[rt][j][3] + b2v[col + 1] };
                *(float2*)&H2[r0 * 100 + col] = u0;
                *(float2*)&H2[r1 * 100 + col] = u1;
            }
        }
    }
    __syncthreads();

    // ---- segment max/min/sum/mean + relu -> g_gfeat
    {
        int c = tid & 63, q = tid >> 6;
        float mx = -1e30f, mn = 1e30f, sm = 0.f;
        for (int r = q * 32; r < q * 32 + 32; r++) {
            float v = H2[r * 100 + c];
            mx = fmaxf(mx, v); mn = fminf(mn, v); sm += v;
        }
        red[q * 192 + c] = mx; red[q * 192 + 64 + c] = mn; red[q * 192 + 128 + c] = sm;
        __syncthreads();
        if (tid < 64) {
            float MX = red[c], MN = red[64 + c], SM = red[128 + c];
            for (int qq = 1; qq < 4; qq++) {
                MX = fmaxf(MX, red[qq * 192 + c]);
                MN = fminf(MN, red[qq * 192 + 64 + c]);
                SM += red[qq * 192 + 128 + c];
            }
            float* o = g_gfeat + (size_t)g * 256;
            o[c]        = fmaxf(MX, 0.f);
            o[64 + c]   = fmaxf(MN, 0.f);
            o[128 + c]  = fmaxf(SM, 0.f);
            o[192 + c]  = fmaxf(SM * (1.f / 128.f), 0.f);
        }
    }
}

// ---------------- GI = permute(gfeat) @ wih0T + bih0 (permute fused into A-load) ----------------
__global__ void __launch_bounds__(256) gi_gemm_kernel(
    const float* __restrict__ W, const float* __restrict__ bias, float* __restrict__ C)
{
    __shared__ __align__(16) float As[32][36];
    __shared__ float Ws[32][96];
    const int tid  = threadIdx.x;
    const int bm   = blockIdx.x * 32;
    const int trow = (tid & 7) * 4;
    const int tcol = (tid >> 3) * 3;

    float acc[4][3];
#pragma unroll
    for (int i = 0; i < 4; i++)
#pragma unroll
        for (int j = 0; j < 3; j++) acc[i][j] = 0.f;

    const int lr = tid >> 3;          // 0..31
    const int lc = (tid & 7) * 4;     // 0..28

    const int rg = bm + lr;
    const int t = rg >> 10, b = rg & 1023;
    const float* gf = g_gfeat + (size_t)(t * 1024 + (b >> 8)) * 256 + (b & 255);
    // element k of this row: gf[k * 1024]

    for (int k0 = 0; k0 < 256; k0 += 32) {
        As[lc + 0][lr] = gf[(size_t)(k0 + lc + 0) << 10];
        As[lc + 1][lr] = gf[(size_t)(k0 + lc + 1) << 10];
        As[lc + 2][lr] = gf[(size_t)(k0 + lc + 2) << 10];
        As[lc + 3][lr] = gf[(size_t)(k0 + lc + 3) << 10];
        for (int i = tid; i < 32 * 96; i += 256)
            (&Ws[0][0])[i] = W[k0 * 96 + i];
        __syncthreads();
#pragma unroll
        for (int k = 0; k < 32; k++) {
            const float4 a4 = *(const float4*)&As[k][trow];
            const float av[4] = {a4.x, a4.y, a4.z, a4.w};
#pragma unroll
            for (int j = 0; j < 3; j++) {
                const float w = Ws[k][tcol + j];
#pragma unroll
                for (int i = 0; i < 4; i++) acc[i][j] = fmaf(av[i], w, acc[i][j]);
            }
        }
        __syncthreads();
    }
#pragma unroll
    for (int j = 0; j < 3; j++) {
        const float b2 = bias[tcol + j];
#pragma unroll
        for (int i = 0; i < 4; i++)
            C[(size_t)(bm + trow + i) * 96 + tcol + j] = acc[i][j] + b2;
    }
}

// ---------------- fast GRU step ----------------
__global__ void __launch_bounds__(512) gru_fast_kernel(
    const float* __restrict__ gi,
    const float* __restrict__ xprev,
    const float* __restrict__ wih,
    const float* __restrict__ bih,
    const float* __restrict__ whh,
    const float* __restrict__ bhh,
    const float* __restrict__ h_in,
    float* __restrict__ h_out)
{
    __shared__ float whh_s[96][33];
    __shared__ float wih_s[96][33];
    __shared__ float hs[16][33];
    __shared__ float xsv[16][33];
    const int tid = threadIdx.x;
    const int r = tid >> 5, u = tid & 31;
    const int row = blockIdx.x * 16 + r;

    for (int i = tid; i < 96 * 32; i += 512) whh_s[i >> 5][i & 31] = whh[i];
    if (gi == nullptr)
        for (int i = tid; i < 96 * 32; i += 512) wih_s[i >> 5][i & 31] = wih[i];
    hs[r][u] = h_in[row * 32 + u];
    if (gi == nullptr) xsv[r][u] = xprev[row * 32 + u];
    __syncthreads();

    float gir, giz, gin;
    if (gi != nullptr) {
        gir = gi[row * 96 + u];
        giz = gi[row * 96 + 32 + u];
        gin = gi[row * 96 + 64 + u];
    } else {
        gir = bih[u]; giz = bih[32 + u]; gin = bih[64 + u];
#pragma unroll
        for (int d = 0; d < 32; d++) {
            float xv = xsv[r][d];
            gir = fmaf(xv, wih_s[u][d], gir);
            giz = fmaf(xv, wih_s[32 + u][d], giz);
            gin = fmaf(xv, wih_s[64 + u][d], gin);
        }
    }
    float ghr = bhh[u], ghz = bhh[32 + u], ghn = bhh[64 + u];
#pragma unroll
    for (int d = 0; d < 32; d++) {
        float hv = hs[r][d];
        ghr = fmaf(hv, whh_s[u][d], ghr);
        ghz = fmaf(hv, whh_s[32 + u][d], ghz);
        ghn = fmaf(hv, whh_s[64 + u][d], ghn);
    }
    float rr = 1.f / (1.f + expf(-(gir + ghr)));
    float zz = 1.f / (1.f + expf(-(giz + ghz)));
    float nn = tanhf(gin + rr * ghn);
    h_out[row * 32 + u] = (1.f - zz) * nn + zz * hs[r][u];
}

// ---------------- final head + hT pack ----------------
__global__ void final_kernel(const float* __restrict__ nn4W, const float* __restrict__ nn4b,
                             float* __restrict__ out, int out_size)
{
    const int idx = blockIdx.x * 256 + threadIdx.x;
    if (idx >= out_size) return;
    if (idx < 2048) {
        const int t  = idx >> 10;
        const int ch = (idx >> 5) & 31;
        const int b0 = (idx & 31) * 32;
        float acc = nn4b[0];
#pragma unroll
        for (int c = 0; c < 32; c++) {
            const float v = g_out1[t * 32768 + (b0 + c) * 32 + ch];
            acc = fmaf(fmaxf(v, 0.f), nn4W[c], acc);
        }
        out[idx] = fmaxf(acc, 0.f);
    } else if (idx < 2048 + 65536) {
        const int j = idx - 2048;
        out[idx] = (j < 32768) ? g_out0[32768 + j] : g_out1[32768 + (j - 32768)];
    }
}

// ---------------- launch ----------------
extern "C" void kernel_launch(void* const* d_in, const int* in_sizes, int n_in,
                              void* d_out, int out_size)
{
    const float* x    = (const float*)d_in[0];
    const float* h1   = (const float*)d_in[2];
    const float* W1   = (const float*)d_in[3];
    const float* b1   = (const float*)d_in[4];
    const float* W2   = (const float*)d_in[5];
    const float* b2   = (const float*)d_in[6];
    const float* nn1W = (const float*)d_in[7];
    const float* nn1b = (const float*)d_in[8];
    const float* nn2W = (const float*)d_in[9];
    const float* nn2b = (const float*)d_in[10];
    const float* nn4W = (const float*)d_in[11];
    const float* nn4b = (const float*)d_in[12];
    const float* wih0 = (const float*)d_in[13];
    const float* whh0 = (const float*)d_in[14];
    const float* bih0 = (const float*)d_in[15];
    const float* bhh0 = (const float*)d_in[16];
    const float* wih1 = (const float*)d_in[17];
    const float* whh1 = (const float*)d_in[18];
    const float* bih1 = (const float*)d_in[19];
    const float* bhh1 = (const float*)d_in[20];
    float* out = (float*)d_out;

    float *gi, *out0, *out1, *wih0T;
    cudaGetSymbolAddress((void**)&gi,    g_gi);
    cudaGetSymbolAddress((void**)&out0,  g_out0);
    cudaGetSymbolAddress((void**)&out1,  g_out1);
    cudaGetSymbolAddress((void**)&wih0T, g_wih0T);

    cudaFuncSetAttribute(ec_kernel, cudaFuncAttributeMaxDynamicSharedMemorySize, EC_SMEM);
    cudaFuncSetAttribute(nn_kernel, cudaFuncAttributeMaxDynamicSharedMemorySize, NN_SMEM);

    prep_kernel<<<96, 256>>>(nn1W, nn1b, nn2W, W2, wih0);
    ec_kernel<<<NG, 256, EC_SMEM>>>(x, W1, b1, b2);
    nn_kernel<<<NG, 256, NN_SMEM>>>(nn2b);
    gi_gemm_kernel<<<64, 256>>>(wih0T, bih0, gi);
    gru_fast_kernel<<<64, 512>>>(gi,         nullptr,       nullptr, nullptr, whh0, bhh0, h1,         out0);
    gru_fast_kernel<<<64, 512>>>(gi + 98304, nullptr,       nullptr, nullptr, whh0, bhh0, out0,       out0 + 32768);
    gru_fast_kernel<<<64, 512>>>(nullptr,    out0,          wih1,    bih1,    whh1, bhh1, h1 + 32768, out1);
    gru_fast_kernel<<<64, 512>>>(nullptr,    out0 + 32768,  wih1,    bih1,    whh1, bhh1, out1,       out1 + 32768);
    final_kernel<<<(out_size + 255) / 256, 256>>>(nn4W, nn4b, out, out_size);
}

// round 9
// speedup vs baseline: 2.4424x; 1.2771x over previous
#include <cuda_runtime.h>
#include <cuda_fp16.h>
#include <math.h>
#include <stdint.h>

#define NG 2048
#define NP 128

// ---------------- scratch (device globals) ----------------
__device__ __half g_hagghi[(size_t)NG * NP * 256];
__device__ __half g_hagglo[(size_t)NG * NP * 256];
__device__ float g_gfeat[NG * 256];
__device__ float g_gi[2 * 1024 * 96];
__device__ float g_out0[2 * 1024 * 32];
__device__ float g_out1[2 * 1024 * 32];
__device__ __half g_w1h[64 * 16],   g_w1l[64 * 16];     // W1^T padded k16
__device__ __half g_w2Th[128 * 64], g_w2Tl[128 * 64];   // edge W2^T
__device__ __half g_nn1Th[96 * 256], g_nn1Tl[96 * 256]; // folded nn1^T
__device__ __half g_nn2Th[64 * 96],  g_nn2Tl[64 * 96];  // nn2^T padded
__device__ float g_nn1bp[96];
__device__ float g_wih0T[256 * 96];

// ---------------- helpers ----------------
__device__ __forceinline__ void splith(float x, __half& h, __half& l) {
    h = __float2half_rn(x);
    l = __float2half_rn(x - __half2float(h));
}
__device__ __forceinline__ uint32_t packh(__half a, __half b) {
    __half2 p = __halves2half2(a, b);
    return *(uint32_t*)&p;
}
__device__ __forceinline__ void splitpack(float x0, float x1, uint32_t& hi, uint32_t& lo) {
    __half h0, l0, h1, l1;
    splith(x0, h0, l0); splith(x1, h1, l1);
    hi = packh(h0, h1); lo = packh(l0, l1);
}
__device__ __forceinline__ void mma16(float d[4], const uint32_t a[4], const uint32_t b[2]) {
    asm volatile(
        "mma.sync.aligned.m16n8k16.row.col.f32.f16.f16.f32 "
        "{%0,%1,%2,%3},{%4,%5,%6,%7},{%8,%9},{%0,%1,%2,%3};"
        : "+f"(d[0]), "+f"(d[1]), "+f"(d[2]), "+f"(d[3])
        : "r"(a[0]), "r"(a[1]), "r"(a[2]), "r"(a[3]), "r"(b[0]), "r"(b[1]));
}
__device__ __forceinline__ void mma3h(float d[4], const uint32_t ah[4], const uint32_t al[4],
                                      const uint32_t bh[2], const uint32_t bl[2]) {
    mma16(d, ah, bh); mma16(d, ah, bl); mma16(d, al, bh);
}
// A frag from half plane [m][k], stride in halves (even), k0 multiple of 16
__device__ __forceinline__ void ldAh(const __half* P, int strideH, int m0, int k0, int lid, uint32_t a[4]) {
    const uint32_t* p = (const uint32_t*)(P + (size_t)(m0 + (lid >> 2)) * strideH + k0) + (lid & 3);
    const int rs = strideH >> 1;
    a[0] = p[0]; a[1] = p[8 * rs]; a[2] = p[4]; a[3] = p[8 * rs + 4];
}
__device__ __forceinline__ void ldBh(const __half* P, int strideH, int n0, int k0, int lid, uint32_t b[2]) {
    const uint32_t* p = (const uint32_t*)(P + (size_t)(n0 + (lid >> 2)) * strideH + k0) + (lid & 3);
    b[0] = p[0]; b[1] = p[4];
}

// ---------------- weight prep: pre-split hi/lo half planes ----------------
__global__ void prep_kernel(const float* __restrict__ nn1W, const float* __restrict__ nn1b,
                            const float* __restrict__ nn2W, const float* __restrict__ W2,
                            const float* __restrict__ W1, const float* __restrict__ wih0)
{
    int idx = blockIdx.x * 256 + threadIdx.x;   // 96 blocks -> 24576
    __half h, l;
    if (idx < 64 * 16) {
        int n = idx >> 4, k = idx & 15;
        float v = (k < 10) ? W1[k * 64 + n] : 0.f;
        splith(v, h, l); g_w1h[idx] = h; g_w1l[idx] = l;
    }
    if (idx < 128 * 64) {
        int n = idx >> 6, k = idx & 63;
        splith(W2[k * 128 + n], h, l); g_w2Th[idx] = h; g_w2Tl[idx] = l;
    }
    if (idx < 96 * 256) {
        int n = idx >> 8, k = idx & 255;
        float v = 0.f;
        if (n < 94) {
            if (k < 128) v = nn1W[k * 94 + n];
            else { int kk = k - 128; v = 0.25f * nn1W[(128 + kk) * 94 + n] + nn1W[(256 + kk) * 94 + n]; }
        }
        splith(v, h, l); g_nn1Th[idx] = h; g_nn1Tl[idx] = l;
    }
    if (idx < 64 * 96) {
        int n = idx / 96, k = idx % 96;
        float v = (k < 94) ? nn2W[k * 64 + n] : 0.f;
        splith(v, h, l); g_nn2Th[idx] = h; g_nn2Tl[idx] = l;
    }
    if (idx < 96) g_nn1bp[idx] = (idx < 94) ? nn1b[idx] : 0.f;
    if (idx < 96 * 256) { int gg = idx >> 8, d = idx & 255; g_wih0T[d * 96 + gg] = wih0[idx]; }
}

// ================= EC kernel: KNN + EdgeConv + edge agg -> hagg hi/lo planes =================
#define EC_XS    0        // 2560
#define EC_NBR   2560     // 2048
#define EC_W1H   4608     // [64][24] half = 3072
#define EC_W1L   7680     // 3072
#define EC_B1    10752    // 256
#define EC_B2    11008    // 512
#define EC_FH    11520    // feats hi [128][24] half = 6144
#define EC_FL    17664    // 6144
#define EC_W2H   23808    // [128][72] half = 18432
#define EC_W2L   42240    // 18432
#define EC_HH    60672    // [128][72] half = 18432
#define EC_HL    79104    // 18432
#define EC_SMEM  97536

__global__ void __launch_bounds__(256, 2) ec_kernel(
    const float* __restrict__ x, const float* __restrict__ b1, const float* __restrict__ b2)
{
    extern __shared__ __align__(16) char smem[];
    float* xs   = (float*)(smem + EC_XS);
    int*   nbr  = (int*)(smem + EC_NBR);
    __half* W1H = (__half*)(smem + EC_W1H);
    __half* W1L = (__half*)(smem + EC_W1L);
    float* b1s  = (float*)(smem + EC_B1);
    float* b2s  = (float*)(smem + EC_B2);
    __half* FH  = (__half*)(smem + EC_FH);
    __half* FL  = (__half*)(smem + EC_FL);
    __half* W2H = (__half*)(smem + EC_W2H);
    __half* W2L = (__half*)(smem + EC_W2L);
    __half* HH  = (__half*)(smem + EC_HH);
    __half* HL  = (__half*)(smem + EC_HL);

    const int tid = threadIdx.x, wid = tid >> 5, lid = tid & 31;
    const int rw = wid >> 1, nh = wid & 1;
    const int qr = lid >> 2, qc = lid & 3;
    const int g = blockIdx.x;
    const size_t base = (size_t)g * NP;

    for (int i = tid; i < NP * 5; i += 256) xs[i] = x[base * 5 + i];
    for (int i = tid; i < 512; i += 256) {       // W1 planes: [64][16] words -> [64][24] stride
        int n = i >> 3, kw = i & 7;
        ((uint32_t*)W1H)[n * 12 + kw] = ((const uint32_t*)g_w1h)[i];
        ((uint32_t*)W1L)[n * 12 + kw] = ((const uint32_t*)g_w1l)[i];
    }
    if (tid < 64) b1s[tid] = b1[tid];
    if (tid >= 64 && tid < 192) b2s[tid - 64] = b2[tid - 64];
    for (int i = tid; i < 4096; i += 256) {      // W2 planes: [128][32] words -> stride 36
        int n = i >> 5, kw = i & 31;
        ((uint32_t*)W2H)[n * 36 + kw] = ((const uint32_t*)g_w2Th)[i];
        ((uint32_t*)W2L)[n * 36 + kw] = ((const uint32_t*)g_w2Tl)[i];
    }
    for (int i = tid; i < 1536; i += 256) {      // zero feats planes (incl. k-pad 10..15)
        ((uint32_t*)FH)[i] = 0; ((uint32_t*)FL)[i] = 0;
    }
    __syncthreads();

    // ---- KNN (thread = node), branchless, stable ties
    if (tid < NP) {
        const float px = xs[tid * 5 + 0], py = xs[tid * 5 + 1], pz = xs[tid * 5 + 2];
        float d0 = 1e30f, d1 = 1e30f, d2v = 1e30f, d3 = 1e30f;
        int i0 = 0, i1 = 0, i2 = 0, i3 = 0;
#pragma unroll 4
        for (int j = 0; j < NP; j++) {
            float dx = xs[j * 5 + 0] - px, dy = xs[j * 5 + 1] - py, dz = xs[j * 5 + 2] - pz;
            float dd = dx * dx + dy * dy + dz * dz;
            dd = (j == tid) ? 1e30f : dd;
            bool c0 = dd < d0, c1 = dd < d1, c2 = dd < d2v, c3 = dd < d3;
            i3 = c2 ? i2 : (c3 ? j : i3);  d3  = c2 ? d2v : (c3 ? dd : d3);
            i2 = c1 ? i1 : (c2 ? j : i2);  d2v = c1 ? d1  : (c2 ? dd : d2v);
            i1 = c0 ? i0 : (c1 ? j : i1);  d1  = c0 ? d0  : (c1 ? dd : d1);
            i0 = c0 ? j : i0;              d0  = c0 ? dd  : d0;
        }
        nbr[tid * 4 + 0] = i0; nbr[tid * 4 + 1] = i1; nbr[tid * 4 + 2] = i2; nbr[tid * 4 + 3] = i3;
    }
    __syncthreads();

    // 4 passes of 128 edges; node = p*32 + (fr>>5)*8 + (r&7), k = ((r>>4)<<1)|((r>>3)&1)
    for (int p = 0; p < 4; p++) {
        for (int i = tid; i < 128 * 10; i += 256) {
            int fr = i / 10, d = i % 10;
            int r = fr & 31;
            int node = p * 32 + (fr >> 5) * 8 + (r & 7);
            int k = ((r >> 4) << 1) | ((r >> 3) & 1);
            float v;
            if (d < 5) v = xs[node * 5 + d];
            else { int j = nbr[node * 4 + k]; v = xs[j * 5 + (d - 5)] - xs[node * 5 + (d - 5)]; }
            __half hv, lv; splith(v, hv, lv);
            FH[fr * 24 + d] = hv; FL[fr * 24 + d] = lv;
        }
        __syncthreads();

        // layer-1: K=16 (one k16 step), 2 M-tiles x 4 nt
        {
            float la[2][4][4];
#pragma unroll
            for (int rt = 0; rt < 2; rt++)
#pragma unroll
                for (int j = 0; j < 4; j++) { la[rt][j][0]=0.f; la[rt][j][1]=0.f; la[rt][j][2]=0.f; la[rt][j][3]=0.f; }
            uint32_t ah[2][4], al[2][4];
            ldAh(FH, 24, rw * 32,      0, lid, ah[0]); ldAh(FL, 24, rw * 32,      0, lid, al[0]);
            ldAh(FH, 24, rw * 32 + 16, 0, lid, ah[1]); ldAh(FL, 24, rw * 32 + 16, 0, lid, al[1]);
#pragma unroll
            for (int j = 0; j < 4; j++) {
                uint32_t bh[2], bl[2];
                ldBh(W1H, 24, (nh * 4 + j) * 8, 0, lid, bh);
                ldBh(W1L, 24, (nh * 4 + j) * 8, 0, lid, bl);
                mma3h(la[0][j], ah[0], al[0], bh, bl);
                mma3h(la[1][j], ah[1], al[1], bh, bl);
            }
            // epilogue: +b1, relu -> H hi/lo planes
#pragma unroll
            for (int rt = 0; rt < 2; rt++) {
                int r0 = rw * 32 + rt * 16 + qr, r1 = r0 + 8;
#pragma unroll
                for (int j = 0; j < 4; j++) {
                    int col = (nh * 4 + j) * 8 + 2 * qc;
                    float v0 = fmaxf(la[rt][j][0] + b1s[col], 0.f), v1 = fmaxf(la[rt][j][1] + b1s[col + 1], 0.f);
                    float v2 = fmaxf(la[rt][j][2] + b1s[col], 0.f), v3 = fmaxf(la[rt][j][3] + b1s[col + 1], 0.f);
                    uint32_t h, l;
                    splitpack(v0, v1, h, l);
                    ((uint32_t*)HH)[r0 * 36 + (col >> 1)] = h; ((uint32_t*)HL)[r0 * 36 + (col >> 1)] = l;
                    splitpack(v2, v3, h, l);
                    ((uint32_t*)HH)[r1 * 36 + (col >> 1)] = h; ((uint32_t*)HL)[r1 * 36 + (col >> 1)] = l;
                }
            }
        }
        __syncthreads();

        // layer-2: K=64 (4 k16 steps), 2 M-tiles x 8 nt
        float acc[2][8][4];
#pragma unroll
        for (int rt = 0; rt < 2; rt++)
#pragma unroll
            for (int j = 0; j < 8; j++) { acc[rt][j][0]=0.f; acc[rt][j][1]=0.f; acc[rt][j][2]=0.f; acc[rt][j][3]=0.f; }
#pragma unroll
        for (int ks = 0; ks < 4; ks++) {
            uint32_t ah[2][4], al[2][4];
            ldAh(HH, 72, rw * 32,      ks * 16, lid, ah[0]); ldAh(HL, 72, rw * 32,      ks * 16, lid, al[0]);
            ldAh(HH, 72, rw * 32 + 16, ks * 16, lid, ah[1]); ldAh(HL, 72, rw * 32 + 16, ks * 16, lid, al[1]);
#pragma unroll
            for (int j = 0; j < 8; j++) {
                uint32_t bh[2], bl[2];
                ldBh(W2H, 72, (nh * 8 + j) * 8, ks * 16, lid, bh);
                ldBh(W2L, 72, (nh * 8 + j) * 8, ks * 16, lid, bl);
                mma3h(acc[0][j], ah[0], al[0], bh, bl);
                mma3h(acc[1][j], ah[1], al[1], bh, bl);
            }
        }

        // epilogue: 4 edges of node in-thread; split-pack -> gmem hagg planes
        {
            const int node = p * 32 + rw * 8 + qr;
            uint32_t* Ghh = (uint32_t*)g_hagghi + (base + node) * 128;
            uint32_t* Ghl = (uint32_t*)g_hagglo + (base + node) * 128;
#pragma unroll
            for (int j = 0; j < 8; j++) {
                int col = (nh * 8 + j) * 8 + 2 * qc;
                float bcol = b2s[col], bcol1 = b2s[col + 1];
                float v00 = fmaxf(acc[0][j][0] + bcol, 0.f),  v01 = fmaxf(acc[0][j][1] + bcol1, 0.f);
                float v10 = fmaxf(acc[0][j][2] + bcol, 0.f),  v11 = fmaxf(acc[0][j][3] + bcol1, 0.f);
                float v20 = fmaxf(acc[1][j][0] + bcol, 0.f),  v21 = fmaxf(acc[1][j][1] + bcol1, 0.f);
                float v30 = fmaxf(acc[1][j][2] + bcol, 0.f),  v31 = fmaxf(acc[1][j][3] + bcol1, 0.f);
                float mx0 = fmaxf(fmaxf(v00, v10), fmaxf(v20, v30));
                float mx1 = fmaxf(fmaxf(v01, v11), fmaxf(v21, v31));
                float sm0 = (v00 + v10) + (v20 + v30);
                float sm1 = (v01 + v11) + (v21 + v31);
                uint32_t h, l;
                splitpack(mx0, mx1, h, l); Ghh[col >> 1] = h;        Ghl[col >> 1] = l;
                splitpack(sm0, sm1, h, l); Ghh[64 + (col >> 1)] = h; Ghl[64 + (col >> 1)] = l;
            }
        }
    }
}

// ================= NN kernel: nn1 + nn2 + segreduce (block = graph) =================
#define NN_B1H  0         // [96][40] half = 7680; B2 planes [64][104]x2 = 26624 overlay
#define NN_B1L  7680
#define NN_B2H  0
#define NN_B2L  13312
#define NN_H2H  26624     // [128][104] half = 26624
#define NN_H2L  53248     // 26624  (h2 fp32 [128][68]=34816 overlays H2H.. after nn2)
#define NN_RED  79872     // 3072
#define NN_B1V  82944     // 384
#define NN_B2V  83328     // 256
#define NN_SMEM 83584

__global__ void __launch_bounds__(256, 2) nn_kernel(const float* __restrict__ nn2b)
{
    extern __shared__ __align__(16) char smem[];
    __half* B1H = (__half*)(smem + NN_B1H);
    __half* B1L = (__half*)(smem + NN_B1L);
    __half* B2H = (__half*)(smem + NN_B2H);
    __half* B2L = (__half*)(smem + NN_B2L);
    __half* H2H = (__half*)(smem + NN_H2H);
    __half* H2L = (__half*)(smem + NN_H2L);
    float* red  = (float*)(smem + NN_RED);
    float* b1v  = (float*)(smem + NN_B1V);
    float* b2v  = (float*)(smem + NN_B2V);

    const int tid = threadIdx.x, wid = tid >> 5, lid = tid & 31;
    const int rw = wid >> 1, nh = wid & 1;
    const int qr = lid >> 2, qc = lid & 3;
    const int g = blockIdx.x;
    const __half* Ah = g_hagghi + (size_t)g * NP * 256;
    const __half* Al = g_hagglo + (size_t)g * NP * 256;

    if (tid < 96) b1v[tid] = g_nn1bp[tid];
    if (tid >= 96 && tid < 160) b2v[tid - 96] = nn2b[tid - 96];

    // ---- nn1: [128][256] @ [256][96], A direct from gmem planes
    float acc1[2][6][4];
#pragma unroll
    for (int rt = 0; rt < 2; rt++)
#pragma unroll
        for (int j = 0; j < 6; j++) { acc1[rt][j][0]=0.f; acc1[rt][j][1]=0.f; acc1[rt][j][2]=0.f; acc1[rt][j][3]=0.f; }
    for (int kc = 0; kc < 8; kc++) {
        for (int i = tid; i < 1536; i += 256) {   // B1 chunk planes [96][16] words -> stride 20
            int n = i >> 4, kw = i & 15;
            ((uint32_t*)B1H)[n * 20 + kw] = ((const uint32_t*)g_nn1Th)[n * 128 + kc * 16 + kw];
            ((uint32_t*)B1L)[n * 20 + kw] = ((const uint32_t*)g_nn1Tl)[n * 128 + kc * 16 + kw];
        }
        __syncthreads();
#pragma unroll
        for (int ks = 0; ks < 2; ks++) {
            uint32_t ah[2][4], al[2][4];
            ldAh(Ah, 256, rw * 32,      kc * 32 + ks * 16, lid, ah[0]);
            ldAh(Al, 256, rw * 32,      kc * 32 + ks * 16, lid, al[0]);
            ldAh(Ah, 256, rw * 32 + 16, kc * 32 + ks * 16, lid, ah[1]);
            ldAh(Al, 256, rw * 32 + 16, kc * 32 + ks * 16, lid, al[1]);
#pragma unroll
            for (int j = 0; j < 6; j++) {
                uint32_t bh[2], bl[2];
                ldBh(B1H, 40, (nh * 6 + j) * 8, ks * 16, lid, bh);
                ldBh(B1L, 40, (nh * 6 + j) * 8, ks * 16, lid, bl);
                mma3h(acc1[0][j], ah[0], al[0], bh, bl);
                mma3h(acc1[1][j], ah[1], al[1], bh, bl);
            }
        }
        __syncthreads();
    }
    // epilogue1: H2 hi/lo planes = split(relu(acc1 + b1v)); stage B2 planes (overlay B1)
    {
#pragma unroll
        for (int rt = 0; rt < 2; rt++) {
            int r0 = rw * 32 + rt * 16 + qr, r1 = r0 + 8;
#pragma unroll
            for (int j = 0; j < 6; j++) {
                int col = (nh * 6 + j) * 8 + 2 * qc;
                float v0 = fmaxf(acc1[rt][j][0] + b1v[col], 0.f), v1 = fmaxf(acc1[rt][j][1] + b1v[col + 1], 0.f);
                float v2 = fmaxf(acc1[rt][j][2] + b1v[col], 0.f), v3 = fmaxf(acc1[rt][j][3] + b1v[col + 1], 0.f);
                uint32_t h, l;
                splitpack(v0, v1, h, l);
                ((uint32_t*)H2H)[r0 * 52 + (col >> 1)] = h; ((uint32_t*)H2L)[r0 * 52 + (col >> 1)] = l;
                splitpack(v2, v3, h, l);
                ((uint32_t*)H2H)[r1 * 52 + (col >> 1)] = h; ((uint32_t*)H2L)[r1 * 52 + (col >> 1)] = l;
            }
        }
        for (int i = tid; i < 3072; i += 256) {   // B2 planes [64][48] words -> stride 52
            int n = i / 48, kw = i % 48;
            ((uint32_t*)B2H)[n * 52 + kw] = ((const uint32_t*)g_nn2Th)[n * 48 + kw];
            ((uint32_t*)B2L)[n * 52 + kw] = ((const uint32_t*)g_nn2Tl)[n * 48 + kw];
        }
    }
    __syncthreads();

    // ---- nn2: [128][96] @ [96][64], K=96 (6 k16 steps)
    float acc2[2][4][4];
#pragma unroll
    for (int rt = 0; rt < 2; rt++)
#pragma unroll
        for (int j = 0; j < 4; j++) { acc2[rt][j][0]=0.f; acc2[rt][j][1]=0.f; acc2[rt][j][2]=0.f; acc2[rt][j][3]=0.f; }
#pragma unroll
    for (int ks = 0; ks < 6; ks++) {
        uint32_t ah[2][4], al[2][4];
        ldAh(H2H, 104, rw * 32,      ks * 16, lid, ah[0]); ldAh(H2L, 104, rw * 32,      ks * 16, lid, al[0]);
        ldAh(H2H, 104, rw * 32 + 16, ks * 16, lid, ah[1]); ldAh(H2L, 104, rw * 32 + 16, ks * 16, lid, al[1]);
#pragma unroll
        for (int j = 0; j < 4; j++) {
            uint32_t bh[2], bl[2];
            ldBh(B2H, 104, (nh * 4 + j) * 8, ks * 16, lid, bh);
            ldBh(B2L, 104, (nh * 4 + j) * 8, ks * 16, lid, bl);
            mma3h(acc2[0][j], ah[0], al[0], bh, bl);
            mma3h(acc2[1][j], ah[1], al[1], bh, bl);
        }
    }
    __syncthreads();    // all warps done reading H2/B2 before fp32 overlay
    float* h2 = (float*)(smem + NN_H2H);          // [128][68] fp32
    {
#pragma unroll
        for (int rt = 0; rt < 2; rt++) {
            int r0 = rw * 32 + rt * 16 + qr, r1 = r0 + 8;
#pragma unroll
            for (int j = 0; j < 4; j++) {
                int col = (nh * 4 + j) * 8 + 2 * qc;
                float2 u0 = { acc2[rt][j][0] + b2v[col], acc2[rt][j][1] + b2v[col + 1] };
                float2 u1 = { acc2[rt][j][2] + b2v[col], acc2[rt][j][3] + b2v[col + 1] };
                *(float2*)&h2[r0 * 68 + col] = u0;
                *(float2*)&h2[r1 * 68 + col] = u1;
            }
        }
    }
    __syncthreads();

    // ---- segment max/min/sum/mean + relu -> g_gfeat
    {
        int c = tid & 63, q = tid >> 6;
        float mx = -1e30f, mn = 1e30f, sm = 0.f;
        for (int r = q * 32; r < q * 32 + 32; r++) {
            float v = h2[r * 68 + c];
            mx = fmaxf(mx, v); mn = fminf(mn, v); sm += v;
        }
        red[q * 192 + c] = mx; red[q * 192 + 64 + c] = mn; red[q * 192 + 128 + c] = sm;
        __syncthreads();
        if (tid < 64) {
            float MX = red[c], MN = red[64 + c], SM = red[128 + c];
            for (int qq = 1; qq < 4; qq++) {
                MX = fmaxf(MX, red[qq * 192 + c]);
                MN = fminf(MN, red[qq * 192 + 64 + c]);
                SM += red[qq * 192 + 128 + c];
            }
            float* o = g_gfeat + (size_t)g * 256;
            o[c]        = fmaxf(MX, 0.f);
            o[64 + c]   = fmaxf(MN, 0.f);
            o[128 + c]  = fmaxf(SM, 0.f);
            o[192 + c]  = fmaxf(SM * (1.f / 128.f), 0.f);
        }
    }
}

// ---------------- GI = permute(gfeat) @ wih0T + bih0 ----------------
__global__ void __launch_bounds__(256) gi_gemm_kernel(
    const float* __restrict__ W, const float* __restrict__ bias, float* __restrict__ C)
{
    __shared__ __align__(16) float As[32][36];
    __shared__ float Ws[32][96];
    const int tid  = threadIdx.x;
    const int bm   = blockIdx.x * 32;
    const int trow = (tid & 7) * 4;
    const int tcol = (tid >> 3) * 3;

    float acc[4][3];
#pragma unroll
    for (int i = 0; i < 4; i++)
#pragma unroll
        for (int j = 0; j < 3; j++) acc[i][j] = 0.f;

    const int lr = tid >> 3;
    const int lc = (tid & 7) * 4;

    const int rg = bm + lr;
    const int t = rg >> 10, b = rg & 1023;
    const float* gf = g_gfeat + (size_t)(t * 1024 + (b >> 8)) * 256 + (b & 255);

    for (int k0 = 0; k0 < 256; k0 += 32) {
        As[lc + 0][lr] = gf[(size_t)(k0 + lc + 0) << 10];
        As[lc + 1][lr] = gf[(size_t)(k0 + lc + 1) << 10];
        As[lc + 2][lr] = gf[(size_t)(k0 + lc + 2) << 10];
        As[lc + 3][lr] = gf[(size_t)(k0 + lc + 3) << 10];
        for (int i = tid; i < 32 * 96; i += 256)
            (&Ws[0][0])[i] = W[k0 * 96 + i];
        __syncthreads();
#pragma unroll
        for (int k = 0; k < 32; k++) {
            const float4 a4 = *(const float4*)&As[k][trow];
            const float av[4] = {a4.x, a4.y, a4.z, a4.w};
#pragma unroll
            for (int j = 0; j < 3; j++) {
                const float w = Ws[k][tcol + j];
#pragma unroll
                for (int i = 0; i < 4; i++) acc[i][j] = fmaf(av[i], w, acc[i][j]);
            }
        }
        __syncthreads();
    }
#pragma unroll
    for (int j = 0; j < 3; j++) {
        const float b2 = bias[tcol + j];
#pragma unroll
        for (int i = 0; i < 4; i++)
            C[(size_t)(bm + trow + i) * 96 + tcol + j] = acc[i][j] + b2;
    }
}

// ---------------- fast GRU step ----------------
__global__ void __launch_bounds__(512) gru_fast_kernel(
    const float* __restrict__ gi,
    const float* __restrict__ xprev,
    const float* __restrict__ wih,
    const float* __restrict__ bih,
    const float* __restrict__ whh,
    const float* __restrict__ bhh,
    const float* __restrict__ h_in,
    float* __restrict__ h_out)
{
    __shared__ float whh_s[96][33];
    __shared__ float wih_s[96][33];
    __shared__ float hs[16][33];
    __shared__ float xsv[16][33];
    const int tid = threadIdx.x;
    const int r = tid >> 5, u = tid & 31;
    const int row = blockIdx.x * 16 + r;

    for (int i = tid; i < 96 * 32; i += 512) whh_s[i >> 5][i & 31] = whh[i];
    if (gi == nullptr)
        for (int i = tid; i < 96 * 32; i += 512) wih_s[i >> 5][i & 31] = wih[i];
    hs[r][u] = h_in[row * 32 + u];
    if (gi == nullptr) xsv[r][u] = xprev[row * 32 + u];
    __syncthreads();

    float gir, giz, gin;
    if (gi != nullptr) {
        gir = gi[row * 96 + u];
        giz = gi[row * 96 + 32 + u];
        gin = gi[row * 96 + 64 + u];
    } else {
        gir = bih[u]; giz = bih[32 + u]; gin = bih[64 + u];
#pragma unroll
        for (int d = 0; d < 32; d++) {
            float xv = xsv[r][d];
            gir = fmaf(xv, wih_s[u][d], gir);
            giz = fmaf(xv, wih_s[32 + u][d], giz);
            gin = fmaf(xv, wih_s[64 + u][d], gin);
        }
    }
    float ghr = bhh[u], ghz = bhh[32 + u], ghn = bhh[64 + u];
#pragma unroll
    for (int d = 0; d < 32; d++) {
        float hv = hs[r][d];
        ghr = fmaf(hv, whh_s[u][d], ghr);
        ghz = fmaf(hv, whh_s[32 + u][d], ghz);
        ghn = fmaf(hv, whh_s[64 + u][d], ghn);
    }
    float rr = 1.f / (1.f + expf(-(gir + ghr)));
    float zz = 1.f / (1.f + expf(-(giz + ghz)));
    float nn = tanhf(gin + rr * ghn);
    h_out[row * 32 + u] = (1.f - zz) * nn + zz * hs[r][u];
}

// ---------------- final head + hT pack ----------------
__global__ void final_kernel(const float* __restrict__ nn4W, const float* __restrict__ nn4b,
                             float* __restrict__ out, int out_size)
{
    const int idx = blockIdx.x * 256 + threadIdx.x;
    if (idx >= out_size) return;
    if (idx < 2048) {
        const int t  = idx >> 10;
        const int ch = (idx >> 5) & 31;
        const int b0 = (idx & 31) * 32;
        float acc = nn4b[0];
#pragma unroll
        for (int c = 0; c < 32; c++) {
            const float v = g_out1[t * 32768 + (b0 + c) * 32 + ch];
            acc = fmaf(fmaxf(v, 0.f), nn4W[c], acc);
        }
        out[idx] = fmaxf(acc, 0.f);
    } else if (idx < 2048 + 65536) {
        const int j = idx - 2048;
        out[idx] = (j < 32768) ? g_out0[32768 + j] : g_out1[32768 + (j - 32768)];
    }
}

// ---------------- launch ----------------
extern "C" void kernel_launch(void* const* d_in, const int* in_sizes, int n_in,
                              void* d_out, int out_size)
{
    const float* x    = (const float*)d_in[0];
    const float* h1   = (const float*)d_in[2];
    const float* W1   = (const float*)d_in[3];
    const float* b1   = (const float*)d_in[4];
    const float* W2   = (const float*)d_in[5];
    const float* b2   = (const float*)d_in[6];
    const float* nn1W = (const float*)d_in[7];
    const float* nn1b = (const float*)d_in[8];
    const float* nn2W = (const float*)d_in[9];
    const float* nn2b = (const float*)d_in[10];
    const float* nn4W = (const float*)d_in[11];
    const float* nn4b = (const float*)d_in[12];
    const float* wih0 = (const float*)d_in[13];
    const float* whh0 = (const float*)d_in[14];
    const float* bih0 = (const float*)d_in[15];
    const float* bhh0 = (const float*)d_in[16];
    const float* wih1 = (const float*)d_in[17];
    const float* whh1 = (const float*)d_in[18];
    const float* bih1 = (const float*)d_in[19];
    const float* bhh1 = (const float*)d_in[20];
    float* out = (float*)d_out;

    float *gi, *out0, *out1, *wih0T;
    cudaGetSymbolAddress((void**)&gi,    g_gi);
    cudaGetSymbolAddress((void**)&out0,  g_out0);
    cudaGetSymbolAddress((void**)&out1,  g_out1);
    cudaGetSymbolAddress((void**)&wih0T, g_wih0T);

    cudaFuncSetAttribute(ec_kernel, cudaFuncAttributeMaxDynamicSharedMemorySize, EC_SMEM);
    cudaFuncSetAttribute(nn_kernel, cudaFuncAttributeMaxDynamicSharedMemorySize, NN_SMEM);

    prep_kernel<<<96, 256>>>(nn1W, nn1b, nn2W, W2, W1, wih0);
    ec_kernel<<<NG, 256, EC_SMEM>>>(x, b1, b2);
    nn_kernel<<<NG, 256, NN_SMEM>>>(nn2b);
    gi_gemm_kernel<<<64, 256>>>(wih0T, bih0, gi);
    gru_fast_kernel<<<64, 512>>>(gi,         nullptr,       nullptr, nullptr, whh0, bhh0, h1,         out0);
    gru_fast_kernel<<<64, 512>>>(gi + 98304, nullptr,       nullptr, nullptr, whh0, bhh0, out0,       out0 + 32768);
    gru_fast_kernel<<<64, 512>>>(nullptr,    out0,          wih1,    bih1,    whh1, bhh1, h1 + 32768, out1);
    gru_fast_kernel<<<64, 512>>>(nullptr,    out0 + 32768,  wih1,    bih1,    whh1, bhh1, out1,       out1 + 32768);
    final_kernel<<<(out_size + 255) / 256, 256>>>(nn4W, nn4b, out, out_size);
}

// round 10
// speedup vs baseline: 2.6539x; 1.0866x over previous
#include <cuda_runtime.h>
#include <cuda_fp16.h>
#include <math.h>
#include <stdint.h>

#define NG 2048
#define NP 128

// ---------------- scratch (device globals) ----------------
__device__ __half g_hagghi[(size_t)NG * NP * 256];
__device__ __half g_hagglo[(size_t)NG * NP * 256];
__device__ float g_gfeat[NG * 256];
__device__ float g_gi[2 * 1024 * 96];
__device__ float g_out0[2 * 1024 * 32];
__device__ float g_out1[2 * 1024 * 32];
__device__ __half g_w1h[64 * 16],   g_w1l[64 * 16];     // W1^T padded k16
__device__ __half g_w2Th[128 * 64], g_w2Tl[128 * 64];   // edge W2^T
__device__ __half g_nn1Th[96 * 256], g_nn1Tl[96 * 256]; // folded nn1^T
__device__ __half g_nn2Th[64 * 96],  g_nn2Tl[64 * 96];  // nn2^T padded
__device__ float g_nn1bp[96];
__device__ float g_wih0T[256 * 96];

// ---------------- helpers ----------------
__device__ __forceinline__ void splith(float x, __half& h, __half& l) {
    h = __float2half_rn(x);
    l = __float2half_rn(x - __half2float(h));
}
__device__ __forceinline__ uint32_t packh(__half a, __half b) {
    __half2 p = __halves2half2(a, b);
    return *(uint32_t*)&p;
}
__device__ __forceinline__ void splitpack(float x0, float x1, uint32_t& hi, uint32_t& lo) {
    __half h0, l0, h1, l1;
    splith(x0, h0, l0); splith(x1, h1, l1);
    hi = packh(h0, h1); lo = packh(l0, l1);
}
__device__ __forceinline__ void mma16(float d[4], const uint32_t a[4], const uint32_t b[2]) {
    asm volatile(
        "mma.sync.aligned.m16n8k16.row.col.f32.f16.f16.f32 "
        "{%0,%1,%2,%3},{%4,%5,%6,%7},{%8,%9},{%0,%1,%2,%3};"
        : "+f"(d[0]), "+f"(d[1]), "+f"(d[2]), "+f"(d[3])
        : "r"(a[0]), "r"(a[1]), "r"(a[2]), "r"(a[3]), "r"(b[0]), "r"(b[1]));
}
__device__ __forceinline__ void mma3h(float d[4], const uint32_t ah[4], const uint32_t al[4],
                                      const uint32_t bh[2], const uint32_t bl[2]) {
    mma16(d, ah, bh); mma16(d, ah, bl); mma16(d, al, bh);
}
// ldmatrix x4: A m16k16 frag (also used for B-pair loads). stride in halves (16B-mult).
__device__ __forceinline__ void ldsm4(const __half* P, int strideH, int m0, int k0, int lid, uint32_t a[4]) {
    uint32_t addr = (uint32_t)__cvta_generic_to_shared(
        P + (size_t)(m0 + (lid & 15)) * strideH + k0 + ((lid >> 4) << 3));
    asm volatile("ldmatrix.sync.aligned.m8n8.x4.shared.b16 {%0,%1,%2,%3}, [%4];"
        : "=r"(a[0]), "=r"(a[1]), "=r"(a[2]), "=r"(a[3]) : "r"(addr));
}

// ---------------- weight prep: pre-split hi/lo half planes ----------------
__global__ void prep_kernel(const float* __restrict__ nn1W, const float* __restrict__ nn1b,
                            const float* __restrict__ nn2W, const float* __restrict__ W2,
                            const float* __restrict__ W1, const float* __restrict__ wih0)
{
    int idx = blockIdx.x * 256 + threadIdx.x;   // 96 blocks -> 24576
    __half h, l;
    if (idx < 64 * 16) {
        int n = idx >> 4, k = idx & 15;
        float v = (k < 10) ? W1[k * 64 + n] : 0.f;
        splith(v, h, l); g_w1h[idx] = h; g_w1l[idx] = l;
    }
    if (idx < 128 * 64) {
        int n = idx >> 6, k = idx & 63;
        splith(W2[k * 128 + n], h, l); g_w2Th[idx] = h; g_w2Tl[idx] = l;
    }
    if (idx < 96 * 256) {
        int n = idx >> 8, k = idx & 255;
        float v = 0.f;
        if (n < 94) {
            if (k < 128) v = nn1W[k * 94 + n];
            else { int kk = k - 128; v = 0.25f * nn1W[(128 + kk) * 94 + n] + nn1W[(256 + kk) * 94 + n]; }
        }
        splith(v, h, l); g_nn1Th[idx] = h; g_nn1Tl[idx] = l;
    }
    if (idx < 64 * 96) {
        int n = idx / 96, k = idx % 96;
        float v = (k < 94) ? nn2W[k * 64 + n] : 0.f;
        splith(v, h, l); g_nn2Th[idx] = h; g_nn2Tl[idx] = l;
    }
    if (idx < 96) g_nn1bp[idx] = (idx < 94) ? nn1b[idx] : 0.f;
    if (idx < 96 * 256) { int gg = idx >> 8, d = idx & 255; g_wih0T[d * 96 + gg] = wih0[idx]; }
}

// ================= EC kernel: KNN + EdgeConv + edge agg -> hagg hi/lo planes =================
#define EC_XS    0        // 2560
#define EC_NBR   2560     // 2048
#define EC_W1H   4608     // [64][24] half = 3072
#define EC_W1L   7680     // 3072
#define EC_B1    10752    // 256
#define EC_B2    11008    // 512
#define EC_FH    11520    // feats hi [128][24] half = 6144
#define EC_FL    17664    // 6144
#define EC_W2H   23808    // [128][72] half = 18432
#define EC_W2L   42240    // 18432
#define EC_HH    60672    // [128][72] half = 18432
#define EC_HL    79104    // 18432
#define EC_SMEM  97536

__global__ void __launch_bounds__(256, 2) ec_kernel(
    const float* __restrict__ x, const float* __restrict__ b1, const float* __restrict__ b2)
{
    extern __shared__ __align__(16) char smem[];
    float* xs   = (float*)(smem + EC_XS);
    int*   nbr  = (int*)(smem + EC_NBR);
    __half* W1H = (__half*)(smem + EC_W1H);
    __half* W1L = (__half*)(smem + EC_W1L);
    float* b1s  = (float*)(smem + EC_B1);
    float* b2s  = (float*)(smem + EC_B2);
    __half* FH  = (__half*)(smem + EC_FH);
    __half* FL  = (__half*)(smem + EC_FL);
    __half* W2H = (__half*)(smem + EC_W2H);
    __half* W2L = (__half*)(smem + EC_W2L);
    __half* HH  = (__half*)(smem + EC_HH);
    __half* HL  = (__half*)(smem + EC_HL);

    const int tid = threadIdx.x, wid = tid >> 5, lid = tid & 31;
    const int rw = wid >> 1, nh = wid & 1;
    const int qr = lid >> 2, qc = lid & 3;
    const int g = blockIdx.x;
    const size_t base = (size_t)g * NP;

    for (int i = tid; i < NP * 5; i += 256) xs[i] = x[base * 5 + i];
    for (int i = tid; i < 512; i += 256) {       // W1 planes: [64][16] -> stride 24 halves
        int n = i >> 3, kw = i & 7;
        ((uint32_t*)W1H)[n * 12 + kw] = ((const uint32_t*)g_w1h)[i];
        ((uint32_t*)W1L)[n * 12 + kw] = ((const uint32_t*)g_w1l)[i];
    }
    if (tid < 64) b1s[tid] = b1[tid];
    if (tid >= 64 && tid < 192) b2s[tid - 64] = b2[tid - 64];
    for (int i = tid; i < 4096; i += 256) {      // W2 planes: stride 72 halves
        int n = i >> 5, kw = i & 31;
        ((uint32_t*)W2H)[n * 36 + kw] = ((const uint32_t*)g_w2Th)[i];
        ((uint32_t*)W2L)[n * 36 + kw] = ((const uint32_t*)g_w2Tl)[i];
    }
    for (int i = tid; i < 1536; i += 256) {      // zero feats planes (incl. k-pad)
        ((uint32_t*)FH)[i] = 0; ((uint32_t*)FL)[i] = 0;
    }
    __syncthreads();

    // ---- KNN (thread = node), branchless, stable ties
    if (tid < NP) {
        const float px = xs[tid * 5 + 0], py = xs[tid * 5 + 1], pz = xs[tid * 5 + 2];
        float d0 = 1e30f, d1 = 1e30f, d2v = 1e30f, d3 = 1e30f;
        int i0 = 0, i1 = 0, i2 = 0, i3 = 0;
#pragma unroll 4
        for (int j = 0; j < NP; j++) {
            float dx = xs[j * 5 + 0] - px, dy = xs[j * 5 + 1] - py, dz = xs[j * 5 + 2] - pz;
            float dd = dx * dx + dy * dy + dz * dz;
            dd = (j == tid) ? 1e30f : dd;
            bool c0 = dd < d0, c1 = dd < d1, c2 = dd < d2v, c3 = dd < d3;
            i3 = c2 ? i2 : (c3 ? j : i3);  d3  = c2 ? d2v : (c3 ? dd : d3);
            i2 = c1 ? i1 : (c2 ? j : i2);  d2v = c1 ? d1  : (c2 ? dd : d2v);
            i1 = c0 ? i0 : (c1 ? j : i1);  d1  = c0 ? d0  : (c1 ? dd : d1);
            i0 = c0 ? j : i0;              d0  = c0 ? dd  : d0;
        }
        nbr[tid * 4 + 0] = i0; nbr[tid * 4 + 1] = i1; nbr[tid * 4 + 2] = i2; nbr[tid * 4 + 3] = i3;
    }
    __syncthreads();

    // 4 passes of 128 edges; node = p*32 + (fr>>5)*8 + (r&7), k = ((r>>4)<<1)|((r>>3)&1)
    for (int p = 0; p < 4; p++) {
        for (int i = tid; i < 128 * 10; i += 256) {
            int fr = i / 10, d = i % 10;
            int r = fr & 31;
            int node = p * 32 + (fr >> 5) * 8 + (r & 7);
            int k = ((r >> 4) << 1) | ((r >> 3) & 1);
            float v;
            if (d < 5) v = xs[node * 5 + d];
            else { int j = nbr[node * 4 + k]; v = xs[j * 5 + (d - 5)] - xs[node * 5 + (d - 5)]; }
            __half hv, lv; splith(v, hv, lv);
            FH[fr * 24 + d] = hv; FL[fr * 24 + d] = lv;
        }
        __syncthreads();

        // layer-1: K=16 (one k16 step), 2 M-tiles x 4 nt (2 pairs)
        {
            float la[2][4][4];
#pragma unroll
            for (int rt = 0; rt < 2; rt++)
#pragma unroll
                for (int j = 0; j < 4; j++) { la[rt][j][0]=0.f; la[rt][j][1]=0.f; la[rt][j][2]=0.f; la[rt][j][3]=0.f; }
            uint32_t ah[2][4], al[2][4];
            ldsm4(FH, 24, rw * 32,      0, lid, ah[0]); ldsm4(FL, 24, rw * 32,      0, lid, al[0]);
            ldsm4(FH, 24, rw * 32 + 16, 0, lid, ah[1]); ldsm4(FL, 24, rw * 32 + 16, 0, lid, al[1]);
#pragma unroll
            for (int jp = 0; jp < 2; jp++) {
                uint32_t bh4[4], bl4[4];
                ldsm4(W1H, 24, (nh * 4 + jp * 2) * 8, 0, lid, bh4);
                ldsm4(W1L, 24, (nh * 4 + jp * 2) * 8, 0, lid, bl4);
                uint32_t b0h[2] = {bh4[0], bh4[2]}, b1h[2] = {bh4[1], bh4[3]};
                uint32_t b0l[2] = {bl4[0], bl4[2]}, b1l[2] = {bl4[1], bl4[3]};
                mma3h(la[0][jp * 2],     ah[0], al[0], b0h, b0l);
                mma3h(la[1][jp * 2],     ah[1], al[1], b0h, b0l);
                mma3h(la[0][jp * 2 + 1], ah[0], al[0], b1h, b1l);
                mma3h(la[1][jp * 2 + 1], ah[1], al[1], b1h, b1l);
            }
            // epilogue: +b1, relu -> H hi/lo planes
#pragma unroll
            for (int rt = 0; rt < 2; rt++) {
                int r0 = rw * 32 + rt * 16 + qr, r1 = r0 + 8;
#pragma unroll
                for (int j = 0; j < 4; j++) {
                    int col = (nh * 4 + j) * 8 + 2 * qc;
                    float v0 = fmaxf(la[rt][j][0] + b1s[col], 0.f), v1 = fmaxf(la[rt][j][1] + b1s[col + 1], 0.f);
                    float v2 = fmaxf(la[rt][j][2] + b1s[col], 0.f), v3 = fmaxf(la[rt][j][3] + b1s[col + 1], 0.f);
                    uint32_t h, l;
                    splitpack(v0, v1, h, l);
                    ((uint32_t*)HH)[r0 * 36 + (col >> 1)] = h; ((uint32_t*)HL)[r0 * 36 + (col >> 1)] = l;
                    splitpack(v2, v3, h, l);
                    ((uint32_t*)HH)[r1 * 36 + (col >> 1)] = h; ((uint32_t*)HL)[r1 * 36 + (col >> 1)] = l;
                }
            }
        }
        __syncthreads();

        // layer-2: K=64 (4 k16 steps), 2 M-tiles x 8 nt (4 pairs)
        float acc[2][8][4];
#pragma unroll
        for (int rt = 0; rt < 2; rt++)
#pragma unroll
            for (int j = 0; j < 8; j++) { acc[rt][j][0]=0.f; acc[rt][j][1]=0.f; acc[rt][j][2]=0.f; acc[rt][j][3]=0.f; }
#pragma unroll
        for (int ks = 0; ks < 4; ks++) {
            uint32_t ah[2][4], al[2][4];
            ldsm4(HH, 72, rw * 32,      ks * 16, lid, ah[0]); ldsm4(HL, 72, rw * 32,      ks * 16, lid, al[0]);
            ldsm4(HH, 72, rw * 32 + 16, ks * 16, lid, ah[1]); ldsm4(HL, 72, rw * 32 + 16, ks * 16, lid, al[1]);
#pragma unroll
            for (int jp = 0; jp < 4; jp++) {
                uint32_t bh4[4], bl4[4];
                ldsm4(W2H, 72, (nh * 8 + jp * 2) * 8, ks * 16, lid, bh4);
                ldsm4(W2L, 72, (nh * 8 + jp * 2) * 8, ks * 16, lid, bl4);
                uint32_t b0h[2] = {bh4[0], bh4[2]}, b1h[2] = {bh4[1], bh4[3]};
                uint32_t b0l[2] = {bl4[0], bl4[2]}, b1l[2] = {bl4[1], bl4[3]};
                mma3h(acc[0][jp * 2],     ah[0], al[0], b0h, b0l);
                mma3h(acc[1][jp * 2],     ah[1], al[1], b0h, b0l);
                mma3h(acc[0][jp * 2 + 1], ah[0], al[0], b1h, b1l);
                mma3h(acc[1][jp * 2 + 1], ah[1], al[1], b1h, b1l);
            }
        }

        // epilogue: 4 edges of node in-thread; split-pack -> gmem hagg planes
        {
            const int node = p * 32 + rw * 8 + qr;
            uint32_t* Ghh = (uint32_t*)g_hagghi + (base + node) * 128;
            uint32_t* Ghl = (uint32_t*)g_hagglo + (base + node) * 128;
#pragma unroll
            for (int j = 0; j < 8; j++) {
                int col = (nh * 8 + j) * 8 + 2 * qc;
                float bcol = b2s[col], bcol1 = b2s[col + 1];
                float v00 = fmaxf(acc[0][j][0] + bcol, 0.f),  v01 = fmaxf(acc[0][j][1] + bcol1, 0.f);
                float v10 = fmaxf(acc[0][j][2] + bcol, 0.f),  v11 = fmaxf(acc[0][j][3] + bcol1, 0.f);
                float v20 = fmaxf(acc[1][j][0] + bcol, 0.f),  v21 = fmaxf(acc[1][j][1] + bcol1, 0.f);
                float v30 = fmaxf(acc[1][j][2] + bcol, 0.f),  v31 = fmaxf(acc[1][j][3] + bcol1, 0.f);
                float mx0 = fmaxf(fmaxf(v00, v10), fmaxf(v20, v30));
                float mx1 = fmaxf(fmaxf(v01, v11), fmaxf(v21, v31));
                float sm0 = (v00 + v10) + (v20 + v30);
                float sm1 = (v01 + v11) + (v21 + v31);
                uint32_t h, l;
                splitpack(mx0, mx1, h, l); Ghh[col >> 1] = h;        Ghl[col >> 1] = l;
                splitpack(sm0, sm1, h, l); Ghh[64 + (col >> 1)] = h; Ghl[64 + (col >> 1)] = l;
            }
        }
    }
}

// ================= NN kernel: nn1 + nn2 + segreduce (block = graph) =================
#define NN_ASH  0         // A chunk hi [128][40] half = 10240
#define NN_ASL  10240     // 10240
#define NN_B1H  20480     // [96][40] half = 7680
#define NN_B1L  28160     // 7680
#define NN_B2H  0         // overlay after nn1: [64][104] half = 13312
#define NN_B2L  13312     // 13312
#define NN_H2H  35840     // [128][104] half = 26624
#define NN_H2L  62464     // 26624  (h2 fp32 [128][68] overlays H2H after nn2)
#define NN_RED  89088     // 3072
#define NN_B1V  92160     // 384
#define NN_B2V  92544     // 256
#define NN_SMEM 92800

__global__ void __launch_bounds__(256, 2) nn_kernel(const float* __restrict__ nn2b)
{
    extern __shared__ __align__(16) char smem[];
    __half* AsH = (__half*)(smem + NN_ASH);
    __half* AsL = (__half*)(smem + NN_ASL);
    __half* B1H = (__half*)(smem + NN_B1H);
    __half* B1L = (__half*)(smem + NN_B1L);
    __half* B2H = (__half*)(smem + NN_B2H);
    __half* B2L = (__half*)(smem + NN_B2L);
    __half* H2H = (__half*)(smem + NN_H2H);
    __half* H2L = (__half*)(smem + NN_H2L);
    float* red  = (float*)(smem + NN_RED);
    float* b1v  = (float*)(smem + NN_B1V);
    float* b2v  = (float*)(smem + NN_B2V);

    const int tid = threadIdx.x, wid = tid >> 5, lid = tid & 31;
    const int rw = wid >> 1, nh = wid & 1;
    const int qr = lid >> 2, qc = lid & 3;
    const int g = blockIdx.x;
    const __half* Ah = g_hagghi + (size_t)g * NP * 256;
    const __half* Al = g_hagglo + (size_t)g * NP * 256;

    if (tid < 96) b1v[tid] = g_nn1bp[tid];
    if (tid >= 96 && tid < 160) b2v[tid - 96] = nn2b[tid - 96];

    // ---- nn1: [128][256] @ [256][96]; A chunk + B1 chunk staged in smem per kc
    float acc1[2][6][4];
#pragma unroll
    for (int rt = 0; rt < 2; rt++)
#pragma unroll
        for (int j = 0; j < 6; j++) { acc1[rt][j][0]=0.f; acc1[rt][j][1]=0.f; acc1[rt][j][2]=0.f; acc1[rt][j][3]=0.f; }
    for (int kc = 0; kc < 8; kc++) {
        for (int i = tid; i < 512; i += 256) {    // A chunk [128][32] halves, coalesced 16B
            int r = i >> 2, q = i & 3;
            *(uint4*)(AsH + r * 40 + q * 8) = *(const uint4*)(Ah + r * 256 + kc * 32 + q * 8);
            *(uint4*)(AsL + r * 40 + q * 8) = *(const uint4*)(Al + r * 256 + kc * 32 + q * 8);
        }
        for (int i = tid; i < 1536; i += 256) {   // B1 chunk planes [96][16] words -> stride 20
            int n = i >> 4, kw = i & 15;
            ((uint32_t*)B1H)[n * 20 + kw] = ((const uint32_t*)g_nn1Th)[n * 128 + kc * 16 + kw];
            ((uint32_t*)B1L)[n * 20 + kw] = ((const uint32_t*)g_nn1Tl)[n * 128 + kc * 16 + kw];
        }
        __syncthreads();
#pragma unroll
        for (int ks = 0; ks < 2; ks++) {
            uint32_t ah[2][4], al[2][4];
            ldsm4(AsH, 40, rw * 32,      ks * 16, lid, ah[0]); ldsm4(AsL, 40, rw * 32,      ks * 16, lid, al[0]);
            ldsm4(AsH, 40, rw * 32 + 16, ks * 16, lid, ah[1]); ldsm4(AsL, 40, rw * 32 + 16, ks * 16, lid, al[1]);
#pragma unroll
            for (int jp = 0; jp < 3; jp++) {
                uint32_t bh4[4], bl4[4];
                ldsm4(B1H, 40, (nh * 6 + jp * 2) * 8, ks * 16, lid, bh4);
                ldsm4(B1L, 40, (nh * 6 + jp * 2) * 8, ks * 16, lid, bl4);
                uint32_t b0h[2] = {bh4[0], bh4[2]}, b1h[2] = {bh4[1], bh4[3]};
                uint32_t b0l[2] = {bl4[0], bl4[2]}, b1l[2] = {bl4[1], bl4[3]};
                mma3h(acc1[0][jp * 2],     ah[0], al[0], b0h, b0l);
                mma3h(acc1[1][jp * 2],     ah[1], al[1], b0h, b0l);
                mma3h(acc1[0][jp * 2 + 1], ah[0], al[0], b1h, b1l);
                mma3h(acc1[1][jp * 2 + 1], ah[1], al[1], b1h, b1l);
            }
        }
        __syncthreads();
    }
    // epilogue1: H2 hi/lo planes = split(relu(acc1 + b1v)); stage B2 planes (overlay A/B1)
    {
#pragma unroll
        for (int rt = 0; rt < 2; rt++) {
            int r0 = rw * 32 + rt * 16 + qr, r1 = r0 + 8;
#pragma unroll
            for (int j = 0; j < 6; j++) {
                int col = (nh * 6 + j) * 8 + 2 * qc;
                float v0 = fmaxf(acc1[rt][j][0] + b1v[col], 0.f), v1 = fmaxf(acc1[rt][j][1] + b1v[col + 1], 0.f);
                float v2 = fmaxf(acc1[rt][j][2] + b1v[col], 0.f), v3 = fmaxf(acc1[rt][j][3] + b1v[col + 1], 0.f);
                uint32_t h, l;
                splitpack(v0, v1, h, l);
                ((uint32_t*)H2H)[r0 * 52 + (col >> 1)] = h; ((uint32_t*)H2L)[r0 * 52 + (col >> 1)] = l;
                splitpack(v2, v3, h, l);
                ((uint32_t*)H2H)[r1 * 52 + (col >> 1)] = h; ((uint32_t*)H2L)[r1 * 52 + (col >> 1)] = l;
            }
        }
        for (int i = tid; i < 3072; i += 256) {   // B2 planes [64][48] words -> stride 52
            int n = i / 48, kw = i % 48;
            ((uint32_t*)B2H)[n * 52 + kw] = ((const uint32_t*)g_nn2Th)[n * 48 + kw];
            ((uint32_t*)B2L)[n * 52 + kw] = ((const uint32_t*)g_nn2Tl)[n * 48 + kw];
        }
    }
    __syncthreads();

    // ---- nn2: [128][96] @ [96][64], K=96 (6 k16 steps), 4 nt (2 pairs)
    float acc2[2][4][4];
#pragma unroll
    for (int rt = 0; rt < 2; rt++)
#pragma unroll
        for (int j = 0; j < 4; j++) { acc2[rt][j][0]=0.f; acc2[rt][j][1]=0.f; acc2[rt][j][2]=0.f; acc2[rt][j][3]=0.f; }
#pragma unroll
    for (int ks = 0; ks < 6; ks++) {
        uint32_t ah[2][4], al[2][4];
        ldsm4(H2H, 104, rw * 32,      ks * 16, lid, ah[0]); ldsm4(H2L, 104, rw * 32,      ks * 16, lid, al[0]);
        ldsm4(H2H, 104, rw * 32 + 16, ks * 16, lid, ah[1]); ldsm4(H2L, 104, rw * 32 + 16, ks * 16, lid, al[1]);
#pragma unroll
        for (int jp = 0; jp < 2; jp++) {
            uint32_t bh4[4], bl4[4];
            ldsm4(B2H, 104, (nh * 4 + jp * 2) * 8, ks * 16, lid, bh4);
            ldsm4(B2L, 104, (nh * 4 + jp * 2) * 8, ks * 16, lid, bl4);
            uint32_t b0h[2] = {bh4[0], bh4[2]}, b1h[2] = {bh4[1], bh4[3]};
            uint32_t b0l[2] = {bl4[0], bl4[2]}, b1l[2] = {bl4[1], bl4[3]};
            mma3h(acc2[0][jp * 2],     ah[0], al[0], b0h, b0l);
            mma3h(acc2[1][jp * 2],     ah[1], al[1], b0h, b0l);
            mma3h(acc2[0][jp * 2 + 1], ah[0], al[0], b1h, b1l);
            mma3h(acc2[1][jp * 2 + 1], ah[1], al[1], b1h, b1l);
        }
    }
    __syncthreads();    // all warps done reading H2/B2 before fp32 overlay
    float* h2 = (float*)(smem + NN_H2H);          // [128][68] fp32
    {
#pragma unroll
        for (int rt = 0; rt < 2; rt++) {
            int r0 = rw * 32 + rt * 16 + qr, r1 = r0 + 8;
#pragma unroll
            for (int j = 0; j < 4; j++) {
                int col = (nh * 4 + j) * 8 + 2 * qc;
                float2 u0 = { acc2[rt][j][0] + b2v[col], acc2[rt][j][1] + b2v[col + 1] };
                float2 u1 = { acc2[rt][j][2] + b2v[col], acc2[rt][j][3] + b2v[col + 1] };
                *(float2*)&h2[r0 * 68 + col] = u0;
                *(float2*)&h2[r1 * 68 + col] = u1;
            }
        }
    }
    __syncthreads();

    // ---- segment max/min/sum/mean + relu -> g_gfeat
    {
        int c = tid & 63, q = tid >> 6;
        float mx = -1e30f, mn = 1e30f, sm = 0.f;
        for (int r = q * 32; r < q * 32 + 32; r++) {
            float v = h2[r * 68 + c];
            mx = fmaxf(mx, v); mn = fminf(mn, v); sm += v;
        }
        red[q * 192 + c] = mx; red[q * 192 + 64 + c] = mn; red[q * 192 + 128 + c] = sm;
        __syncthreads();
        if (tid < 64) {
            float MX = red[c], MN = red[64 + c], SM = red[128 + c];
            for (int qq = 1; qq < 4; qq++) {
                MX = fmaxf(MX, red[qq * 192 + c]);
                MN = fminf(MN, red[qq * 192 + 64 + c]);
                SM += red[qq * 192 + 128 + c];
            }
            float* o = g_gfeat + (size_t)g * 256;
            o[c]        = fmaxf(MX, 0.f);
            o[64 + c]   = fmaxf(MN, 0.f);
            o[128 + c]  = fmaxf(SM, 0.f);
            o[192 + c]  = fmaxf(SM * (1.f / 128.f), 0.f);
        }
    }
}

// ---------------- GI = permute(gfeat) @ wih0T + bih0; 8-row tiles, grid 256 ----------------
__global__ void __launch_bounds__(256) gi_gemm_kernel(
    const float* __restrict__ W, const float* __restrict__ bias, float* __restrict__ C)
{
    __shared__ float As[8][260];
    __shared__ float Ws[32][96];
    const int tid = threadIdx.x;
    const int bm = blockIdx.x * 8;
    const int r = tid >> 5, c = tid & 31;

    {
        const int rg = bm + r;
        const int t = rg >> 10, b = rg & 1023;
        const float* gf = g_gfeat + (size_t)(t * 1024 + (b >> 8)) * 256 + (b & 255);
        for (int k = c; k < 256; k += 32) As[r][k] = gf[(size_t)k << 10];
    }
    float a0 = 0.f, a1 = 0.f, a2 = 0.f;
    for (int kc = 0; kc < 8; kc++) {
        for (int i = tid; i < 3072; i += 256)
            (&Ws[0][0])[i] = W[kc * 3072 + i];
        __syncthreads();
#pragma unroll
        for (int k = 0; k < 32; k++) {
            const float av = As[r][kc * 32 + k];
            a0 = fmaf(av, Ws[k][c], a0);
            a1 = fmaf(av, Ws[k][c + 32], a1);
            a2 = fmaf(av, Ws[k][c + 64], a2);
        }
        __syncthreads();
    }
    float* o = C + (size_t)(bm + r) * 96;
    o[c] = a0 + bias[c];
    o[c + 32] = a1 + bias[c + 32];
    o[c + 64] = a2 + bias[c + 64];
}

// ---------------- fused GRU: both layers x both timesteps; warp = row ----------------
__global__ void __launch_bounds__(512) gru_all_kernel(
    const float* __restrict__ gi,     // [2][1024][96]
    const float* __restrict__ h1in,   // [2][1024][32]
    const float* __restrict__ wih1, const float* __restrict__ bih1,
    const float* __restrict__ whh0, const float* __restrict__ bhh0,
    const float* __restrict__ whh1, const float* __restrict__ bhh1)
{
    __shared__ float w0[96][33], w1[96][33], wi1[96][33];
    const int tid = threadIdx.x;
    const int wr = tid >> 5, u = tid & 31;
    const int row = blockIdx.x * 16 + wr;

    for (int i = tid; i < 3072; i += 512) {
        w0[i >> 5][i & 31] = whh0[i];
        w1[i >> 5][i & 31] = whh1[i];
        wi1[i >> 5][i & 31] = wih1[i];
    }
    __syncthreads();

    float h0 = h1in[row * 32 + u];
    float hv1 = h1in[32768 + row * 32 + u];
    const float b0r = bhh0[u], b0z = bhh0[32 + u], b0n = bhh0[64 + u];
    const float bi1r = bih1[u], bi1z = bih1[32 + u], bi1n = bih1[64 + u];
    const float b1r = bhh1[u], b1z = bhh1[32 + u], b1n = bhh1[64 + u];

#pragma unroll
    for (int t = 0; t < 2; t++) {
        const float* gr0 = gi + t * 98304 + (size_t)row * 96;
        float gr = gr0[u], gz = gr0[32 + u], gn = gr0[64 + u];
        float hr = b0r, hz = b0z, hn = b0n;
#pragma unroll
        for (int d = 0; d < 32; d++) {
            float hv = __shfl_sync(0xffffffffu, h0, d);
            hr = fmaf(hv, w0[u][d], hr);
            hz = fmaf(hv, w0[32 + u][d], hz);
            hn = fmaf(hv, w0[64 + u][d], hn);
        }
        float rr = 1.f / (1.f + expf(-(gr + hr)));
        float zz = 1.f / (1.f + expf(-(gz + hz)));
        float nn = tanhf(gn + rr * hn);
        h0 = (1.f - zz) * nn + zz * h0;

        float xr = bi1r, xz = bi1z, xn = bi1n;
        float yr = b1r, yz = b1z, yn = b1n;
#pragma unroll
        for (int d = 0; d < 32; d++) {
            float xv = __shfl_sync(0xffffffffu, h0, d);
            xr = fmaf(xv, wi1[u][d], xr);
            xz = fmaf(xv, wi1[32 + u][d], xz);
            xn = fmaf(xv, wi1[64 + u][d], xn);
            float hv = __shfl_sync(0xffffffffu, hv1, d);
            yr = fmaf(hv, w1[u][d], yr);
            yz = fmaf(hv, w1[32 + u][d], yz);
            yn = fmaf(hv, w1[64 + u][d], yn);
        }
        float r1 = 1.f / (1.f + expf(-(xr + yr)));
        float z1 = 1.f / (1.f + expf(-(xz + yz)));
        float n1 = tanhf(xn + r1 * yn);
        hv1 = (1.f - z1) * n1 + z1 * hv1;
        g_out1[t * 32768 + row * 32 + u] = hv1;
    }
    g_out0[32768 + row * 32 + u] = h0;   // hT of layer 0
}

// ---------------- final head + hT pack ----------------
__global__ void final_kernel(const float* __restrict__ nn4W, const float* __restrict__ nn4b,
                             float* __restrict__ out, int out_size)
{
    const int idx = blockIdx.x * 256 + threadIdx.x;
    if (idx >= out_size) return;
    if (idx < 2048) {
        const int t  = idx >> 10;
        const int ch = (idx >> 5) & 31;
        const int b0 = (idx & 31) * 32;
        float acc = nn4b[0];
#pragma unroll
        for (int c = 0; c < 32; c++) {
            const float v = g_out1[t * 32768 + (b0 + c) * 32 + ch];
            acc = fmaf(fmaxf(v, 0.f), nn4W[c], acc);
        }
        out[idx] = fmaxf(acc, 0.f);
    } else if (idx < 2048 + 65536) {
        const int j = idx - 2048;
        out[idx] = (j < 32768) ? g_out0[32768 + j] : g_out1[32768 + (j - 32768)];
    }
}

// ---------------- launch ----------------
extern "C" void kernel_launch(void* const* d_in, const int* in_sizes, int n_in,
                              void* d_out, int out_size)
{
    const float* x    = (const float*)d_in[0];
    const float* h1   = (const float*)d_in[2];
    const float* W1   = (const float*)d_in[3];
    const float* b1   = (const float*)d_in[4];
    const float* W2   = (const float*)d_in[5];
    const float* b2   = (const float*)d_in[6];
    const float* nn1W = (const float*)d_in[7];
    const float* nn1b = (const float*)d_in[8];
    const float* nn2W = (const float*)d_in[9];
    const float* nn2b = (const float*)d_in[10];
    const float* nn4W = (const float*)d_in[11];
    const float* nn4b = (const float*)d_in[12];
    const float* wih0 = (const float*)d_in[13];
    const float* whh0 = (const float*)d_in[14];
    const float* bih0 = (const float*)d_in[15];
    const float* bhh0 = (const float*)d_in[16];
    const float* wih1 = (const float*)d_in[17];
    const float* whh1 = (const float*)d_in[18];
    const float* bih1 = (const float*)d_in[19];
    const float* bhh1 = (const float*)d_in[20];
    float* out = (float*)d_out;

    float *gi, *wih0T;
    cudaGetSymbolAddress((void**)&gi,    g_gi);
    cudaGetSymbolAddress((void**)&wih0T, g_wih0T);

    cudaFuncSetAttribute(ec_kernel, cudaFuncAttributeMaxDynamicSharedMemorySize, EC_SMEM);
    cudaFuncSetAttribute(nn_kernel, cudaFuncAttributeMaxDynamicSharedMemorySize, NN_SMEM);

    prep_kernel<<<96, 256>>>(nn1W, nn1b, nn2W, W2, W1, wih0);
    ec_kernel<<<NG, 256, EC_SMEM>>>(x, b1, b2);
    nn_kernel<<<NG, 256, NN_SMEM>>>(nn2b);
    gi_gemm_kernel<<<256, 256>>>(wih0T, bih0, gi);
    gru_all_kernel<<<64, 512>>>(gi, h1, wih1, bih1, whh0, bhh0, whh1, bhh1);
    final_kernel<<<(out_size + 255) / 256, 256>>>(nn4W, nn4b, out, out_size);
}

// round 12
// speedup vs baseline: 2.7354x; 1.0307x over previous
#include <cuda_runtime.h>
#include <cuda_fp16.h>
#include <math.h>
#include <stdint.h>

#define NG 2048
#define NP 128

// ---------------- scratch (device globals) ----------------
__device__ __half g_hagghi[(size_t)NG * NP * 256];
__device__ __half g_hagglo[(size_t)NG * NP * 256];
__device__ float g_gfeat[NG * 256];
__device__ float g_gi[2 * 1024 * 96];
__device__ float g_out0[2 * 1024 * 32];
__device__ float g_out1[2 * 1024 * 32];
__device__ __half g_w1h[64 * 16],   g_w1l[64 * 16];     // W1^T padded k16
__device__ __half g_w2Th[128 * 64], g_w2Tl[128 * 64];   // edge W2^T
__device__ __half g_nn1Th[96 * 256], g_nn1Tl[96 * 256]; // folded nn1^T
__device__ __half g_nn2Th[64 * 96],  g_nn2Tl[64 * 96];  // nn2^T padded
__device__ float g_nn1bp[96];
__device__ float g_wih0T[256 * 96];

// ---------------- helpers ----------------
__device__ __forceinline__ void splith(float x, __half& h, __half& l) {
    h = __float2half_rn(x);
    l = __float2half_rn(x - __half2float(h));
}
__device__ __forceinline__ uint32_t packh(__half a, __half b) {
    __half2 p = __halves2half2(a, b);
    return *(uint32_t*)&p;
}
__device__ __forceinline__ void splitpack(float x0, float x1, uint32_t& hi, uint32_t& lo) {
    __half h0, l0, h1, l1;
    splith(x0, h0, l0); splith(x1, h1, l1);
    hi = packh(h0, h1); lo = packh(l0, l1);
}
__device__ __forceinline__ void mma16(float d[4], const uint32_t a[4], const uint32_t b[2]) {
    asm volatile(
        "mma.sync.aligned.m16n8k16.row.col.f32.f16.f16.f32 "
        "{%0,%1,%2,%3},{%4,%5,%6,%7},{%8,%9},{%0,%1,%2,%3};"
        : "+f"(d[0]), "+f"(d[1]), "+f"(d[2]), "+f"(d[3])
        : "r"(a[0]), "r"(a[1]), "r"(a[2]), "r"(a[3]), "r"(b[0]), "r"(b[1]));
}
__device__ __forceinline__ void mma3h(float d[4], const uint32_t ah[4], const uint32_t al[4],
                                      const uint32_t bh[2], const uint32_t bl[2]) {
    mma16(d, ah, bh); mma16(d, ah, bl); mma16(d, al, bh);
}
// ldmatrix x4 (A m16k16 frag, or B-pair load). stride in halves (16B-mult rows).
__device__ __forceinline__ void ldsm4(const __half* P, int strideH, int m0, int k0, int lid, uint32_t a[4]) {
    uint32_t addr = (uint32_t)__cvta_generic_to_shared(
        P + (size_t)(m0 + (lid & 15)) * strideH + k0 + ((lid >> 4) << 3));
    asm volatile("ldmatrix.sync.aligned.m8n8.x4.shared.b16 {%0,%1,%2,%3}, [%4];"
        : "=r"(a[0]), "=r"(a[1]), "=r"(a[2]), "=r"(a[3]) : "r"(addr));
}

// ---------------- weight prep: pre-split hi/lo half planes ----------------
__global__ void prep_kernel(const float* __restrict__ nn1W, const float* __restrict__ nn1b,
                            const float* __restrict__ nn2W, const float* __restrict__ W2,
                            const float* __restrict__ W1, const float* __restrict__ wih0)
{
    int idx = blockIdx.x * 256 + threadIdx.x;   // 96 blocks -> 24576
    __half h, l;
    if (idx < 64 * 16) {
        int n = idx >> 4, k = idx & 15;
        float v = (k < 10) ? W1[k * 64 + n] : 0.f;
        splith(v, h, l); g_w1h[idx] = h; g_w1l[idx] = l;
    }
    if (idx < 128 * 64) {
        int n = idx >> 6, k = idx & 63;
        splith(W2[k * 128 + n], h, l); g_w2Th[idx] = h; g_w2Tl[idx] = l;
    }
    if (idx < 96 * 256) {
        int n = idx >> 8, k = idx & 255;
        float v = 0.f;
        if (n < 94) {
            if (k < 128) v = nn1W[k * 94 + n];
            else { int kk = k - 128; v = 0.25f * nn1W[(128 + kk) * 94 + n] + nn1W[(256 + kk) * 94 + n]; }
        }
        splith(v, h, l); g_nn1Th[idx] = h; g_nn1Tl[idx] = l;
    }
    if (idx < 64 * 96) {
        int n = idx / 96, k = idx % 96;
        float v = (k < 94) ? nn2W[k * 64 + n] : 0.f;
        splith(v, h, l); g_nn2Th[idx] = h; g_nn2Tl[idx] = l;
    }
    if (idx < 96) g_nn1bp[idx] = (idx < 94) ? nn1b[idx] : 0.f;
    if (idx < 96 * 256) { int gg = idx >> 8, d = idx & 255; g_wih0T[d * 96 + gg] = wih0[idx]; }
}

// ================= EC kernel: KNN + EdgeConv, register-chained l1->l2 =================
// warp = 16-edge tile; tile t: nodes t*4..t*4+3; row r: node = t*4+(r&3), k = ((r>>3)<<1)|((r>>2)&1)
#define EC_XS    0        // 2560
#define EC_NBR   2560     // 2048
#define EC_W1H   4608     // [64][24] half = 3072
#define EC_W1L   7680     // 3072
#define EC_B1    10752    // 256
#define EC_B2    11008    // 512
#define EC_W2H   11520    // [128][72] half = 18432
#define EC_W2L   29952    // 18432
#define EC_SMEM  48384

__global__ void __launch_bounds__(256, 2) ec_kernel(
    const float* __restrict__ x, const float* __restrict__ b1, const float* __restrict__ b2)
{
    extern __shared__ __align__(16) char smem[];
    float* xs   = (float*)(smem + EC_XS);
    int*   nbr  = (int*)(smem + EC_NBR);
    __half* W1H = (__half*)(smem + EC_W1H);
    __half* W1L = (__half*)(smem + EC_W1L);
    float* b1s  = (float*)(smem + EC_B1);
    float* b2s  = (float*)(smem + EC_B2);
    __half* W2H = (__half*)(smem + EC_W2H);
    __half* W2L = (__half*)(smem + EC_W2L);

    const int tid = threadIdx.x, wid = tid >> 5, lid = tid & 31;
    const int qr = lid >> 2, qc = lid & 3;
    const int g = blockIdx.x;
    const size_t base = (size_t)g * NP;

    for (int i = tid; i < NP * 5; i += 256) xs[i] = x[base * 5 + i];
    for (int i = tid; i < 512; i += 256) {       // W1 planes -> stride 24 halves
        int n = i >> 3, kw = i & 7;
        ((uint32_t*)W1H)[n * 12 + kw] = ((const uint32_t*)g_w1h)[i];
        ((uint32_t*)W1L)[n * 12 + kw] = ((const uint32_t*)g_w1l)[i];
    }
    if (tid < 64) b1s[tid] = b1[tid];
    if (tid >= 64 && tid < 192) b2s[tid - 64] = b2[tid - 64];
    for (int i = tid; i < 4096; i += 256) {      // W2 planes -> stride 72 halves
        int n = i >> 5, kw = i & 31;
        ((uint32_t*)W2H)[n * 36 + kw] = ((const uint32_t*)g_w2Th)[i];
        ((uint32_t*)W2L)[n * 36 + kw] = ((const uint32_t*)g_w2Tl)[i];
    }
    __syncthreads();

    // ---- KNN (thread = node), branchless, stable ties
    if (tid < NP) {
        const float px = xs[tid * 5 + 0], py = xs[tid * 5 + 1], pz = xs[tid * 5 + 2];
        float d0 = 1e30f, d1 = 1e30f, d2v = 1e30f, d3 = 1e30f;
        int i0 = 0, i1 = 0, i2 = 0, i3 = 0;
#pragma unroll 4
        for (int j = 0; j < NP; j++) {
            float dx = xs[j * 5 + 0] - px, dy = xs[j * 5 + 1] - py, dz = xs[j * 5 + 2] - pz;
            float dd = dx * dx + dy * dy + dz * dz;
            dd = (j == tid) ? 1e30f : dd;
            bool c0 = dd < d0, c1 = dd < d1, c2 = dd < d2v, c3 = dd < d3;
            i3 = c2 ? i2 : (c3 ? j : i3);  d3  = c2 ? d2v : (c3 ? dd : d3);
            i2 = c1 ? i1 : (c2 ? j : i2);  d2v = c1 ? d1  : (c2 ? dd : d2v);
            i1 = c0 ? i0 : (c1 ? j : i1);  d1  = c0 ? d0  : (c1 ? dd : d1);
            i0 = c0 ? j : i0;              d0  = c0 ? dd  : d0;
        }
        nbr[tid * 4 + 0] = i0; nbr[tid * 4 + 1] = i1; nbr[tid * 4 + 2] = i2; nbr[tid * 4 + 3] = i3;
    }
    __syncthreads();

    // ---- main loop: warp-independent 16-edge tiles, NO block syncs
    for (int it = 0; it < 4; it++) {
        const int tile = it * 8 + wid;
        const int node = tile * 4 + (qr & 3);
        const int kb = (qr >> 2) & 1;            // row qr: k=kb; row qr+8: k=kb+2
        const int j0 = nbr[node * 4 + kb];
        const int j1 = nbr[node * 4 + kb + 2];

        // edge features in registers -> l1 A-frag
        uint32_t a1h[4], a1l[4];
        {
            const int d0 = 2 * qc, d2 = 8 + 2 * qc;
            float f0, f1, f2, f3, f4, f5, f6, f7;
            if (d0 < 5) { f0 = xs[node * 5 + d0]; f2 = f0; }
            else        { f0 = xs[j0 * 5 + d0 - 5] - xs[node * 5 + d0 - 5];
                          f2 = xs[j1 * 5 + d0 - 5] - xs[node * 5 + d0 - 5]; }
            if (d0 + 1 < 5) { f1 = xs[node * 5 + d0 + 1]; f3 = f1; }
            else            { f1 = xs[j0 * 5 + d0 - 4] - xs[node * 5 + d0 - 4];
                              f3 = xs[j1 * 5 + d0 - 4] - xs[node * 5 + d0 - 4]; }
            if (d2 < 10) {   // qc==0: dims 8,9 -> x_j - x_i at 3,4
                f4 = xs[j0 * 5 + 3] - xs[node * 5 + 3];
                f5 = xs[j0 * 5 + 4] - xs[node * 5 + 4];
                f6 = xs[j1 * 5 + 3] - xs[node * 5 + 3];
                f7 = xs[j1 * 5 + 4] - xs[node * 5 + 4];
            } else { f4 = 0.f; f5 = 0.f; f6 = 0.f; f7 = 0.f; }
            splitpack(f0, f1, a1h[0], a1l[0]);
            splitpack(f2, f3, a1h[1], a1l[1]);
            splitpack(f4, f5, a1h[2], a1l[2]);
            splitpack(f6, f7, a1h[3], a1l[3]);
        }

        // layer-1: 8 nt (64 cols), K=16
        float acc1[8][4];
#pragma unroll
        for (int j = 0; j < 8; j++) { acc1[j][0]=0.f; acc1[j][1]=0.f; acc1[j][2]=0.f; acc1[j][3]=0.f; }
#pragma unroll
        for (int jp = 0; jp < 4; jp++) {
            uint32_t bh4[4], bl4[4];
            ldsm4(W1H, 24, jp * 16, 0, lid, bh4);
            ldsm4(W1L, 24, jp * 16, 0, lid, bl4);
            uint32_t b0h[2] = {bh4[0], bh4[2]}, b1h[2] = {bh4[1], bh4[3]};
            uint32_t b0l[2] = {bl4[0], bl4[2]}, b1l[2] = {bl4[1], bl4[3]};
            mma3h(acc1[jp * 2],     a1h, a1l, b0h, b0l);
            mma3h(acc1[jp * 2 + 1], a1h, a1l, b1h, b1l);
        }

        // layer-2: A-frags straight from acc1 (bias+relu+split in regs), 16 nt, K=64
        float acc2[16][4];
#pragma unroll
        for (int j = 0; j < 16; j++) { acc2[j][0]=0.f; acc2[j][1]=0.f; acc2[j][2]=0.f; acc2[j][3]=0.f; }
#pragma unroll
        for (int ks = 0; ks < 4; ks++) {
            uint32_t a2h[4], a2l[4];
            {
                const int c0 = (2 * ks) * 8 + 2 * qc;
                const int c2 = (2 * ks + 1) * 8 + 2 * qc;
                float v0 = fmaxf(acc1[2 * ks][0] + b1s[c0], 0.f);
                float v1 = fmaxf(acc1[2 * ks][1] + b1s[c0 + 1], 0.f);
                float v2 = fmaxf(acc1[2 * ks][2] + b1s[c0], 0.f);
                float v3 = fmaxf(acc1[2 * ks][3] + b1s[c0 + 1], 0.f);
                float v4 = fmaxf(acc1[2 * ks + 1][0] + b1s[c2], 0.f);
                float v5 = fmaxf(acc1[2 * ks + 1][1] + b1s[c2 + 1], 0.f);
                float v6 = fmaxf(acc1[2 * ks + 1][2] + b1s[c2], 0.f);
                float v7 = fmaxf(acc1[2 * ks + 1][3] + b1s[c2 + 1], 0.f);
                splitpack(v0, v1, a2h[0], a2l[0]);
                splitpack(v2, v3, a2h[1], a2l[1]);
                splitpack(v4, v5, a2h[2], a2l[2]);
                splitpack(v6, v7, a2h[3], a2l[3]);
            }
#pragma unroll
            for (int jp = 0; jp < 8; jp++) {
                uint32_t bh4[4], bl4[4];
                ldsm4(W2H, 72, jp * 16, ks * 16, lid, bh4);
                ldsm4(W2L, 72, jp * 16, ks * 16, lid, bl4);
                uint32_t b0h[2] = {bh4[0], bh4[2]}, b1h[2] = {bh4[1], bh4[3]};
                uint32_t b0l[2] = {bl4[0], bl4[2]}, b1l[2] = {bl4[1], bl4[3]};
                mma3h(acc2[jp * 2],     a2h, a2l, b0h, b0l);
                mma3h(acc2[jp * 2 + 1], a2h, a2l, b1h, b1l);
            }
        }

        // epilogue: +b2, relu; in-thread combine k={kb,kb+2}; XOR-16 combines kb<->kb^1
        {
            uint32_t* Ghh = (uint32_t*)g_hagghi + (base + node) * 128;
            uint32_t* Ghl = (uint32_t*)g_hagglo + (base + node) * 128;
#pragma unroll
            for (int j = 0; j < 16; j++) {
                const int col = j * 8 + 2 * qc;
                float v0 = fmaxf(acc2[j][0] + b2s[col], 0.f);
                float v1 = fmaxf(acc2[j][1] + b2s[col + 1], 0.f);
                float v2 = fmaxf(acc2[j][2] + b2s[col], 0.f);
                float v3 = fmaxf(acc2[j][3] + b2s[col + 1], 0.f);
                float mx0 = fmaxf(v0, v2), mx1 = fmaxf(v1, v3);
                float sm0 = v0 + v2,       sm1 = v1 + v3;
                mx0 = fmaxf(mx0, __shfl_xor_sync(0xffffffffu, mx0, 16));
                mx1 = fmaxf(mx1, __shfl_xor_sync(0xffffffffu, mx1, 16));
                sm0 += __shfl_xor_sync(0xffffffffu, sm0, 16);
                sm1 += __shfl_xor_sync(0xffffffffu, sm1, 16);
                // writers: kb=0 (qr<4) write nt 0..7, kb=1 (qr>=4) write nt 8..15
                if ((qr < 4) == (j < 8)) {
                    uint32_t h, l;
                    splitpack(mx0, mx1, h, l); Ghh[col >> 1] = h;        Ghl[col >> 1] = l;
                    splitpack(sm0, sm1, h, l); Ghh[64 + (col >> 1)] = h; Ghl[64 + (col >> 1)] = l;
                }
            }
        }
    }
}

// ================= NN kernel: nn1 + nn2 + segreduce (block = graph) =================
#define NN_ASH  0         // A chunk hi [128][40] half = 10240
#define NN_ASL  10240     // 10240
#define NN_B1H  20480     // [96][40] half = 7680
#define NN_B1L  28160     // 7680
#define NN_B2H  0         // overlay after nn1: [64][104] half = 13312
#define NN_B2L  13312     // 13312
#define NN_H2H  35840     // [128][104] half = 26624
#define NN_H2L  62464     // 26624  (h2 fp32 [128][68] overlays H2H after nn2)
#define NN_RED  89088     // 3072
#define NN_B1V  92160     // 384
#define NN_B2V  92544     // 256
#define NN_SMEM 92800

__global__ void __launch_bounds__(256, 2) nn_kernel(const float* __restrict__ nn2b)
{
    extern __shared__ __align__(16) char smem[];
    __half* AsH = (__half*)(smem + NN_ASH);
    __half* AsL = (__half*)(smem + NN_ASL);
    __half* B1H = (__half*)(smem + NN_B1H);
    __half* B1L = (__half*)(smem + NN_B1L);
    __half* B2H = (__half*)(smem + NN_B2H);
    __half* B2L = (__half*)(smem + NN_B2L);
    __half* H2H = (__half*)(smem + NN_H2H);
    __half* H2L = (__half*)(smem + NN_H2L);
    float* red  = (float*)(smem + NN_RED);
    float* b1v  = (float*)(smem + NN_B1V);
    float* b2v  = (float*)(smem + NN_B2V);

    const int tid = threadIdx.x, wid = tid >> 5, lid = tid & 31;
    const int rw = wid >> 1, nh = wid & 1;
    const int qr = lid >> 2, qc = lid & 3;
    const int g = blockIdx.x;
    const __half* Ah = g_hagghi + (size_t)g * NP * 256;
    const __half* Al = g_hagglo + (size_t)g * NP * 256;

    if (tid < 96) b1v[tid] = g_nn1bp[tid];
    if (tid >= 96 && tid < 160) b2v[tid - 96] = nn2b[tid - 96];

    // ---- nn1: [128][256] @ [256][96]; A chunk + B1 chunk staged in smem per kc
    float acc1[2][6][4];
#pragma unroll
    for (int rt = 0; rt < 2; rt++)
#pragma unroll
        for (int j = 0; j < 6; j++) { acc1[rt][j][0]=0.f; acc1[rt][j][1]=0.f; acc1[rt][j][2]=0.f; acc1[rt][j][3]=0.f; }
    for (int kc = 0; kc < 8; kc++) {
        for (int i = tid; i < 512; i += 256) {    // A chunk [128][32] halves, coalesced 16B
            int r = i >> 2, q = i & 3;
            *(uint4*)(AsH + r * 40 + q * 8) = *(const uint4*)(Ah + r * 256 + kc * 32 + q * 8);
            *(uint4*)(AsL + r * 40 + q * 8) = *(const uint4*)(Al + r * 256 + kc * 32 + q * 8);
        }
        for (int i = tid; i < 1536; i += 256) {   // B1 chunk planes [96][16] words -> stride 20
            int n = i >> 4, kw = i & 15;
            ((uint32_t*)B1H)[n * 20 + kw] = ((const uint32_t*)g_nn1Th)[n * 128 + kc * 16 + kw];
            ((uint32_t*)B1L)[n * 20 + kw] = ((const uint32_t*)g_nn1Tl)[n * 128 + kc * 16 + kw];
        }
        __syncthreads();
#pragma unroll
        for (int ks = 0; ks < 2; ks++) {
            uint32_t ah[2][4], al[2][4];
            ldsm4(AsH, 40, rw * 32,      ks * 16, lid, ah[0]); ldsm4(AsL, 40, rw * 32,      ks * 16, lid, al[0]);
            ldsm4(AsH, 40, rw * 32 + 16, ks * 16, lid, ah[1]); ldsm4(AsL, 40, rw * 32 + 16, ks * 16, lid, al[1]);
#pragma unroll
            for (int jp = 0; jp < 3; jp++) {
                uint32_t bh4[4], bl4[4];
                ldsm4(B1H, 40, (nh * 6 + jp * 2) * 8, ks * 16, lid, bh4);
                ldsm4(B1L, 40, (nh * 6 + jp * 2) * 8, ks * 16, lid, bl4);
                uint32_t b0h[2] = {bh4[0], bh4[2]}, b1h[2] = {bh4[1], bh4[3]};
                uint32_t b0l[2] = {bl4[0], bl4[2]}, b1l[2] = {bl4[1], bl4[3]};
                mma3h(acc1[0][jp * 2],     ah[0], al[0], b0h, b0l);
                mma3h(acc1[1][jp * 2],     ah[1], al[1], b0h, b0l);
                mma3h(acc1[0][jp * 2 + 1], ah[0], al[0], b1h, b1l);
                mma3h(acc1[1][jp * 2 + 1], ah[1], al[1], b1h, b1l);
            }
        }
        __syncthreads();
    }
    // epilogue1: H2 hi/lo planes = split(relu(acc1 + b1v)); stage B2 planes (overlay A/B1)
    {
#pragma unroll
        for (int rt = 0; rt < 2; rt++) {
            int r0 = rw * 32 + rt * 16 + qr, r1 = r0 + 8;
#pragma unroll
            for (int j = 0; j < 6; j++) {
                int col = (nh * 6 + j) * 8 + 2 * qc;
                float v0 = fmaxf(acc1[rt][j][0] + b1v[col], 0.f), v1 = fmaxf(acc1[rt][j][1] + b1v[col + 1], 0.f);
                float v2 = fmaxf(acc1[rt][j][2] + b1v[col], 0.f), v3 = fmaxf(acc1[rt][j][3] + b1v[col + 1], 0.f);
                uint32_t h, l;
                splitpack(v0, v1, h, l);
                ((uint32_t*)H2H)[r0 * 52 + (col >> 1)] = h; ((uint32_t*)H2L)[r0 * 52 + (col >> 1)] = l;
                splitpack(v2, v3, h, l);
                ((uint32_t*)H2H)[r1 * 52 + (col >> 1)] = h; ((uint32_t*)H2L)[r1 * 52 + (col >> 1)] = l;
            }
        }
        for (int i = tid; i < 3072; i += 256) {   // B2 planes [64][48] words -> stride 52
            int n = i / 48, kw = i % 48;
            ((uint32_t*)B2H)[n * 52 + kw] = ((const uint32_t*)g_nn2Th)[n * 48 + kw];
            ((uint32_t*)B2L)[n * 52 + kw] = ((const uint32_t*)g_nn2Tl)[n * 48 + kw];
        }
    }
    __syncthreads();

    // ---- nn2: [128][96] @ [96][64], K=96 (6 k16 steps), 4 nt (2 pairs)
    float acc2[2][4][4];
#pragma unroll
    for (int rt = 0; rt < 2; rt++)
#pragma unroll
        for (int j = 0; j < 4; j++) { acc2[rt][j][0]=0.f; acc2[rt][j][1]=0.f; acc2[rt][j][2]=0.f; acc2[rt][j][3]=0.f; }
#pragma unroll
    for (int ks = 0; ks < 6; ks++) {
        uint32_t ah[2][4], al[2][4];
        ldsm4(H2H, 104, rw * 32,      ks * 16, lid, ah[0]); ldsm4(H2L, 104, rw * 32,      ks * 16, lid, al[0]);
        ldsm4(H2H, 104, rw * 32 + 16, ks * 16, lid, ah[1]); ldsm4(H2L, 104, rw * 32 + 16, ks * 16, lid, al[1]);
#pragma unroll
        for (int jp = 0; jp < 2; jp++) {
            uint32_t bh4[4], bl4[4];
            ldsm4(B2H, 104, (nh * 4 + jp * 2) * 8, ks * 16, lid, bh4);
            ldsm4(B2L, 104, (nh * 4 + jp * 2) * 8, ks * 16, lid, bl4);
            uint32_t b0h[2] = {bh4[0], bh4[2]}, b1h[2] = {bh4[1], bh4[3]};
            uint32_t b0l[2] = {bl4[0], bl4[2]}, b1l[2] = {bl4[1], bl4[3]};
            mma3h(acc2[0][jp * 2],     ah[0], al[0], b0h, b0l);
            mma3h(acc2[1][jp * 2],     ah[1], al[1], b0h, b0l);
            mma3h(acc2[0][jp * 2 + 1], ah[0], al[0], b1h, b1l);
            mma3h(acc2[1][jp * 2 + 1], ah[1], al[1], b1h, b1l);
        }
    }
    __syncthreads();    // all warps done reading H2/B2 before fp32 overlay
    float* h2 = (float*)(smem + NN_H2H);          // [128][68] fp32
    {
#pragma unroll
        for (int rt = 0; rt < 2; rt++) {
            int r0 = rw * 32 + rt * 16 + qr, r1 = r0 + 8;
#pragma unroll
            for (int j = 0; j < 4; j++) {
                int col = (nh * 4 + j) * 8 + 2 * qc;
                float2 u0 = { acc2[rt][j][0] + b2v[col], acc2[rt][j][1] + b2v[col + 1] };
                float2 u1 = { acc2[rt][j][2] + b2v[col], acc2[rt][j][3] + b2v[col + 1] };
                *(float2*)&h2[r0 * 68 + col] = u0;
                *(float2*)&h2[r1 * 68 + col] = u1;
            }
        }
    }
    __syncthreads();

    // ---- segment max/min/sum/mean + relu -> g_gfeat
    {
        int c = tid & 63, q = tid >> 6;
        float mx = -1e30f, mn = 1e30f, sm = 0.f;
        for (int r = q * 32; r < q * 32 + 32; r++) {
            float v = h2[r * 68 + c];
            mx = fmaxf(mx, v); mn = fminf(mn, v); sm += v;
        }
        red[q * 192 + c] = mx; red[q * 192 + 64 + c] = mn; red[q * 192 + 128 + c] = sm;
        __syncthreads();
        if (tid < 64) {
            float MX = red[c], MN = red[64 + c], SM = red[128 + c];
            for (int qq = 1; qq < 4; qq++) {
                MX = fmaxf(MX, red[qq * 192 + c]);
                MN = fminf(MN, red[qq * 192 + 64 + c]);
                SM += red[qq * 192 + 128 + c];
            }
            float* o = g_gfeat + (size_t)g * 256;
            o[c]        = fmaxf(MX, 0.f);
            o[64 + c]   = fmaxf(MN, 0.f);
            o[128 + c]  = fmaxf(SM, 0.f);
            o[192 + c]  = fmaxf(SM * (1.f / 128.f), 0.f);
        }
    }
}

// ---------------- GI = permute(gfeat) @ wih0T + bih0; 8-row tiles, grid 256 ----------------
__global__ void __launch_bounds__(256) gi_gemm_kernel(
    const float* __restrict__ W, const float* __restrict__ bias, float* __restrict__ C)
{
    __shared__ float As[8][260];
    __shared__ float Ws[32][96];
    const int tid = threadIdx.x;
    const int bm = blockIdx.x * 8;
    const int r = tid >> 5, c = tid & 31;

    {
        const int rg = bm + r;
        const int t = rg >> 10, b = rg & 1023;
        const float* gf = g_gfeat + (size_t)(t * 1024 + (b >> 8)) * 256 + (b & 255);
        for (int k = c; k < 256; k += 32) As[r][k] = gf[(size_t)k << 10];
    }
    float a0 = 0.f, a1 = 0.f, a2 = 0.f;
    for (int kc = 0; kc < 8; kc++) {
        for (int i = tid; i < 3072; i += 256)
            (&Ws[0][0])[i] = W[kc * 3072 + i];
        __syncthreads();
#pragma unroll
        for (int k = 0; k < 32; k++) {
            const float av = As[r][kc * 32 + k];
            a0 = fmaf(av, Ws[k][c], a0);
            a1 = fmaf(av, Ws[k][c + 32], a1);
            a2 = fmaf(av, Ws[k][c + 64], a2);
        }
        __syncthreads();
    }
    float* o = C + (size_t)(bm + r) * 96;
    o[c] = a0 + bias[c];
    o[c + 32] = a1 + bias[c + 32];
    o[c + 64] = a2 + bias[c + 64];
}

// ---------------- fused GRU: both layers x both timesteps; warp = row ----------------
__global__ void __launch_bounds__(512) gru_all_kernel(
    const float* __restrict__ gi,     // [2][1024][96]
    const float* __restrict__ h1in,   // [2][1024][32]
    const float* __restrict__ wih1, const float* __restrict__ bih1,
    const float* __restrict__ whh0, const float* __restrict__ bhh0,
    const float* __restrict__ whh1, const float* __restrict__ bhh1)
{
    __shared__ float w0[96][33], w1[96][33], wi1[96][33];
    const int tid = threadIdx.x;
    const int wr = tid >> 5, u = tid & 31;
    const int row = blockIdx.x * 16 + wr;

    for (int i = tid; i < 3072; i += 512) {
        w0[i >> 5][i & 31] = whh0[i];
        w1[i >> 5][i & 31] = whh1[i];
        wi1[i >> 5][i & 31] = wih1[i];
    }
    __syncthreads();

    float h0 = h1in[row * 32 + u];
    float hv1 = h1in[32768 + row * 32 + u];
    const float b0r = bhh0[u], b0z = bhh0[32 + u], b0n = bhh0[64 + u];
    const float bi1r = bih1[u], bi1z = bih1[32 + u], bi1n = bih1[64 + u];
    const float b1r = bhh1[u], b1z = bhh1[32 + u], b1n = bhh1[64 + u];

#pragma unroll
    for (int t = 0; t < 2; t++) {
        const float* gr0 = gi + t * 98304 + (size_t)row * 96;
        float gr = gr0[u], gz = gr0[32 + u], gn = gr0[64 + u];
        float hr = b0r, hz = b0z, hn = b0n;
#pragma unroll
        for (int d = 0; d < 32; d++) {
            float hv = __shfl_sync(0xffffffffu, h0, d);
            hr = fmaf(hv, w0[u][d], hr);
            hz = fmaf(hv, w0[32 + u][d], hz);
            hn = fmaf(hv, w0[64 + u][d], hn);
        }
        float rr = 1.f / (1.f + expf(-(gr + hr)));
        float zz = 1.f / (1.f + expf(-(gz + hz)));
        float nn = tanhf(gn + rr * hn);
        h0 = (1.f - zz) * nn + zz * h0;

        float xr = bi1r, xz = bi1z, xn = bi1n;
        float yr = b1r, yz = b1z, yn = b1n;
#pragma unroll
        for (int d = 0; d < 32; d++) {
            float xv = __shfl_sync(0xffffffffu, h0, d);
            xr = fmaf(xv, wi1[u][d], xr);
            xz = fmaf(xv, wi1[32 + u][d], xz);
            xn = fmaf(xv, wi1[64 + u][d], xn);
            float hv = __shfl_sync(0xffffffffu, hv1, d);
            yr = fmaf(hv, w1[u][d], yr);
            yz = fmaf(hv, w1[32 + u][d], yz);
            yn = fmaf(hv, w1[64 + u][d], yn);
        }
        float r1 = 1.f / (1.f + expf(-(xr + yr)));
        float z1 = 1.f / (1.f + expf(-(xz + yz)));
        float n1 = tanhf(xn + r1 * yn);
        hv1 = (1.f - z1) * n1 + z1 * hv1;
        g_out1[t * 32768 + row * 32 + u] = hv1;
    }
    g_out0[32768 + row * 32 + u] = h0;   // hT of layer 0
}

// ---------------- final head + hT pack ----------------
__global__ void final_kernel(const float* __restrict__ nn4W, const float* __restrict__ nn4b,
                             float* __restrict__ out, int out_size)
{
    const int idx = blockIdx.x * 256 + threadIdx.x;
    if (idx >= out_size) return;
    if (idx < 2048) {
        const int t  = idx >> 10;
        const int ch = (idx >> 5) & 31;
        const int b0 = (idx & 31) * 32;
        float acc = nn4b[0];
#pragma unroll
        for (int c = 0; c < 32; c++) {
            const float v = g_out1[t * 32768 + (b0 + c) * 32 + ch];
            acc = fmaf(fmaxf(v, 0.f), nn4W[c], acc);
        }
        out[idx] = fmaxf(acc, 0.f);
    } else if (idx < 2048 + 65536) {
        const int j = idx - 2048;
        out[idx] = (j < 32768) ? g_out0[32768 + j] : g_out1[32768 + (j - 32768)];
    }
}

// ---------------- launch ----------------
extern "C" void kernel_launch(void* const* d_in, const int* in_sizes, int n_in,
                              void* d_out, int out_size)
{
    const float* x    = (const float*)d_in[0];
    const float* h1   = (const float*)d_in[2];
    const float* W1   = (const float*)d_in[3];
    const float* b1   = (const float*)d_in[4];
    const float* W2   = (const float*)d_in[5];
    const float* b2   = (const float*)d_in[6];
    const float* nn1W = (const float*)d_in[7];
    const float* nn1b = (const float*)d_in[8];
    const float* nn2W = (const float*)d_in[9];
    const float* nn2b = (const float*)d_in[10];
    const float* nn4W = (const float*)d_in[11];
    const float* nn4b = (const float*)d_in[12];
    const float* wih0 = (const float*)d_in[13];
    const float* whh0 = (const float*)d_in[14];
    const float* bih0 = (const float*)d_in[15];
    const float* bhh0 = (const float*)d_in[16];
    const float* wih1 = (const float*)d_in[17];
    const float* whh1 = (const float*)d_in[18];
    const float* bih1 = (const float*)d_in[19];
    const float* bhh1 = (const float*)d_in[20];
    float* out = (float*)d_out;

    float *gi, *wih0T;
    cudaGetSymbolAddress((void**)&gi,    g_gi);
    cudaGetSymbolAddress((void**)&wih0T, g_wih0T);

    cudaFuncSetAttribute(ec_kernel, cudaFuncAttributeMaxDynamicSharedMemorySize, EC_SMEM);
    cudaFuncSetAttribute(nn_kernel, cudaFuncAttributeMaxDynamicSharedMemorySize, NN_SMEM);

    prep_kernel<<<96, 256>>>(nn1W, nn1b, nn2W, W2, W1, wih0);
    ec_kernel<<<NG, 256, EC_SMEM>>>(x, b1, b2);
    nn_kernel<<<NG, 256, NN_SMEM>>>(nn2b);
    gi_gemm_kernel<<<256, 256>>>(wih0T, bih0, gi);
    gru_all_kernel<<<64, 512>>>(gi, h1, wih1, bih1, whh0, bhh0, whh1, bhh1);
    final_kernel<<<(out_size + 255) / 256, 256>>>(nn4W, nn4b, out, out_size);
}

// round 13
// speedup vs baseline: 3.1283x; 1.1436x over previous
#include <cuda_runtime.h>
#include <cuda_fp16.h>
#include <math.h>
#include <stdint.h>

#define NG 2048
#define NP 128

// ---------------- scratch (device globals) ----------------
__device__ __half g_hagg[(size_t)NG * NP * 256];    // single fp16 plane
__device__ float g_xin[2 * 1024 * 256];
__device__ float g_gi[2 * 1024 * 96];
__device__ float g_out0[2 * 1024 * 32];
__device__ float g_out1[2 * 1024 * 32];
__device__ __half g_w1h[64 * 16],   g_w1l[64 * 16];     // W1^T padded k16
__device__ __half g_w2Th[128 * 64], g_w2Tl[128 * 64];   // edge W2^T
__device__ __half g_nn1Th[96 * 256], g_nn1Tl[96 * 256]; // folded nn1^T
__device__ __half g_nn2Th[64 * 96],  g_nn2Tl[64 * 96];  // nn2^T padded
__device__ float g_nn1bp[96];
__device__ float g_wih0T[256 * 96];

// ---------------- helpers ----------------
__device__ __forceinline__ void splith(float x, __half& h, __half& l) {
    h = __float2half_rn(x);
    l = __float2half_rn(x - __half2float(h));
}
__device__ __forceinline__ uint32_t packh(__half a, __half b) {
    __half2 p = __halves2half2(a, b);
    return *(uint32_t*)&p;
}
__device__ __forceinline__ void splitpack(float x0, float x1, uint32_t& hi, uint32_t& lo) {
    __half h0, l0, h1, l1;
    splith(x0, h0, l0); splith(x1, h1, l1);
    hi = packh(h0, h1); lo = packh(l0, l1);
}
__device__ __forceinline__ uint32_t packf(float x0, float x1) {
    return packh(__float2half_rn(x0), __float2half_rn(x1));
}
__device__ __forceinline__ void mma16(float d[4], const uint32_t a[4], const uint32_t b[2]) {
    asm volatile(
        "mma.sync.aligned.m16n8k16.row.col.f32.f16.f16.f32 "
        "{%0,%1,%2,%3},{%4,%5,%6,%7},{%8,%9},{%0,%1,%2,%3};"
        : "+f"(d[0]), "+f"(d[1]), "+f"(d[2]), "+f"(d[3])
        : "r"(a[0]), "r"(a[1]), "r"(a[2]), "r"(a[3]), "r"(b[0]), "r"(b[1]));
}
__device__ __forceinline__ void mma3h(float d[4], const uint32_t ah[4], const uint32_t al[4],
                                      const uint32_t bh[2], const uint32_t bl[2]) {
    mma16(d, ah, bh); mma16(d, ah, bl); mma16(d, al, bh);
}
__device__ __forceinline__ void mma2h(float d[4], const uint32_t ah[4],
                                      const uint32_t bh[2], const uint32_t bl[2]) {
    mma16(d, ah, bh); mma16(d, ah, bl);
}
// ldmatrix x4 (A m16k16 frag, or B-pair load). stride in halves (16B-mult rows).
__device__ __forceinline__ void ldsm4(const __half* P, int strideH, int m0, int k0, int lid, uint32_t a[4]) {
    uint32_t addr = (uint32_t)__cvta_generic_to_shared(
        P + (size_t)(m0 + (lid & 15)) * strideH + k0 + ((lid >> 4) << 3));
    asm volatile("ldmatrix.sync.aligned.m8n8.x4.shared.b16 {%0,%1,%2,%3}, [%4];"
        : "=r"(a[0]), "=r"(a[1]), "=r"(a[2]), "=r"(a[3]) : "r"(addr));
}

// ---------------- weight prep: pre-split hi/lo half planes ----------------
__global__ void prep_kernel(const float* __restrict__ nn1W, const float* __restrict__ nn1b,
                            const float* __restrict__ nn2W, const float* __restrict__ W2,
                            const float* __restrict__ W1, const float* __restrict__ wih0)
{
    int idx = blockIdx.x * 256 + threadIdx.x;   // 96 blocks -> 24576
    __half h, l;
    if (idx < 64 * 16) {
        int n = idx >> 4, k = idx & 15;
        float v = (k < 10) ? W1[k * 64 + n] : 0.f;
        splith(v, h, l); g_w1h[idx] = h; g_w1l[idx] = l;
    }
    if (idx < 128 * 64) {
        int n = idx >> 6, k = idx & 63;
        splith(W2[k * 128 + n], h, l); g_w2Th[idx] = h; g_w2Tl[idx] = l;
    }
    if (idx < 96 * 256) {
        int n = idx >> 8, k = idx & 255;
        float v = 0.f;
        if (n < 94) {
            if (k < 128) v = nn1W[k * 94 + n];
            else { int kk = k - 128; v = 0.25f * nn1W[(128 + kk) * 94 + n] + nn1W[(256 + kk) * 94 + n]; }
        }
        splith(v, h, l); g_nn1Th[idx] = h; g_nn1Tl[idx] = l;
    }
    if (idx < 64 * 96) {
        int n = idx / 96, k = idx % 96;
        float v = (k < 94) ? nn2W[k * 64 + n] : 0.f;
        splith(v, h, l); g_nn2Th[idx] = h; g_nn2Tl[idx] = l;
    }
    if (idx < 96) g_nn1bp[idx] = (idx < 94) ? nn1b[idx] : 0.f;
    if (idx < 96 * 256) { int gg = idx >> 8, d = idx & 255; g_wih0T[d * 96 + gg] = wih0[idx]; }
}

// ================= EC kernel: KNN + EdgeConv, register-chained l1->l2 =================
#define EC_XS    0        // 2560
#define EC_NBR   2560     // 2048
#define EC_W1H   4608     // [64][24] half = 3072
#define EC_W1L   7680     // 3072
#define EC_B1    10752    // 256
#define EC_B2    11008    // 512
#define EC_W2H   11520    // [128][72] half = 18432
#define EC_W2L   29952    // 18432
#define EC_SMEM  48384

__global__ void __launch_bounds__(256, 2) ec_kernel(
    const float* __restrict__ x, const float* __restrict__ b1, const float* __restrict__ b2)
{
    extern __shared__ __align__(16) char smem[];
    float* xs   = (float*)(smem + EC_XS);
    int*   nbr  = (int*)(smem + EC_NBR);
    __half* W1H = (__half*)(smem + EC_W1H);
    __half* W1L = (__half*)(smem + EC_W1L);
    float* b1s  = (float*)(smem + EC_B1);
    float* b2s  = (float*)(smem + EC_B2);
    __half* W2H = (__half*)(smem + EC_W2H);
    __half* W2L = (__half*)(smem + EC_W2L);

    const int tid = threadIdx.x, wid = tid >> 5, lid = tid & 31;
    const int qr = lid >> 2, qc = lid & 3;
    const int g = blockIdx.x;
    const size_t base = (size_t)g * NP;

    for (int i = tid; i < NP * 5; i += 256) xs[i] = x[base * 5 + i];
    for (int i = tid; i < 512; i += 256) {
        int n = i >> 3, kw = i & 7;
        ((uint32_t*)W1H)[n * 12 + kw] = ((const uint32_t*)g_w1h)[i];
        ((uint32_t*)W1L)[n * 12 + kw] = ((const uint32_t*)g_w1l)[i];
    }
    if (tid < 64) b1s[tid] = b1[tid];
    if (tid >= 64 && tid < 192) b2s[tid - 64] = b2[tid - 64];
    for (int i = tid; i < 4096; i += 256) {
        int n = i >> 5, kw = i & 31;
        ((uint32_t*)W2H)[n * 36 + kw] = ((const uint32_t*)g_w2Th)[i];
        ((uint32_t*)W2L)[n * 36 + kw] = ((const uint32_t*)g_w2Tl)[i];
    }
    __syncthreads();

    // ---- KNN (thread = node), branchless, stable ties
    if (tid < NP) {
        const float px = xs[tid * 5 + 0], py = xs[tid * 5 + 1], pz = xs[tid * 5 + 2];
        float d0 = 1e30f, d1 = 1e30f, d2v = 1e30f, d3 = 1e30f;
        int i0 = 0, i1 = 0, i2 = 0, i3 = 0;
#pragma unroll 4
        for (int j = 0; j < NP; j++) {
            float dx = xs[j * 5 + 0] - px, dy = xs[j * 5 + 1] - py, dz = xs[j * 5 + 2] - pz;
            float dd = dx * dx + dy * dy + dz * dz;
            dd = (j == tid) ? 1e30f : dd;
            bool c0 = dd < d0, c1 = dd < d1, c2 = dd < d2v, c3 = dd < d3;
            i3 = c2 ? i2 : (c3 ? j : i3);  d3  = c2 ? d2v : (c3 ? dd : d3);
            i2 = c1 ? i1 : (c2 ? j : i2);  d2v = c1 ? d1  : (c2 ? dd : d2v);
            i1 = c0 ? i0 : (c1 ? j : i1);  d1  = c0 ? d0  : (c1 ? dd : d1);
            i0 = c0 ? j : i0;              d0  = c0 ? dd  : d0;
        }
        nbr[tid * 4 + 0] = i0; nbr[tid * 4 + 1] = i1; nbr[tid * 4 + 2] = i2; nbr[tid * 4 + 3] = i3;
    }
    __syncthreads();

    // ---- main loop: warp-independent 16-edge tiles, NO block syncs
    for (int it = 0; it < 4; it++) {
        const int tile = it * 8 + wid;
        const int node = tile * 4 + (qr & 3);
        const int kb = (qr >> 2) & 1;
        const int j0 = nbr[node * 4 + kb];
        const int j1 = nbr[node * 4 + kb + 2];

        // edge features in registers -> l1 A-frag
        uint32_t a1h[4], a1l[4];
        {
            const int d0 = 2 * qc, d2 = 8 + 2 * qc;
            float f0, f1, f2, f3, f4, f5, f6, f7;
            if (d0 < 5) { f0 = xs[node * 5 + d0]; f2 = f0; }
            else        { f0 = xs[j0 * 5 + d0 - 5] - xs[node * 5 + d0 - 5];
                          f2 = xs[j1 * 5 + d0 - 5] - xs[node * 5 + d0 - 5]; }
            if (d0 + 1 < 5) { f1 = xs[node * 5 + d0 + 1]; f3 = f1; }
            else            { f1 = xs[j0 * 5 + d0 - 4] - xs[node * 5 + d0 - 4];
                              f3 = xs[j1 * 5 + d0 - 4] - xs[node * 5 + d0 - 4]; }
            if (d2 < 10) {
                f4 = xs[j0 * 5 + 3] - xs[node * 5 + 3];
                f5 = xs[j0 * 5 + 4] - xs[node * 5 + 4];
                f6 = xs[j1 * 5 + 3] - xs[node * 5 + 3];
                f7 = xs[j1 * 5 + 4] - xs[node * 5 + 4];
            } else { f4 = 0.f; f5 = 0.f; f6 = 0.f; f7 = 0.f; }
            splitpack(f0, f1, a1h[0], a1l[0]);
            splitpack(f2, f3, a1h[1], a1l[1]);
            splitpack(f4, f5, a1h[2], a1l[2]);
            splitpack(f6, f7, a1h[3], a1l[3]);
        }

        // layer-1: 8 nt (64 cols), K=16, x3
        float acc1[8][4];
#pragma unroll
        for (int j = 0; j < 8; j++) { acc1[j][0]=0.f; acc1[j][1]=0.f; acc1[j][2]=0.f; acc1[j][3]=0.f; }
#pragma unroll
        for (int jp = 0; jp < 4; jp++) {
            uint32_t bh4[4], bl4[4];
            ldsm4(W1H, 24, jp * 16, 0, lid, bh4);
            ldsm4(W1L, 24, jp * 16, 0, lid, bl4);
            uint32_t b0h[2] = {bh4[0], bh4[2]}, b1h[2] = {bh4[1], bh4[3]};
            uint32_t b0l[2] = {bl4[0], bl4[2]}, b1l[2] = {bl4[1], bl4[3]};
            mma3h(acc1[jp * 2],     a1h, a1l, b0h, b0l);
            mma3h(acc1[jp * 2 + 1], a1h, a1l, b1h, b1l);
        }

        // layer-2: A-frags from acc1 (bias+relu+split in regs), 16 nt, K=64, x3
        float acc2[16][4];
#pragma unroll
        for (int j = 0; j < 16; j++) { acc2[j][0]=0.f; acc2[j][1]=0.f; acc2[j][2]=0.f; acc2[j][3]=0.f; }
#pragma unroll
        for (int ks = 0; ks < 4; ks++) {
            uint32_t a2h[4], a2l[4];
            {
                const int c0 = (2 * ks) * 8 + 2 * qc;
                const int c2 = (2 * ks + 1) * 8 + 2 * qc;
                float v0 = fmaxf(acc1[2 * ks][0] + b1s[c0], 0.f);
                float v1 = fmaxf(acc1[2 * ks][1] + b1s[c0 + 1], 0.f);
                float v2 = fmaxf(acc1[2 * ks][2] + b1s[c0], 0.f);
                float v3 = fmaxf(acc1[2 * ks][3] + b1s[c0 + 1], 0.f);
                float v4 = fmaxf(acc1[2 * ks + 1][0] + b1s[c2], 0.f);
                float v5 = fmaxf(acc1[2 * ks + 1][1] + b1s[c2 + 1], 0.f);
                float v6 = fmaxf(acc1[2 * ks + 1][2] + b1s[c2], 0.f);
                float v7 = fmaxf(acc1[2 * ks + 1][3] + b1s[c2 + 1], 0.f);
                splitpack(v0, v1, a2h[0], a2l[0]);
                splitpack(v2, v3, a2h[1], a2l[1]);
                splitpack(v4, v5, a2h[2], a2l[2]);
                splitpack(v6, v7, a2h[3], a2l[3]);
            }
#pragma unroll
            for (int jp = 0; jp < 8; jp++) {
                uint32_t bh4[4], bl4[4];
                ldsm4(W2H, 72, jp * 16, ks * 16, lid, bh4);
                ldsm4(W2L, 72, jp * 16, ks * 16, lid, bl4);
                uint32_t b0h[2] = {bh4[0], bh4[2]}, b1h[2] = {bh4[1], bh4[3]};
                uint32_t b0l[2] = {bl4[0], bl4[2]}, b1l[2] = {bl4[1], bl4[3]};
                mma3h(acc2[jp * 2],     a2h, a2l, b0h, b0l);
                mma3h(acc2[jp * 2 + 1], a2h, a2l, b1h, b1l);
            }
        }

        // epilogue: +b2, relu; in-thread k={kb,kb+2}; XOR-16 pairs kb<->kb^1; fp16 store
        {
            uint32_t* Gh = (uint32_t*)g_hagg + (base + node) * 128;
#pragma unroll
            for (int j = 0; j < 16; j++) {
                const int col = j * 8 + 2 * qc;
                float v0 = fmaxf(acc2[j][0] + b2s[col], 0.f);
                float v1 = fmaxf(acc2[j][1] + b2s[col + 1], 0.f);
                float v2 = fmaxf(acc2[j][2] + b2s[col], 0.f);
                float v3 = fmaxf(acc2[j][3] + b2s[col + 1], 0.f);
                float mx0 = fmaxf(v0, v2), mx1 = fmaxf(v1, v3);
                float sm0 = v0 + v2,       sm1 = v1 + v3;
                mx0 = fmaxf(mx0, __shfl_xor_sync(0xffffffffu, mx0, 16));
                mx1 = fmaxf(mx1, __shfl_xor_sync(0xffffffffu, mx1, 16));
                sm0 += __shfl_xor_sync(0xffffffffu, sm0, 16);
                sm1 += __shfl_xor_sync(0xffffffffu, sm1, 16);
                if ((qr < 4) == (j < 8)) {
                    Gh[col >> 1]      = packf(mx0, mx1);
                    Gh[64 + (col >> 1)] = packf(sm0, sm1);
                }
            }
        }
    }
}

// ================= NN kernel: nn1(x2) + nn2(x3) + segreduce -> g_xin =================
#define NN_ASH  0         // A chunk [128][40] half = 10240
#define NN_B1H  10240     // [96][40] half = 7680
#define NN_B1L  17920     // 7680 -> end 25600
#define NN_B2H  0         // overlay after nn1: [64][104] half = 13312
#define NN_B2L  13312     // 13312 -> end 26624
#define NN_H2H  26624     // [128][104] half = 26624
#define NN_H2L  53248     // 26624 -> end 79872 (h2 fp32 [128][68] overlays H2H after nn2)
#define NN_RED  79872     // 3072
#define NN_B1V  82944     // 384
#define NN_B2V  83328     // 256
#define NN_SMEM 83584

__global__ void __launch_bounds__(256, 2) nn_kernel(const float* __restrict__ nn2b)
{
    extern __shared__ __align__(16) char smem[];
    __half* AsH = (__half*)(smem + NN_ASH);
    __half* B1H = (__half*)(smem + NN_B1H);
    __half* B1L = (__half*)(smem + NN_B1L);
    __half* B2H = (__half*)(smem + NN_B2H);
    __half* B2L = (__half*)(smem + NN_B2L);
    __half* H2H = (__half*)(smem + NN_H2H);
    __half* H2L = (__half*)(smem + NN_H2L);
    float* red  = (float*)(smem + NN_RED);
    float* b1v  = (float*)(smem + NN_B1V);
    float* b2v  = (float*)(smem + NN_B2V);

    const int tid = threadIdx.x, wid = tid >> 5, lid = tid & 31;
    const int rw = wid >> 1, nh = wid & 1;
    const int qr = lid >> 2, qc = lid & 3;
    const int g = blockIdx.x;
    const __half* Ah = g_hagg + (size_t)g * NP * 256;

    if (tid < 96) b1v[tid] = g_nn1bp[tid];
    if (tid >= 96 && tid < 160) b2v[tid - 96] = nn2b[tid - 96];

    // ---- nn1: [128][256] @ [256][96]; A plain fp16 (x2 compensation on B only)
    float acc1[2][6][4];
#pragma unroll
    for (int rt = 0; rt < 2; rt++)
#pragma unroll
        for (int j = 0; j < 6; j++) { acc1[rt][j][0]=0.f; acc1[rt][j][1]=0.f; acc1[rt][j][2]=0.f; acc1[rt][j][3]=0.f; }
    for (int kc = 0; kc < 8; kc++) {
        for (int i = tid; i < 512; i += 256) {
            int r = i >> 2, q = i & 3;
            *(uint4*)(AsH + r * 40 + q * 8) = *(const uint4*)(Ah + r * 256 + kc * 32 + q * 8);
        }
        for (int i = tid; i < 1536; i += 256) {
            int n = i >> 4, kw = i & 15;
            ((uint32_t*)B1H)[n * 20 + kw] = ((const uint32_t*)g_nn1Th)[n * 128 + kc * 16 + kw];
            ((uint32_t*)B1L)[n * 20 + kw] = ((const uint32_t*)g_nn1Tl)[n * 128 + kc * 16 + kw];
        }
        __syncthreads();
#pragma unroll
        for (int ks = 0; ks < 2; ks++) {
            uint32_t ah[2][4];
            ldsm4(AsH, 40, rw * 32,      ks * 16, lid, ah[0]);
            ldsm4(AsH, 40, rw * 32 + 16, ks * 16, lid, ah[1]);
#pragma unroll
            for (int jp = 0; jp < 3; jp++) {
                uint32_t bh4[4], bl4[4];
                ldsm4(B1H, 40, (nh * 6 + jp * 2) * 8, ks * 16, lid, bh4);
                ldsm4(B1L, 40, (nh * 6 + jp * 2) * 8, ks * 16, lid, bl4);
                uint32_t b0h[2] = {bh4[0], bh4[2]}, b1h[2] = {bh4[1], bh4[3]};
                uint32_t b0l[2] = {bl4[0], bl4[2]}, b1l[2] = {bl4[1], bl4[3]};
                mma2h(acc1[0][jp * 2],     ah[0], b0h, b0l);
                mma2h(acc1[1][jp * 2],     ah[1], b0h, b0l);
                mma2h(acc1[0][jp * 2 + 1], ah[0], b1h, b1l);
                mma2h(acc1[1][jp * 2 + 1], ah[1], b1h, b1l);
            }
        }
        __syncthreads();
    }
    // epilogue1: H2 hi/lo planes = split(relu(acc1 + b1v)); stage B2 planes (overlay)
    {
#pragma unroll
        for (int rt = 0; rt < 2; rt++) {
            int r0 = rw * 32 + rt * 16 + qr, r1 = r0 + 8;
#pragma unroll
            for (int j = 0; j < 6; j++) {
                int col = (nh * 6 + j) * 8 + 2 * qc;
                float v0 = fmaxf(acc1[rt][j][0] + b1v[col], 0.f), v1 = fmaxf(acc1[rt][j][1] + b1v[col + 1], 0.f);
                float v2 = fmaxf(acc1[rt][j][2] + b1v[col], 0.f), v3 = fmaxf(acc1[rt][j][3] + b1v[col + 1], 0.f);
                uint32_t h, l;
                splitpack(v0, v1, h, l);
                ((uint32_t*)H2H)[r0 * 52 + (col >> 1)] = h; ((uint32_t*)H2L)[r0 * 52 + (col >> 1)] = l;
                splitpack(v2, v3, h, l);
                ((uint32_t*)H2H)[r1 * 52 + (col >> 1)] = h; ((uint32_t*)H2L)[r1 * 52 + (col >> 1)] = l;
            }
        }
        for (int i = tid; i < 3072; i += 256) {
            int n = i / 48, kw = i % 48;
            ((uint32_t*)B2H)[n * 52 + kw] = ((const uint32_t*)g_nn2Th)[n * 48 + kw];
            ((uint32_t*)B2L)[n * 52 + kw] = ((const uint32_t*)g_nn2Tl)[n * 48 + kw];
        }
    }
    __syncthreads();

    // ---- nn2: [128][96] @ [96][64], K=96, x3
    float acc2[2][4][4];
#pragma unroll
    for (int rt = 0; rt < 2; rt++)
#pragma unroll
        for (int j = 0; j < 4; j++) { acc2[rt][j][0]=0.f; acc2[rt][j][1]=0.f; acc2[rt][j][2]=0.f; acc2[rt][j][3]=0.f; }
#pragma unroll
    for (int ks = 0; ks < 6; ks++) {
        uint32_t ah[2][4], al[2][4];
        ldsm4(H2H, 104, rw * 32,      ks * 16, lid, ah[0]); ldsm4(H2L, 104, rw * 32,      ks * 16, lid, al[0]);
        ldsm4(H2H, 104, rw * 32 + 16, ks * 16, lid, ah[1]); ldsm4(H2L, 104, rw * 32 + 16, ks * 16, lid, al[1]);
#pragma unroll
        for (int jp = 0; jp < 2; jp++) {
            uint32_t bh4[4], bl4[4];
            ldsm4(B2H, 104, (nh * 4 + jp * 2) * 8, ks * 16, lid, bh4);
            ldsm4(B2L, 104, (nh * 4 + jp * 2) * 8, ks * 16, lid, bl4);
            uint32_t b0h[2] = {bh4[0], bh4[2]}, b1h[2] = {bh4[1], bh4[3]};
            uint32_t b0l[2] = {bl4[0], bl4[2]}, b1l[2] = {bl4[1], bl4[3]};
            mma3h(acc2[0][jp * 2],     ah[0], al[0], b0h, b0l);
            mma3h(acc2[1][jp * 2],     ah[1], al[1], b0h, b0l);
            mma3h(acc2[0][jp * 2 + 1], ah[0], al[0], b1h, b1l);
            mma3h(acc2[1][jp * 2 + 1], ah[1], al[1], b1h, b1l);
        }
    }
    __syncthreads();
    float* h2 = (float*)(smem + NN_H2H);          // [128][68] fp32 overlay
    {
#pragma unroll
        for (int rt = 0; rt < 2; rt++) {
            int r0 = rw * 32 + rt * 16 + qr, r1 = r0 + 8;
#pragma unroll
            for (int j = 0; j < 4; j++) {
                int col = (nh * 4 + j) * 8 + 2 * qc;
                float2 u0 = { acc2[rt][j][0] + b2v[col], acc2[rt][j][1] + b2v[col + 1] };
                float2 u1 = { acc2[rt][j][2] + b2v[col], acc2[rt][j][3] + b2v[col + 1] };
                *(float2*)&h2[r0 * 68 + col] = u0;
                *(float2*)&h2[r1 * 68 + col] = u1;
            }
        }
    }
    __syncthreads();

    // ---- segment max/min/sum/mean + relu -> g_xin (permute fused)
    {
        int c = tid & 63, q = tid >> 6;
        float mx = -1e30f, mn = 1e30f, sm = 0.f;
        for (int r = q * 32; r < q * 32 + 32; r++) {
            float v = h2[r * 68 + c];
            mx = fmaxf(mx, v); mn = fminf(mn, v); sm += v;
        }
        red[q * 192 + c] = mx; red[q * 192 + 64 + c] = mn; red[q * 192 + 128 + c] = sm;
        __syncthreads();
        if (tid < 64) {
            float MX = red[c], MN = red[64 + c], SM = red[128 + c];
            for (int qq = 1; qq < 4; qq++) {
                MX = fmaxf(MX, red[qq * 192 + c]);
                MN = fminf(MN, red[qq * 192 + 64 + c]);
                SM += red[qq * 192 + 128 + c];
            }
            // xin[((t<<10) + (q3)*256 + ch)*256 + i], t=g>>10, q3=(g&1023)&3, i=(g&1023)>>2
            const int t = g >> 10, qg = g & 1023;
            const int i = qg >> 2;
            float* xrow = g_xin + ((size_t)((t << 10) + (qg & 3) * 256) << 8) + i;
            xrow[(size_t)c * 256]         = fmaxf(MX, 0.f);
            xrow[(size_t)(64 + c) * 256]  = fmaxf(MN, 0.f);
            xrow[(size_t)(128 + c) * 256] = fmaxf(SM, 0.f);
            xrow[(size_t)(192 + c) * 256] = fmaxf(SM * (1.f / 128.f), 0.f);
        }
    }
}

// ---------------- GI = xin @ wih0T + bih0; coalesced A, 8-row tiles ----------------
__global__ void __launch_bounds__(256) gi_gemm_kernel(
    const float* __restrict__ W, const float* __restrict__ bias, float* __restrict__ C)
{
    __shared__ float As[8][260];
    __shared__ float Ws[32][96];
    const int tid = threadIdx.x;
    const int bm = blockIdx.x * 8;
    const int r = tid >> 5, c = tid & 31;

    {
        const float* arow = g_xin + (size_t)(bm + r) * 256;
        for (int k = c; k < 256; k += 32) As[r][k] = arow[k];
    }
    float a0 = 0.f, a1 = 0.f, a2 = 0.f;
    for (int kc = 0; kc < 8; kc++) {
        for (int i = tid; i < 3072; i += 256)
            (&Ws[0][0])[i] = W[kc * 3072 + i];
        __syncthreads();
#pragma unroll
        for (int k = 0; k < 32; k++) {
            const float av = As[r][kc * 32 + k];
            a0 = fmaf(av, Ws[k][c], a0);
            a1 = fmaf(av, Ws[k][c + 32], a1);
            a2 = fmaf(av, Ws[k][c + 64], a2);
        }
        __syncthreads();
    }
    float* o = C + (size_t)(bm + r) * 96;
    o[c] = a0 + bias[c];
    o[c + 32] = a1 + bias[c + 32];
    o[c + 64] = a2 + bias[c + 64];
}

// ---------------- fused GRU: both layers x both timesteps; warp = row ----------------
__global__ void __launch_bounds__(512) gru_all_kernel(
    const float* __restrict__ gi,     // [2][1024][96]
    const float* __restrict__ h1in,   // [2][1024][32]
    const float* __restrict__ wih1, const float* __restrict__ bih1,
    const float* __restrict__ whh0, const float* __restrict__ bhh0,
    const float* __restrict__ whh1, const float* __restrict__ bhh1)
{
    __shared__ float w0[96][33], w1[96][33], wi1[96][33];
    const int tid = threadIdx.x;
    const int wr = tid >> 5, u = tid & 31;
    const int row = blockIdx.x * 16 + wr;

    for (int i = tid; i < 3072; i += 512) {
        w0[i >> 5][i & 31] = whh0[i];
        w1[i >> 5][i & 31] = whh1[i];
        wi1[i >> 5][i & 31] = wih1[i];
    }
    __syncthreads();

    float h0 = h1in[row * 32 + u];
    float hv1 = h1in[32768 + row * 32 + u];
    const float b0r = bhh0[u], b0z = bhh0[32 + u], b0n = bhh0[64 + u];
    const float bi1r = bih1[u], bi1z = bih1[32 + u], bi1n = bih1[64 + u];
    const float b1r = bhh1[u], b1z = bhh1[32 + u], b1n = bhh1[64 + u];

#pragma unroll
    for (int t = 0; t < 2; t++) {
        const float* gr0 = gi + t * 98304 + (size_t)row * 96;
        float gr = gr0[u], gz = gr0[32 + u], gn = gr0[64 + u];
        float hr = b0r, hz = b0z, hn = b0n;
#pragma unroll
        for (int d = 0; d < 32; d++) {
            float hv = __shfl_sync(0xffffffffu, h0, d);
            hr = fmaf(hv, w0[u][d], hr);
            hz = fmaf(hv, w0[32 + u][d], hz);
            hn = fmaf(hv, w0[64 + u][d], hn);
        }
        float rr = 1.f / (1.f + expf(-(gr + hr)));
        float zz = 1.f / (1.f + expf(-(gz + hz)));
        float nn = tanhf(gn + rr * hn);
        h0 = (1.f - zz) * nn + zz * h0;

        float xr = bi1r, xz = bi1z, xn = bi1n;
        float yr = b1r, yz = b1z, yn = b1n;
#pragma unroll
        for (int d = 0; d < 32; d++) {
            float xv = __shfl_sync(0xffffffffu, h0, d);
            xr = fmaf(xv, wi1[u][d], xr);
            xz = fmaf(xv, wi1[32 + u][d], xz);
            xn = fmaf(xv, wi1[64 + u][d], xn);
            float hv = __shfl_sync(0xffffffffu, hv1, d);
            yr = fmaf(hv, w1[u][d], yr);
            yz = fmaf(hv, w1[32 + u][d], yz);
            yn = fmaf(hv, w1[64 + u][d], yn);
        }
        float r1 = 1.f / (1.f + expf(-(xr + yr)));
        float z1 = 1.f / (1.f + expf(-(xz + yz)));
        float n1 = tanhf(xn + r1 * yn);
        hv1 = (1.f - z1) * n1 + z1 * hv1;
        g_out1[t * 32768 + row * 32 + u] = hv1;
    }
    g_out0[32768 + row * 32 + u] = h0;   // hT of layer 0
}

// ---------------- final head + hT pack ----------------
__global__ void final_kernel(const float* __restrict__ nn4W, const float* __restrict__ nn4b,
                             float* __restrict__ out, int out_size)
{
    const int idx = blockIdx.x * 256 + threadIdx.x;
    if (idx >= out_size) return;
    if (idx < 2048) {
        const int t  = idx >> 10;
        const int ch = (idx >> 5) & 31;
        const int b0 = (idx & 31) * 32;
        float acc = nn4b[0];
#pragma unroll
        for (int c = 0; c < 32; c++) {
            const float v = g_out1[t * 32768 + (b0 + c) * 32 + ch];
            acc = fmaf(fmaxf(v, 0.f), nn4W[c], acc);
        }
        out[idx] = fmaxf(acc, 0.f);
    } else if (idx < 2048 + 65536) {
        const int j = idx - 2048;
        out[idx] = (j < 32768) ? g_out0[32768 + j] : g_out1[32768 + (j - 32768)];
    }
}

// ---------------- launch ----------------
extern "C" void kernel_launch(void* const* d_in, const int* in_sizes, int n_in,
                              void* d_out, int out_size)
{
    const float* x    = (const float*)d_in[0];
    const float* h1   = (const float*)d_in[2];
    const float* W1   = (const float*)d_in[3];
    const float* b1   = (const float*)d_in[4];
    const float* W2   = (const float*)d_in[5];
    const float* b2   = (const float*)d_in[6];
    const float* nn1W = (const float*)d_in[7];
    const float* nn1b = (const float*)d_in[8];
    const float* nn2W = (const float*)d_in[9];
    const float* nn2b = (const float*)d_in[10];
    const float* nn4W = (const float*)d_in[11];
    const float* nn4b = (const float*)d_in[12];
    const float* wih0 = (const float*)d_in[13];
    const float* whh0 = (const float*)d_in[14];
    const float* bih0 = (const float*)d_in[15];
    const float* bhh0 = (const float*)d_in[16];
    const float* wih1 = (const float*)d_in[17];
    const float* whh1 = (const float*)d_in[18];
    const float* bih1 = (const float*)d_in[19];
    const float* bhh1 = (const float*)d_in[20];
    float* out = (float*)d_out;

    float *gi, *wih0T;
    cudaGetSymbolAddress((void**)&gi,    g_gi);
    cudaGetSymbolAddress((void**)&wih0T, g_wih0T);

    cudaFuncSetAttribute(ec_kernel, cudaFuncAttributeMaxDynamicSharedMemorySize, EC_SMEM);
    cudaFuncSetAttribute(nn_kernel, cudaFuncAttributeMaxDynamicSharedMemorySize, NN_SMEM);

    prep_kernel<<<96, 256>>>(nn1W, nn1b, nn2W, W2, W1, wih0);
    ec_kernel<<<NG, 256, EC_SMEM>>>(x, b1, b2);
    nn_kernel<<<NG, 256, NN_SMEM>>>(nn2b);
    gi_gemm_kernel<<<256, 256>>>(wih0T, bih0, gi);
    gru_all_kernel<<<64, 512>>>(gi, h1, wih1, bih1, whh0, bhh0, whh1, bhh1);
    final_kernel<<<(out_size + 255) / 256, 256>>>(nn4W, nn4b, out, out_size);
}